// round 7
// baseline (speedup 1.0000x reference)
#include <cuda_runtime.h>
#include <math.h>

#define Bn 32
#define Cn 20
#define Sn 65536
#define Mn 16
#define Qn 4096
#define Hn 128

// Scratch (device globals; allocation-free rule)
__device__ float  g_h[(size_t)Bn * Cn * Sn];          // (B, C, S) ~168MB
__device__ float  g_partR[Bn][Cn][2][Mn];
__device__ float  g_partI[Bn][Cn][2][Mn];
__device__ float  g_maxv;
__device__ float  g_invmaxv;

// Fast gelu: A&S 7.1.28 erf approximation, |eps| <= 3e-7, branch-free.
__device__ __forceinline__ float fast_rcp(float x) {
    float r; asm("rcp.approx.f32 %0, %1;" : "=f"(r) : "f"(x)); return r;
}
__device__ __forceinline__ float gelu_fast(float x) {
    const float u = fabsf(x) * 0.7071067811865476f;
    float p = fmaf(0.0000430638f, u, 0.0002765672f);
    p = fmaf(p, u, 0.0001520143f);
    p = fmaf(p, u, 0.0092705272f);
    p = fmaf(p, u, 0.0422820123f);
    p = fmaf(p, u, 0.0705230784f);
    p = fmaf(p, u, 1.0f);
    float r = fast_rcp(p);
    r = r * r; r = r * r; r = r * r; r = r * r;   // ^16
    const float erf_v = copysignf(1.0f - r, x);
    return 0.5f * x * (1.0f + erf_v);
}

// rotation between sample s and s+1: e^{+2pi i/65536}
#define C1R 0.9999999954025773f
#define S1R 9.587379909597734e-5f

// ------------------------------------------------------------------ max
__global__ void fno_kmax(const float* __restrict__ p) {
    __shared__ float sm[1024];
    float m = -1e30f;
    for (int i = threadIdx.x; i < Sn; i += 1024) m = fmaxf(m, p[i]);
    sm[threadIdx.x] = m;
    __syncthreads();
    for (int off = 512; off; off >>= 1) {
        if (threadIdx.x < off) sm[threadIdx.x] = fmaxf(sm[threadIdx.x], sm[threadIdx.x + off]);
        __syncthreads();
    }
    if (threadIdx.x == 0) { g_maxv = sm[0]; g_invmaxv = 1.0f / sm[0]; }
}

// ================= forward truncated DFT (16 modes) ========================
// Core DFT body shared by both variants via macro-ish inline on loaded hp[16].
struct DFTAcc { float Fr[Mn], Fi[Mn]; };

__device__ __forceinline__ void dft16_accum(const float hp[16], float zr, float zi,
                                            float* Fr, float* Fi) {
    const float C16[16] = { 1.f,  0.9238795325112867f,  0.7071067811865476f,  0.3826834323650898f,
                            0.f, -0.3826834323650898f, -0.7071067811865476f, -0.9238795325112867f,
                           -1.f, -0.9238795325112867f, -0.7071067811865476f, -0.3826834323650898f,
                            0.f,  0.3826834323650898f,  0.7071067811865476f,  0.9238795325112867f };
    const float S16[16] = { 0.f,  0.3826834323650898f,  0.7071067811865476f,  0.9238795325112867f,
                            1.f,  0.9238795325112867f,  0.7071067811865476f,  0.3826834323650898f,
                            0.f, -0.3826834323650898f, -0.7071067811865476f, -0.9238795325112867f,
                           -1.f, -0.9238795325112867f, -0.7071067811865476f, -0.3826834323650898f };
    float u[8], dd[8];
#pragma unroll
    for (int p = 0; p < 8; p++) { u[p] = hp[p] + hp[p + 8]; dd[p] = hp[p] - hp[p + 8]; }
    float BR[16], BI[16];
#pragma unroll
    for (int j = 0; j <= 4; j++) {
        float ar = 0.f, ai = 0.f;
#pragma unroll
        for (int p = 0; p < 8; p++) {
            const int m = (2 * j * p) & 15;
            ar += u[p] * C16[m];
            ai -= u[p] * S16[m];
        }
        BR[2 * j] = ar; BI[2 * j] = ai;
    }
#pragma unroll
    for (int k = 1; k < 8; k += 2) {
        float ar = 0.f, ai = 0.f;
#pragma unroll
        for (int p = 0; p < 8; p++) {
            const int m = (k * p) & 15;
            ar += dd[p] * C16[m];
            ai -= dd[p] * S16[m];
        }
        BR[k] = ar; BI[k] = ai;
    }
#pragma unroll
    for (int k = 9; k < 16; k++) { BR[k] = BR[16 - k]; BI[k] = -BI[16 - k]; }

    Fr[0] += BR[0];
    Fi[0] += BI[0];
    float wr = zr, wi = zi;
#pragma unroll
    for (int k = 1; k < 16; k++) {
        Fr[k] += BR[k] * wr - BI[k] * wi;
        Fi[k] += BR[k] * wi + BI[k] * wr;
        const float nwr = wr * zr - wi * zi;
        const float nwi = wr * zi + wi * zr;
        wr = nwr; wi = nwi;
    }
}

__device__ __forceinline__ void dft16_reduce_store(float* Fr, float* Fi,
                                                   int b, int c, int qc, int tid) {
#pragma unroll
    for (int off = 16; off; off >>= 1) {
#pragma unroll
        for (int k = 0; k < Mn; k++) {
            Fr[k] += __shfl_down_sync(0xffffffffu, Fr[k], off);
            Fi[k] += __shfl_down_sync(0xffffffffu, Fi[k], off);
        }
    }
    __shared__ float redR[8][Mn], redI[8][Mn];
    const int warp = tid >> 5, lane = tid & 31;
    if (lane == 0) {
#pragma unroll
        for (int k = 0; k < Mn; k++) { redR[warp][k] = Fr[k]; redI[warp][k] = Fi[k]; }
    }
    __syncthreads();
    if (tid < Mn) {
        float ar = 0.f, ai = 0.f;
#pragma unroll
        for (int w = 0; w < 8; w++) { ar += redR[w][tid]; ai += redI[w][tid]; }
        g_partR[b][c][qc][tid] = ar;
        g_partI[b][c][qc][tid] = ai;
    }
}

// generic forward DFT: reads g_h
__global__ void __launch_bounds__(256) fno_kfwd() {
    const int qc = blockIdx.x, c = blockIdx.y, b = blockIdx.z;
    const float* __restrict__ row = g_h + ((size_t)(b * Cn + c)) * Sn;
    const int tid = threadIdx.x;
    const int q0 = qc * 2048 + tid;

    float Fr[Mn], Fi[Mn];
#pragma unroll
    for (int k = 0; k < Mn; k++) { Fr[k] = 0.f; Fi[k] = 0.f; }
    float zr, zi;
    sincospif(-(float)q0 * (1.0f / 32768.0f), &zi, &zr);
    const float Rr =  0.9996988186962042f;
    const float Ri = -0.0245412285229123f;

    for (int it = 0; it < 8; ++it) {
        const int q = q0 + it * 256;
        float hp[16];
#pragma unroll
        for (int p = 0; p < 16; p++) hp[p] = row[q + p * Qn];
        dft16_accum(hp, zr, zi, Fr, Fi);
        const float nzr = zr * Rr - zi * Ri;
        const float nzi = zr * Ri + zi * Rr;
        zr = nzr; zi = nzi;
    }
    dft16_reduce_store(Fr, Fi, b, c, qc, tid);
}

// layer-0 forward DFT: computes h on the fly from x, point_data, fc0
__global__ void __launch_bounds__(256) fno_kfwd0(const float* __restrict__ x,
                                                 const float* __restrict__ pd,
                                                 const float* __restrict__ fc0w,
                                                 const float* __restrict__ fc0b) {
    const int qc = blockIdx.x, c = blockIdx.y, b = blockIdx.z;
    const int tid = threadIdx.x;
    const int q0 = qc * 2048 + tid;
    const float w0 = fc0w[c], w1 = fc0w[Cn + c], bc = fc0b[c];
    const float invm = g_invmaxv;
    const float* __restrict__ xrow = x + (size_t)b * Sn;

    float Fr[Mn], Fi[Mn];
#pragma unroll
    for (int k = 0; k < Mn; k++) { Fr[k] = 0.f; Fi[k] = 0.f; }
    float zr, zi;
    sincospif(-(float)q0 * (1.0f / 32768.0f), &zi, &zr);
    const float Rr =  0.9996988186962042f;
    const float Ri = -0.0245412285229123f;

    for (int it = 0; it < 8; ++it) {
        const int q = q0 + it * 256;
        float hp[16];
#pragma unroll
        for (int p = 0; p < 16; p++) {
            const int s = q + p * Qn;
            hp[p] = fmaf(xrow[s], w0, fmaf(pd[s] * invm, w1, bc));
        }
        dft16_accum(hp, zr, zi, Fr, Fi);
        const float nzr = zr * Rr - zi * Ri;
        const float nzi = zr * Ri + zi * Rr;
        zr = nzr; zi = nzi;
    }
    dft16_reduce_store(Fr, Fi, b, c, qc, tid);
}

// ================= fused mode-mix into shared memory =======================
__device__ __forceinline__ void mix_to_smem(int b,
                                            const float* __restrict__ sre,
                                            const float* __restrict__ sim,
                                            const float* __restrict__ wb,
                                            float2 s_spec[Mn][Cn],
                                            float* s_base, int tid, int nthr) {
    for (int idx = tid; idx < Cn * Mn; idx += nthr) {
        const int o = idx >> 4, k = idx & 15;
        float Gr = 0.f, Gi = 0.f;
#pragma unroll
        for (int i = 0; i < Cn; i++) {
            const float fr = g_partR[b][i][0][k] + g_partR[b][i][1][k];
            const float fi = g_partI[b][i][0][k] + g_partI[b][i][1][k];
            const float wr = sre[i * (Cn * Mn) + o * Mn + k];
            const float wi = sim[i * (Cn * Mn) + o * Mn + k];
            Gr += fr * wr - fi * wi;
            Gi += fr * wi + fi * wr;
        }
        const float invS = 1.0f / (float)Sn;
        if (k == 0) s_base[o] = Gr * invS + wb[o];
        else        s_spec[k][o] = make_float2(2.f * Gr * invS, -2.f * Gi * invS);
    }
}

// ============ spectral synthesis for 4 samples into to0..to3 ===============
__device__ __forceinline__ void synth4(const float2 s_spec[Mn][Cn], const float* s_base,
                                       int s0, float* to0, float* to1, float* to2, float* to3) {
    float e0r, e0i;
    sincospif((float)s0 * (1.0f / 32768.0f), &e0i, &e0r);
    const float e1r = e0r * C1R - e0i * S1R, e1i = e0r * S1R + e0i * C1R;
    const float e2r = e1r * C1R - e1i * S1R, e2i = e1r * S1R + e1i * C1R;
    const float e3r = e2r * C1R - e2i * S1R, e3i = e2r * S1R + e2i * C1R;

#pragma unroll
    for (int o = 0; o < Cn; o++) {
        const float bse = s_base[o];
        to0[o] = bse; to1[o] = bse; to2[o] = bse; to3[o] = bse;
    }
    float w0r = e0r, w0i = e0i, w1r = e1r, w1i = e1i;
    float w2r = e2r, w2i = e2i, w3r = e3r, w3i = e3i;
#pragma unroll
    for (int k = 1; k < Mn; k++) {
#pragma unroll
        for (int o = 0; o < Cn; o++) {
            const float2 cc = s_spec[k][o];
            to0[o] = fmaf(cc.x, w0r, fmaf(cc.y, w0i, to0[o]));
            to1[o] = fmaf(cc.x, w1r, fmaf(cc.y, w1i, to1[o]));
            to2[o] = fmaf(cc.x, w2r, fmaf(cc.y, w2i, to2[o]));
            to3[o] = fmaf(cc.x, w3r, fmaf(cc.y, w3i, to3[o]));
        }
        if (k < Mn - 1) {
            float nr, ni;
            nr = w0r * e0r - w0i * e0i; ni = w0r * e0i + w0i * e0r; w0r = nr; w0i = ni;
            nr = w1r * e1r - w1i * e1i; ni = w1r * e1i + w1i * e1r; w1r = nr; w1i = ni;
            nr = w2r * e2r - w2i * e2i; ni = w2r * e2i + w2i * e2r; w2r = nr; w2i = ni;
            nr = w3r * e3r - w3i * e3i; ni = w3r * e3i + w3i * e3r; w3r = nr; w3i = ni;
        }
    }
}

// ---- generic inverse + 1x1 conv + gelu, 4 samples/thread, mix fused -------
__global__ void __launch_bounds__(128) fno_kinv4(const float* __restrict__ sre,
                                                 const float* __restrict__ sim,
                                                 const float* __restrict__ ww,
                                                 const float* __restrict__ wb) {
    __shared__ float2 s_spec[Mn][Cn];
    __shared__ float  s_base[Cn];
    __shared__ float  s_ww[Cn * Cn];
    const int b = blockIdx.y;
    const int tid = threadIdx.x;
    mix_to_smem(b, sre, sim, wb, s_spec, s_base, tid, 128);
    for (int i = tid; i < Cn * Cn; i += 128) s_ww[i] = ww[i];
    __syncthreads();

    const int s0 = blockIdx.x * 512 + 4 * tid;
    float to0[Cn], to1[Cn], to2[Cn], to3[Cn];
    synth4(s_spec, s_base, s0, to0, to1, to2, to3);

#pragma unroll
    for (int c = 0; c < Cn; c++) {
        const float4 hp = *(const float4*)(g_h + ((size_t)(b * Cn + c)) * Sn + s0);
#pragma unroll
        for (int o = 0; o < Cn; o++) {
            const float wv = s_ww[o * Cn + c];
            to0[o] = fmaf(hp.x, wv, to0[o]);
            to1[o] = fmaf(hp.y, wv, to1[o]);
            to2[o] = fmaf(hp.z, wv, to2[o]);
            to3[o] = fmaf(hp.w, wv, to3[o]);
        }
    }
#pragma unroll
    for (int o = 0; o < Cn; o++) {
        float4 r = make_float4(gelu_fast(to0[o]), gelu_fast(to1[o]),
                               gelu_fast(to2[o]), gelu_fast(to3[o]));
        *(float4*)(g_h + ((size_t)(b * Cn + o)) * Sn + s0) = r;
    }
}

// ---- layer-0 inverse: h computed on the fly from x/pd/fc0 -----------------
__global__ void __launch_bounds__(128) fno_kinv4_l0(const float* __restrict__ sre,
                                                    const float* __restrict__ sim,
                                                    const float* __restrict__ ww,
                                                    const float* __restrict__ wb,
                                                    const float* __restrict__ x,
                                                    const float* __restrict__ pd,
                                                    const float* __restrict__ fc0w,
                                                    const float* __restrict__ fc0b) {
    __shared__ float2 s_spec[Mn][Cn];
    __shared__ float  s_base[Cn];
    __shared__ float  s_ww[Cn * Cn];
    __shared__ float  s_f0w[2 * Cn];
    __shared__ float  s_f0b[Cn];
    const int b = blockIdx.y;
    const int tid = threadIdx.x;
    mix_to_smem(b, sre, sim, wb, s_spec, s_base, tid, 128);
    for (int i = tid; i < Cn * Cn; i += 128) s_ww[i] = ww[i];
    if (tid < 2 * Cn) s_f0w[tid] = fc0w[tid];
    if (tid < Cn) s_f0b[tid] = fc0b[tid];
    __syncthreads();

    const int s0 = blockIdx.x * 512 + 4 * tid;
    float to0[Cn], to1[Cn], to2[Cn], to3[Cn];
    synth4(s_spec, s_base, s0, to0, to1, to2, to3);

    const float invm = g_invmaxv;
    const float4 xp = *(const float4*)(x + (size_t)b * Sn + s0);
    const float4 pp = *(const float4*)(pd + s0);
    const float g0 = pp.x * invm, g1 = pp.y * invm, g2 = pp.z * invm, g3 = pp.w * invm;
#pragma unroll
    for (int c = 0; c < Cn; c++) {
        const float w0 = s_f0w[c], w1 = s_f0w[Cn + c], bc = s_f0b[c];
        const float h0 = fmaf(xp.x, w0, fmaf(g0, w1, bc));
        const float h1 = fmaf(xp.y, w0, fmaf(g1, w1, bc));
        const float h2 = fmaf(xp.z, w0, fmaf(g2, w1, bc));
        const float h3 = fmaf(xp.w, w0, fmaf(g3, w1, bc));
#pragma unroll
        for (int o = 0; o < Cn; o++) {
            const float wv = s_ww[o * Cn + c];
            to0[o] = fmaf(h0, wv, to0[o]);
            to1[o] = fmaf(h1, wv, to1[o]);
            to2[o] = fmaf(h2, wv, to2[o]);
            to3[o] = fmaf(h3, wv, to3[o]);
        }
    }
#pragma unroll
    for (int o = 0; o < Cn; o++) {
        float4 r = make_float4(gelu_fast(to0[o]), gelu_fast(to1[o]),
                               gelu_fast(to2[o]), gelu_fast(to3[o]));
        *(float4*)(g_h + ((size_t)(b * Cn + o)) * Sn + s0) = r;
    }
}

// ---- final: layer-3 inverse+conv (no gelu) -> fc1 -> gelu -> fc2, 4 samples
__global__ void __launch_bounds__(128) fno_kfinal4(const float* __restrict__ sre,
                                                   const float* __restrict__ sim,
                                                   const float* __restrict__ ww,
                                                   const float* __restrict__ wb,
                                                   const float* __restrict__ fc1w,
                                                   const float* __restrict__ fc1b,
                                                   const float* __restrict__ fc2w,
                                                   const float* __restrict__ fc2b,
                                                   float* __restrict__ out) {
    __shared__ float2 s_spec[Mn][Cn];
    __shared__ float  s_base[Cn];
    __shared__ float  s_ww[Cn * Cn];
    __shared__ float4 s_fc1[Cn][Hn / 4];
    __shared__ float4 s_fc1b[Hn / 4];
    __shared__ float4 s_fc2[Hn / 4];
    const int b = blockIdx.y;
    const int tid = threadIdx.x;
    mix_to_smem(b, sre, sim, wb, s_spec, s_base, tid, 128);
    for (int i = tid; i < Cn * Cn; i += 128) s_ww[i] = ww[i];
    for (int i = tid; i < Cn * (Hn / 4); i += 128) {
        const int c = i / (Hn / 4), h4 = i % (Hn / 4);
        s_fc1[c][h4] = make_float4(fc1w[c * Hn + 4 * h4 + 0], fc1w[c * Hn + 4 * h4 + 1],
                                   fc1w[c * Hn + 4 * h4 + 2], fc1w[c * Hn + 4 * h4 + 3]);
    }
    if (tid < Hn / 4) {
        s_fc1b[tid] = make_float4(fc1b[4 * tid], fc1b[4 * tid + 1], fc1b[4 * tid + 2], fc1b[4 * tid + 3]);
        s_fc2[tid]  = make_float4(fc2w[4 * tid], fc2w[4 * tid + 1], fc2w[4 * tid + 2], fc2w[4 * tid + 3]);
    }
    __syncthreads();

    const int s0 = blockIdx.x * 512 + 4 * tid;
    float to0[Cn], to1[Cn], to2[Cn], to3[Cn];
    synth4(s_spec, s_base, s0, to0, to1, to2, to3);

#pragma unroll
    for (int c = 0; c < Cn; c++) {
        const float4 hp = *(const float4*)(g_h + ((size_t)(b * Cn + c)) * Sn + s0);
#pragma unroll
        for (int o = 0; o < Cn; o++) {
            const float wv = s_ww[o * Cn + c];
            to0[o] = fmaf(hp.x, wv, to0[o]);
            to1[o] = fmaf(hp.y, wv, to1[o]);
            to2[o] = fmaf(hp.z, wv, to2[o]);
            to3[o] = fmaf(hp.w, wv, to3[o]);
        }
    }
    // layer 3: NO gelu. fc1 -> gelu -> fc2 for all 4 samples.
    const float f2b = fc2b[0];
    float res0 = f2b, res1 = f2b, res2 = f2b, res3 = f2b;
#pragma unroll 2
    for (int h4 = 0; h4 < Hn / 4; h4++) {
        const float4 bb = s_fc1b[h4];
        float a0x = bb.x, a0y = bb.y, a0z = bb.z, a0w = bb.w;
        float a1x = bb.x, a1y = bb.y, a1z = bb.z, a1w = bb.w;
        float a2x = bb.x, a2y = bb.y, a2z = bb.z, a2w = bb.w;
        float a3x = bb.x, a3y = bb.y, a3z = bb.z, a3w = bb.w;
#pragma unroll
        for (int c = 0; c < Cn; c++) {
            const float4 w4 = s_fc1[c][h4];
            a0x = fmaf(to0[c], w4.x, a0x); a0y = fmaf(to0[c], w4.y, a0y);
            a0z = fmaf(to0[c], w4.z, a0z); a0w = fmaf(to0[c], w4.w, a0w);
            a1x = fmaf(to1[c], w4.x, a1x); a1y = fmaf(to1[c], w4.y, a1y);
            a1z = fmaf(to1[c], w4.z, a1z); a1w = fmaf(to1[c], w4.w, a1w);
            a2x = fmaf(to2[c], w4.x, a2x); a2y = fmaf(to2[c], w4.y, a2y);
            a2z = fmaf(to2[c], w4.z, a2z); a2w = fmaf(to2[c], w4.w, a2w);
            a3x = fmaf(to3[c], w4.x, a3x); a3y = fmaf(to3[c], w4.y, a3y);
            a3z = fmaf(to3[c], w4.z, a3z); a3w = fmaf(to3[c], w4.w, a3w);
        }
        const float4 f2 = s_fc2[h4];
        res0 += gelu_fast(a0x) * f2.x + gelu_fast(a0y) * f2.y
              + gelu_fast(a0z) * f2.z + gelu_fast(a0w) * f2.w;
        res1 += gelu_fast(a1x) * f2.x + gelu_fast(a1y) * f2.y
              + gelu_fast(a1z) * f2.z + gelu_fast(a1w) * f2.w;
        res2 += gelu_fast(a2x) * f2.x + gelu_fast(a2y) * f2.y
              + gelu_fast(a2z) * f2.z + gelu_fast(a2w) * f2.w;
        res3 += gelu_fast(a3x) * f2.x + gelu_fast(a3y) * f2.y
              + gelu_fast(a3z) * f2.z + gelu_fast(a3w) * f2.w;
    }
    *(float4*)(out + (size_t)b * Sn + s0) = make_float4(res0, res1, res2, res3);
}

// ------------------------------------------------------------------ launch
extern "C" void kernel_launch(void* const* d_in, const int* in_sizes, int n_in,
                              void* d_out, int out_size) {
    const float* x  = (const float*)d_in[0];
    const float* pd = (const float*)d_in[1];
    const float* fc0w = (const float*)d_in[2];
    const float* fc0b = (const float*)d_in[3];
    const float *fc1w, *fc1b, *fc2w, *fc2b;
    const float *sre[4], *sim[4], *lww[4], *lwb[4];

    if (in_sizes[4] == Cn * Hn) {
        fc1w = (const float*)d_in[4]; fc1b = (const float*)d_in[5];
        fc2w = (const float*)d_in[6]; fc2b = (const float*)d_in[7];
        for (int l = 0; l < 4; l++) {
            sre[l] = (const float*)d_in[8 + 4 * l];
            sim[l] = (const float*)d_in[9 + 4 * l];
            lww[l] = (const float*)d_in[10 + 4 * l];
            lwb[l] = (const float*)d_in[11 + 4 * l];
        }
    } else {
        for (int l = 0; l < 4; l++) {
            sre[l] = (const float*)d_in[4 + 4 * l];
            sim[l] = (const float*)d_in[5 + 4 * l];
            lww[l] = (const float*)d_in[6 + 4 * l];
            lwb[l] = (const float*)d_in[7 + 4 * l];
        }
        fc1w = (const float*)d_in[20]; fc1b = (const float*)d_in[21];
        fc2w = (const float*)d_in[22]; fc2b = (const float*)d_in[23];
    }

    float* out = (float*)d_out;
    const dim3 gInv(Sn / 512, Bn);

    fno_kmax<<<1, 1024>>>(pd);

    // layer 0: forward DFT + inverse both compute fc0's h on the fly
    fno_kfwd0<<<dim3(2, Cn, Bn), 256>>>(x, pd, fc0w, fc0b);
    fno_kinv4_l0<<<gInv, 128>>>(sre[0], sim[0], lww[0], lwb[0], x, pd, fc0w, fc0b);

    for (int l = 1; l < 3; l++) {
        fno_kfwd<<<dim3(2, Cn, Bn), 256>>>();
        fno_kinv4<<<gInv, 128>>>(sre[l], sim[l], lww[l], lwb[l]);
    }
    fno_kfwd<<<dim3(2, Cn, Bn), 256>>>();
    fno_kfinal4<<<gInv, 128>>>(sre[3], sim[3], lww[3], lwb[3],
                               fc1w, fc1b, fc2w, fc2b, out);
}

// round 8
// speedup vs baseline: 1.0468x; 1.0468x over previous
#include <cuda_runtime.h>
#include <math.h>

#define Bn 32
#define Cn 20
#define Sn 65536
#define Mn 16
#define Qn 4096
#define Hn 128

// Scratch (device globals; allocation-free rule)
__device__ float  g_h[(size_t)Bn * Cn * Sn];          // (B, C, S) ~168MB
__device__ float  g_partR[Bn][Cn][2][Mn];
__device__ float  g_partI[Bn][Cn][2][Mn];
__device__ float  g_maxv;
__device__ float  g_invmaxv;

// Fast gelu: A&S 7.1.28 erf approximation, |eps| <= 3e-7, branch-free.
__device__ __forceinline__ float fast_rcp(float x) {
    float r; asm("rcp.approx.f32 %0, %1;" : "=f"(r) : "f"(x)); return r;
}
__device__ __forceinline__ float gelu_fast(float x) {
    const float u = fabsf(x) * 0.7071067811865476f;
    float p = fmaf(0.0000430638f, u, 0.0002765672f);
    p = fmaf(p, u, 0.0001520143f);
    p = fmaf(p, u, 0.0092705272f);
    p = fmaf(p, u, 0.0422820123f);
    p = fmaf(p, u, 0.0705230784f);
    p = fmaf(p, u, 1.0f);
    float r = fast_rcp(p);
    r = r * r; r = r * r; r = r * r; r = r * r;   // ^16
    const float erf_v = copysignf(1.0f - r, x);
    return 0.5f * x * (1.0f + erf_v);
}

// rotation between sample s and s+1: e^{+2pi i/65536}
#define C1R 0.9999999954025773f
#define S1R 9.587379909597734e-5f

// ------------------------------------------------------------------ max
__global__ void fno_kmax(const float* __restrict__ p) {
    __shared__ float sm[1024];
    float m = -1e30f;
    for (int i = threadIdx.x; i < Sn; i += 1024) m = fmaxf(m, p[i]);
    sm[threadIdx.x] = m;
    __syncthreads();
    for (int off = 512; off; off >>= 1) {
        if (threadIdx.x < off) sm[threadIdx.x] = fmaxf(sm[threadIdx.x], sm[threadIdx.x + off]);
        __syncthreads();
    }
    if (threadIdx.x == 0) { g_maxv = sm[0]; g_invmaxv = 1.0f / sm[0]; }
}

// ================= forward truncated DFT (16 modes) ========================
__device__ __forceinline__ void dft16_accum(const float hp[16], float zr, float zi,
                                            float* Fr, float* Fi) {
    const float C16[16] = { 1.f,  0.9238795325112867f,  0.7071067811865476f,  0.3826834323650898f,
                            0.f, -0.3826834323650898f, -0.7071067811865476f, -0.9238795325112867f,
                           -1.f, -0.9238795325112867f, -0.7071067811865476f, -0.3826834323650898f,
                            0.f,  0.3826834323650898f,  0.7071067811865476f,  0.9238795325112867f };
    const float S16[16] = { 0.f,  0.3826834323650898f,  0.7071067811865476f,  0.9238795325112867f,
                            1.f,  0.9238795325112867f,  0.7071067811865476f,  0.3826834323650898f,
                            0.f, -0.3826834323650898f, -0.7071067811865476f, -0.9238795325112867f,
                           -1.f, -0.9238795325112867f, -0.7071067811865476f, -0.3826834323650898f };
    float u[8], dd[8];
#pragma unroll
    for (int p = 0; p < 8; p++) { u[p] = hp[p] + hp[p + 8]; dd[p] = hp[p] - hp[p + 8]; }
    float BR[16], BI[16];
#pragma unroll
    for (int j = 0; j <= 4; j++) {
        float ar = 0.f, ai = 0.f;
#pragma unroll
        for (int p = 0; p < 8; p++) {
            const int m = (2 * j * p) & 15;
            ar += u[p] * C16[m];
            ai -= u[p] * S16[m];
        }
        BR[2 * j] = ar; BI[2 * j] = ai;
    }
#pragma unroll
    for (int k = 1; k < 8; k += 2) {
        float ar = 0.f, ai = 0.f;
#pragma unroll
        for (int p = 0; p < 8; p++) {
            const int m = (k * p) & 15;
            ar += dd[p] * C16[m];
            ai -= dd[p] * S16[m];
        }
        BR[k] = ar; BI[k] = ai;
    }
#pragma unroll
    for (int k = 9; k < 16; k++) { BR[k] = BR[16 - k]; BI[k] = -BI[16 - k]; }

    Fr[0] += BR[0];
    Fi[0] += BI[0];
    float wr = zr, wi = zi;
#pragma unroll
    for (int k = 1; k < 16; k++) {
        Fr[k] += BR[k] * wr - BI[k] * wi;
        Fi[k] += BR[k] * wi + BI[k] * wr;
        const float nwr = wr * zr - wi * zi;
        const float nwi = wr * zi + wi * zr;
        wr = nwr; wi = nwi;
    }
}

__device__ __forceinline__ void dft16_reduce_store(float* Fr, float* Fi,
                                                   int b, int c, int qc, int tid) {
#pragma unroll
    for (int off = 16; off; off >>= 1) {
#pragma unroll
        for (int k = 0; k < Mn; k++) {
            Fr[k] += __shfl_down_sync(0xffffffffu, Fr[k], off);
            Fi[k] += __shfl_down_sync(0xffffffffu, Fi[k], off);
        }
    }
    __shared__ float redR[8][Mn], redI[8][Mn];
    const int warp = tid >> 5, lane = tid & 31;
    if (lane == 0) {
#pragma unroll
        for (int k = 0; k < Mn; k++) { redR[warp][k] = Fr[k]; redI[warp][k] = Fi[k]; }
    }
    __syncthreads();
    if (tid < Mn) {
        float ar = 0.f, ai = 0.f;
#pragma unroll
        for (int w = 0; w < 8; w++) { ar += redR[w][tid]; ai += redI[w][tid]; }
        g_partR[b][c][qc][tid] = ar;
        g_partI[b][c][qc][tid] = ai;
    }
}

// generic forward DFT: reads g_h
__global__ void __launch_bounds__(256) fno_kfwd() {
    const int qc = blockIdx.x, c = blockIdx.y, b = blockIdx.z;
    const float* __restrict__ row = g_h + ((size_t)(b * Cn + c)) * Sn;
    const int tid = threadIdx.x;
    const int q0 = qc * 2048 + tid;

    float Fr[Mn], Fi[Mn];
#pragma unroll
    for (int k = 0; k < Mn; k++) { Fr[k] = 0.f; Fi[k] = 0.f; }
    float zr, zi;
    sincospif(-(float)q0 * (1.0f / 32768.0f), &zi, &zr);
    const float Rr =  0.9996988186962042f;
    const float Ri = -0.0245412285229123f;

    for (int it = 0; it < 8; ++it) {
        const int q = q0 + it * 256;
        float hp[16];
#pragma unroll
        for (int p = 0; p < 16; p++) hp[p] = row[q + p * Qn];
        dft16_accum(hp, zr, zi, Fr, Fi);
        const float nzr = zr * Rr - zi * Ri;
        const float nzi = zr * Ri + zi * Rr;
        zr = nzr; zi = nzi;
    }
    dft16_reduce_store(Fr, Fi, b, c, qc, tid);
}

// layer-0 forward DFT: computes h on the fly from x, point_data, fc0
__global__ void __launch_bounds__(256) fno_kfwd0(const float* __restrict__ x,
                                                 const float* __restrict__ pd,
                                                 const float* __restrict__ fc0w,
                                                 const float* __restrict__ fc0b) {
    const int qc = blockIdx.x, c = blockIdx.y, b = blockIdx.z;
    const int tid = threadIdx.x;
    const int q0 = qc * 2048 + tid;
    const float w0 = fc0w[c], w1 = fc0w[Cn + c], bc = fc0b[c];
    const float invm = g_invmaxv;
    const float* __restrict__ xrow = x + (size_t)b * Sn;

    float Fr[Mn], Fi[Mn];
#pragma unroll
    for (int k = 0; k < Mn; k++) { Fr[k] = 0.f; Fi[k] = 0.f; }
    float zr, zi;
    sincospif(-(float)q0 * (1.0f / 32768.0f), &zi, &zr);
    const float Rr =  0.9996988186962042f;
    const float Ri = -0.0245412285229123f;

    for (int it = 0; it < 8; ++it) {
        const int q = q0 + it * 256;
        float hp[16];
#pragma unroll
        for (int p = 0; p < 16; p++) {
            const int s = q + p * Qn;
            hp[p] = fmaf(xrow[s], w0, fmaf(pd[s] * invm, w1, bc));
        }
        dft16_accum(hp, zr, zi, Fr, Fi);
        const float nzr = zr * Rr - zi * Ri;
        const float nzi = zr * Ri + zi * Rr;
        zr = nzr; zi = nzi;
    }
    dft16_reduce_store(Fr, Fi, b, c, qc, tid);
}

// ================= fused mode-mix into shared memory =======================
__device__ __forceinline__ void mix_to_smem(int b,
                                            const float* __restrict__ sre,
                                            const float* __restrict__ sim,
                                            const float* __restrict__ wb,
                                            float2 s_spec[Mn][Cn],
                                            float* s_base, int tid, int nthr) {
    for (int idx = tid; idx < Cn * Mn; idx += nthr) {
        const int o = idx >> 4, k = idx & 15;
        float Gr = 0.f, Gi = 0.f;
#pragma unroll
        for (int i = 0; i < Cn; i++) {
            const float fr = g_partR[b][i][0][k] + g_partR[b][i][1][k];
            const float fi = g_partI[b][i][0][k] + g_partI[b][i][1][k];
            const float wr = sre[i * (Cn * Mn) + o * Mn + k];
            const float wi = sim[i * (Cn * Mn) + o * Mn + k];
            Gr += fr * wr - fi * wi;
            Gi += fr * wi + fi * wr;
        }
        const float invS = 1.0f / (float)Sn;
        if (k == 0) s_base[o] = Gr * invS + wb[o];
        else        s_spec[k][o] = make_float2(2.f * Gr * invS, -2.f * Gi * invS);
    }
}

// ========= spectral synthesis for a pair of samples (s0, s0+1) =============
__device__ __forceinline__ void synth2(const float2 s_spec[Mn][Cn], const float* s_base,
                                       int s0, float* to0, float* to1) {
    float e0r, e0i;
    sincospif((float)s0 * (1.0f / 32768.0f), &e0i, &e0r);
    const float e1r = e0r * C1R - e0i * S1R;
    const float e1i = e0r * S1R + e0i * C1R;

#pragma unroll
    for (int o = 0; o < Cn; o++) { to0[o] = s_base[o]; to1[o] = s_base[o]; }

    float w0r = e0r, w0i = e0i, w1r = e1r, w1i = e1i;
#pragma unroll
    for (int k = 1; k < Mn; k++) {
#pragma unroll
        for (int o = 0; o < Cn; o++) {
            const float2 cc = s_spec[k][o];
            to0[o] = fmaf(cc.x, w0r, fmaf(cc.y, w0i, to0[o]));
            to1[o] = fmaf(cc.x, w1r, fmaf(cc.y, w1i, to1[o]));
        }
        if (k < Mn - 1) {
            float nr = w0r * e0r - w0i * e0i, ni = w0r * e0i + w0i * e0r;
            w0r = nr; w0i = ni;
            nr = w1r * e1r - w1i * e1i; ni = w1r * e1i + w1i * e1r;
            w1r = nr; w1i = ni;
        }
    }
}

// ---- inverse + 1x1 conv + gelu (layers 1..2), 2 samples/thread, mix fused --
__global__ void __launch_bounds__(256) fno_kinv2(const float* __restrict__ sre,
                                                 const float* __restrict__ sim,
                                                 const float* __restrict__ ww,
                                                 const float* __restrict__ wb) {
    __shared__ float2 s_spec[Mn][Cn];   // [k][o] = {cx, -cy}, k>=1
    __shared__ float  s_base[Cn];       // coef[o][0].x + wb[o]
    __shared__ float  s_ww[Cn * Cn];    // w[o][c] at o*Cn+c
    const int b = blockIdx.y;
    const int tid = threadIdx.x;
    mix_to_smem(b, sre, sim, wb, s_spec, s_base, tid, 256);
    for (int i = tid; i < Cn * Cn; i += 256) s_ww[i] = ww[i];
    __syncthreads();

    const int s0 = blockIdx.x * 512 + 2 * tid;   // pair (s0, s0+1)
    float to0[Cn], to1[Cn];
    synth2(s_spec, s_base, s0, to0, to1);

#pragma unroll
    for (int c = 0; c < Cn; c++) {
        const float2 hp = *(const float2*)(g_h + ((size_t)(b * Cn + c)) * Sn + s0);
#pragma unroll
        for (int o = 0; o < Cn; o++) {
            const float wv = s_ww[o * Cn + c];
            to0[o] = fmaf(hp.x, wv, to0[o]);
            to1[o] = fmaf(hp.y, wv, to1[o]);
        }
    }
#pragma unroll
    for (int o = 0; o < Cn; o++) {
        float2 r = make_float2(gelu_fast(to0[o]), gelu_fast(to1[o]));
        *(float2*)(g_h + ((size_t)(b * Cn + o)) * Sn + s0) = r;
    }
}

// ---- layer-0 inverse: h computed on the fly from x/pd/fc0 -----------------
__global__ void __launch_bounds__(256) fno_kinv2_l0(const float* __restrict__ sre,
                                                    const float* __restrict__ sim,
                                                    const float* __restrict__ ww,
                                                    const float* __restrict__ wb,
                                                    const float* __restrict__ x,
                                                    const float* __restrict__ pd,
                                                    const float* __restrict__ fc0w,
                                                    const float* __restrict__ fc0b) {
    __shared__ float2 s_spec[Mn][Cn];
    __shared__ float  s_base[Cn];
    __shared__ float  s_ww[Cn * Cn];
    __shared__ float  s_f0w[2 * Cn];
    __shared__ float  s_f0b[Cn];
    const int b = blockIdx.y;
    const int tid = threadIdx.x;
    mix_to_smem(b, sre, sim, wb, s_spec, s_base, tid, 256);
    for (int i = tid; i < Cn * Cn; i += 256) s_ww[i] = ww[i];
    if (tid < 2 * Cn) s_f0w[tid] = fc0w[tid];
    if (tid < Cn) s_f0b[tid] = fc0b[tid];
    __syncthreads();

    const int s0 = blockIdx.x * 512 + 2 * tid;
    float to0[Cn], to1[Cn];
    synth2(s_spec, s_base, s0, to0, to1);

    const float invm = g_invmaxv;
    const float2 xp = *(const float2*)(x + (size_t)b * Sn + s0);
    const float2 pp = *(const float2*)(pd + s0);
    const float gr0 = pp.x * invm, gr1 = pp.y * invm;
#pragma unroll
    for (int c = 0; c < Cn; c++) {
        const float w0 = s_f0w[c], w1 = s_f0w[Cn + c], bc = s_f0b[c];
        const float h0 = fmaf(xp.x, w0, fmaf(gr0, w1, bc));
        const float h1 = fmaf(xp.y, w0, fmaf(gr1, w1, bc));
#pragma unroll
        for (int o = 0; o < Cn; o++) {
            const float wv = s_ww[o * Cn + c];
            to0[o] = fmaf(h0, wv, to0[o]);
            to1[o] = fmaf(h1, wv, to1[o]);
        }
    }
#pragma unroll
    for (int o = 0; o < Cn; o++) {
        float2 r = make_float2(gelu_fast(to0[o]), gelu_fast(to1[o]));
        *(float2*)(g_h + ((size_t)(b * Cn + o)) * Sn + s0) = r;
    }
}

// ---- final: layer-3 inverse+conv (no gelu) -> fc1 -> gelu -> fc2, 2 samples
__global__ void __launch_bounds__(256) fno_kfinal2(const float* __restrict__ sre,
                                                   const float* __restrict__ sim,
                                                   const float* __restrict__ ww,
                                                   const float* __restrict__ wb,
                                                   const float* __restrict__ fc1w,
                                                   const float* __restrict__ fc1b,
                                                   const float* __restrict__ fc2w,
                                                   const float* __restrict__ fc2b,
                                                   float* __restrict__ out) {
    __shared__ float2 s_spec[Mn][Cn];
    __shared__ float  s_base[Cn];
    __shared__ float  s_ww[Cn * Cn];
    __shared__ float4 s_fc1[Cn][Hn / 4];
    __shared__ float4 s_fc1b[Hn / 4];
    __shared__ float4 s_fc2[Hn / 4];
    const int b = blockIdx.y;
    const int tid = threadIdx.x;
    mix_to_smem(b, sre, sim, wb, s_spec, s_base, tid, 256);
    for (int i = tid; i < Cn * Cn; i += 256) s_ww[i] = ww[i];
    for (int i = tid; i < Cn * (Hn / 4); i += 256) {
        const int c = i / (Hn / 4), h4 = i % (Hn / 4);
        s_fc1[c][h4] = make_float4(fc1w[c * Hn + 4 * h4 + 0], fc1w[c * Hn + 4 * h4 + 1],
                                   fc1w[c * Hn + 4 * h4 + 2], fc1w[c * Hn + 4 * h4 + 3]);
    }
    if (tid < Hn / 4) {
        s_fc1b[tid] = make_float4(fc1b[4 * tid], fc1b[4 * tid + 1], fc1b[4 * tid + 2], fc1b[4 * tid + 3]);
        s_fc2[tid]  = make_float4(fc2w[4 * tid], fc2w[4 * tid + 1], fc2w[4 * tid + 2], fc2w[4 * tid + 3]);
    }
    __syncthreads();

    const int s0 = blockIdx.x * 512 + 2 * tid;
    float to0[Cn], to1[Cn];
    synth2(s_spec, s_base, s0, to0, to1);

#pragma unroll
    for (int c = 0; c < Cn; c++) {
        const float2 hp = *(const float2*)(g_h + ((size_t)(b * Cn + c)) * Sn + s0);
#pragma unroll
        for (int o = 0; o < Cn; o++) {
            const float wv = s_ww[o * Cn + c];
            to0[o] = fmaf(hp.x, wv, to0[o]);
            to1[o] = fmaf(hp.y, wv, to1[o]);
        }
    }
    // layer 3: NO gelu. fc1 -> gelu -> fc2 for both samples.
    const float f2b = fc2b[0];
    float res0 = f2b, res1 = f2b;
#pragma unroll 4
    for (int h4 = 0; h4 < Hn / 4; h4++) {
        const float4 bb = s_fc1b[h4];
        float a0x = bb.x, a0y = bb.y, a0z = bb.z, a0w = bb.w;
        float a1x = bb.x, a1y = bb.y, a1z = bb.z, a1w = bb.w;
#pragma unroll
        for (int c = 0; c < Cn; c++) {
            const float4 w4 = s_fc1[c][h4];
            a0x = fmaf(to0[c], w4.x, a0x);
            a0y = fmaf(to0[c], w4.y, a0y);
            a0z = fmaf(to0[c], w4.z, a0z);
            a0w = fmaf(to0[c], w4.w, a0w);
            a1x = fmaf(to1[c], w4.x, a1x);
            a1y = fmaf(to1[c], w4.y, a1y);
            a1z = fmaf(to1[c], w4.z, a1z);
            a1w = fmaf(to1[c], w4.w, a1w);
        }
        const float4 f2 = s_fc2[h4];
        res0 += gelu_fast(a0x) * f2.x + gelu_fast(a0y) * f2.y
              + gelu_fast(a0z) * f2.z + gelu_fast(a0w) * f2.w;
        res1 += gelu_fast(a1x) * f2.x + gelu_fast(a1y) * f2.y
              + gelu_fast(a1z) * f2.z + gelu_fast(a1w) * f2.w;
    }
    *(float2*)(out + (size_t)b * Sn + s0) = make_float2(res0, res1);
}

// ------------------------------------------------------------------ launch
extern "C" void kernel_launch(void* const* d_in, const int* in_sizes, int n_in,
                              void* d_out, int out_size) {
    const float* x  = (const float*)d_in[0];
    const float* pd = (const float*)d_in[1];
    const float* fc0w = (const float*)d_in[2];
    const float* fc0b = (const float*)d_in[3];
    const float *fc1w, *fc1b, *fc2w, *fc2b;
    const float *sre[4], *sim[4], *lww[4], *lwb[4];

    if (in_sizes[4] == Cn * Hn) {
        fc1w = (const float*)d_in[4]; fc1b = (const float*)d_in[5];
        fc2w = (const float*)d_in[6]; fc2b = (const float*)d_in[7];
        for (int l = 0; l < 4; l++) {
            sre[l] = (const float*)d_in[8 + 4 * l];
            sim[l] = (const float*)d_in[9 + 4 * l];
            lww[l] = (const float*)d_in[10 + 4 * l];
            lwb[l] = (const float*)d_in[11 + 4 * l];
        }
    } else {
        for (int l = 0; l < 4; l++) {
            sre[l] = (const float*)d_in[4 + 4 * l];
            sim[l] = (const float*)d_in[5 + 4 * l];
            lww[l] = (const float*)d_in[6 + 4 * l];
            lwb[l] = (const float*)d_in[7 + 4 * l];
        }
        fc1w = (const float*)d_in[20]; fc1b = (const float*)d_in[21];
        fc2w = (const float*)d_in[22]; fc2b = (const float*)d_in[23];
    }

    float* out = (float*)d_out;
    const dim3 gInv(Sn / 512, Bn);

    fno_kmax<<<1, 1024>>>(pd);

    // layer 0: forward DFT + inverse both compute fc0's h on the fly
    fno_kfwd0<<<dim3(2, Cn, Bn), 256>>>(x, pd, fc0w, fc0b);
    fno_kinv2_l0<<<gInv, 256>>>(sre[0], sim[0], lww[0], lwb[0], x, pd, fc0w, fc0b);

    for (int l = 1; l < 3; l++) {
        fno_kfwd<<<dim3(2, Cn, Bn), 256>>>();
        fno_kinv2<<<gInv, 256>>>(sre[l], sim[l], lww[l], lwb[l]);
    }
    fno_kfwd<<<dim3(2, Cn, Bn), 256>>>();
    fno_kfinal2<<<gInv, 256>>>(sre[3], sim[3], lww[3], lwb[3],
                               fc1w, fc1b, fc2w, fc2b, out);
}

// round 9
// speedup vs baseline: 1.1612x; 1.1093x over previous
#include <cuda_runtime.h>
#include <math.h>

#define Bn 32
#define Cn 20
#define Sn 65536
#define Mn 16
#define Qn 4096
#define Hn 128

// Scratch (device globals; allocation-free rule)
__device__ float  g_h[(size_t)Bn * Cn * Sn];          // (B, C, S) ~168MB
__device__ float  g_partR[Bn][Cn][2][Mn];
__device__ float  g_partI[Bn][Cn][2][Mn];
__device__ float2 g_coef[Bn][Cn][Mn];
__device__ float  g_maxv;
__device__ float  g_invmaxv;

// Fast gelu: A&S 7.1.28 erf approximation, |eps| <= 3e-7, branch-free.
__device__ __forceinline__ float fast_rcp(float x) {
    float r; asm("rcp.approx.f32 %0, %1;" : "=f"(r) : "f"(x)); return r;
}
__device__ __forceinline__ float gelu_fast(float x) {
    const float u = fabsf(x) * 0.7071067811865476f;
    float p = fmaf(0.0000430638f, u, 0.0002765672f);
    p = fmaf(p, u, 0.0001520143f);
    p = fmaf(p, u, 0.0092705272f);
    p = fmaf(p, u, 0.0422820123f);
    p = fmaf(p, u, 0.0705230784f);
    p = fmaf(p, u, 1.0f);
    float r = fast_rcp(p);
    r = r * r; r = r * r; r = r * r; r = r * r;   // ^16
    const float erf_v = copysignf(1.0f - r, x);
    return 0.5f * x * (1.0f + erf_v);
}

// rotation between sample s and s+1: e^{+2pi i/65536}
#define C1R 0.9999999954025773f
#define S1R 9.587379909597734e-5f

// ------------------------------------------------------------------ max
__global__ void fno_kmax(const float* __restrict__ p) {
    __shared__ float sm[1024];
    float m = -1e30f;
    for (int i = threadIdx.x; i < Sn; i += 1024) m = fmaxf(m, p[i]);
    sm[threadIdx.x] = m;
    __syncthreads();
    for (int off = 512; off; off >>= 1) {
        if (threadIdx.x < off) sm[threadIdx.x] = fmaxf(sm[threadIdx.x], sm[threadIdx.x + off]);
        __syncthreads();
    }
    if (threadIdx.x == 0) { g_maxv = sm[0]; g_invmaxv = 1.0f / sm[0]; }
}

// ================= forward truncated DFT (16 modes) ========================
__device__ __forceinline__ void dft16_accum(const float hp[16], float zr, float zi,
                                            float* Fr, float* Fi) {
    const float C16[16] = { 1.f,  0.9238795325112867f,  0.7071067811865476f,  0.3826834323650898f,
                            0.f, -0.3826834323650898f, -0.7071067811865476f, -0.9238795325112867f,
                           -1.f, -0.9238795325112867f, -0.7071067811865476f, -0.3826834323650898f,
                            0.f,  0.3826834323650898f,  0.7071067811865476f,  0.9238795325112867f };
    const float S16[16] = { 0.f,  0.3826834323650898f,  0.7071067811865476f,  0.9238795325112867f,
                            1.f,  0.9238795325112867f,  0.7071067811865476f,  0.3826834323650898f,
                            0.f, -0.3826834323650898f, -0.7071067811865476f, -0.9238795325112867f,
                           -1.f, -0.9238795325112867f, -0.7071067811865476f, -0.3826834323650898f };
    float u[8], dd[8];
#pragma unroll
    for (int p = 0; p < 8; p++) { u[p] = hp[p] + hp[p + 8]; dd[p] = hp[p] - hp[p + 8]; }
    float BR[16], BI[16];
#pragma unroll
    for (int j = 0; j <= 4; j++) {
        float ar = 0.f, ai = 0.f;
#pragma unroll
        for (int p = 0; p < 8; p++) {
            const int m = (2 * j * p) & 15;
            ar += u[p] * C16[m];
            ai -= u[p] * S16[m];
        }
        BR[2 * j] = ar; BI[2 * j] = ai;
    }
#pragma unroll
    for (int k = 1; k < 8; k += 2) {
        float ar = 0.f, ai = 0.f;
#pragma unroll
        for (int p = 0; p < 8; p++) {
            const int m = (k * p) & 15;
            ar += dd[p] * C16[m];
            ai -= dd[p] * S16[m];
        }
        BR[k] = ar; BI[k] = ai;
    }
#pragma unroll
    for (int k = 9; k < 16; k++) { BR[k] = BR[16 - k]; BI[k] = -BI[16 - k]; }

    Fr[0] += BR[0];
    Fi[0] += BI[0];
    float wr = zr, wi = zi;
#pragma unroll
    for (int k = 1; k < 16; k++) {
        Fr[k] += BR[k] * wr - BI[k] * wi;
        Fi[k] += BR[k] * wi + BI[k] * wr;
        const float nwr = wr * zr - wi * zi;
        const float nwi = wr * zi + wi * zr;
        wr = nwr; wi = nwi;
    }
}

__device__ __forceinline__ void dft16_reduce_store(float* Fr, float* Fi,
                                                   int b, int c, int qc, int tid) {
#pragma unroll
    for (int off = 16; off; off >>= 1) {
#pragma unroll
        for (int k = 0; k < Mn; k++) {
            Fr[k] += __shfl_down_sync(0xffffffffu, Fr[k], off);
            Fi[k] += __shfl_down_sync(0xffffffffu, Fi[k], off);
        }
    }
    __shared__ float redR[8][Mn], redI[8][Mn];
    const int warp = tid >> 5, lane = tid & 31;
    if (lane == 0) {
#pragma unroll
        for (int k = 0; k < Mn; k++) { redR[warp][k] = Fr[k]; redI[warp][k] = Fi[k]; }
    }
    __syncthreads();
    if (tid < Mn) {
        float ar = 0.f, ai = 0.f;
#pragma unroll
        for (int w = 0; w < 8; w++) { ar += redR[w][tid]; ai += redI[w][tid]; }
        g_partR[b][c][qc][tid] = ar;
        g_partI[b][c][qc][tid] = ai;
    }
}

// generic forward DFT: reads g_h
__global__ void __launch_bounds__(256) fno_kfwd() {
    const int qc = blockIdx.x, c = blockIdx.y, b = blockIdx.z;
    const float* __restrict__ row = g_h + ((size_t)(b * Cn + c)) * Sn;
    const int tid = threadIdx.x;
    const int q0 = qc * 2048 + tid;

    float Fr[Mn], Fi[Mn];
#pragma unroll
    for (int k = 0; k < Mn; k++) { Fr[k] = 0.f; Fi[k] = 0.f; }
    float zr, zi;
    sincospif(-(float)q0 * (1.0f / 32768.0f), &zi, &zr);
    const float Rr =  0.9996988186962042f;
    const float Ri = -0.0245412285229123f;

    for (int it = 0; it < 8; ++it) {
        const int q = q0 + it * 256;
        float hp[16];
#pragma unroll
        for (int p = 0; p < 16; p++) hp[p] = row[q + p * Qn];
        dft16_accum(hp, zr, zi, Fr, Fi);
        const float nzr = zr * Rr - zi * Ri;
        const float nzi = zr * Ri + zi * Rr;
        zr = nzr; zi = nzi;
    }
    dft16_reduce_store(Fr, Fi, b, c, qc, tid);
}

// layer-0 forward DFT: computes h on the fly from x, point_data, fc0
__global__ void __launch_bounds__(256) fno_kfwd0(const float* __restrict__ x,
                                                 const float* __restrict__ pd,
                                                 const float* __restrict__ fc0w,
                                                 const float* __restrict__ fc0b) {
    const int qc = blockIdx.x, c = blockIdx.y, b = blockIdx.z;
    const int tid = threadIdx.x;
    const int q0 = qc * 2048 + tid;
    const float w0 = fc0w[c], w1 = fc0w[Cn + c], bc = fc0b[c];
    const float invm = g_invmaxv;
    const float* __restrict__ xrow = x + (size_t)b * Sn;

    float Fr[Mn], Fi[Mn];
#pragma unroll
    for (int k = 0; k < Mn; k++) { Fr[k] = 0.f; Fi[k] = 0.f; }
    float zr, zi;
    sincospif(-(float)q0 * (1.0f / 32768.0f), &zi, &zr);
    const float Rr =  0.9996988186962042f;
    const float Ri = -0.0245412285229123f;

    for (int it = 0; it < 8; ++it) {
        const int q = q0 + it * 256;
        float hp[16];
#pragma unroll
        for (int p = 0; p < 16; p++) {
            const int s = q + p * Qn;
            hp[p] = fmaf(xrow[s], w0, fmaf(pd[s] * invm, w1, bc));
        }
        dft16_accum(hp, zr, zi, Fr, Fi);
        const float nzr = zr * Rr - zi * Ri;
        const float nzi = zr * Ri + zi * Rr;
        zr = nzr; zi = nzi;
    }
    dft16_reduce_store(Fr, Fi, b, c, qc, tid);
}

// ------------------------------------------------------------------ mode mixing
// grid (Bn, Cn) blocks x 32 threads: k = tid&15, half = tid>>4 sums 10 inputs,
// shfl-combine (deterministic fixed order), lanes 0..15 write.
__global__ void fno_kmix(const float* __restrict__ sre, const float* __restrict__ sim) {
    const int b = blockIdx.x, o = blockIdx.y;
    const int tid = threadIdx.x;
    const int k = tid & 15, ih = tid >> 4;
    float Gr = 0.f, Gi = 0.f;
#pragma unroll
    for (int j = 0; j < Cn / 2; j++) {
        const int i = ih * (Cn / 2) + j;
        const float fr = g_partR[b][i][0][k] + g_partR[b][i][1][k];
        const float fi = g_partI[b][i][0][k] + g_partI[b][i][1][k];
        const float wr = sre[i * (Cn * Mn) + o * Mn + k];
        const float wi = sim[i * (Cn * Mn) + o * Mn + k];
        Gr += fr * wr - fi * wi;
        Gi += fr * wi + fi * wr;
    }
    Gr += __shfl_down_sync(0xffffffffu, Gr, 16);
    Gi += __shfl_down_sync(0xffffffffu, Gi, 16);
    if (tid < 16) {
        const float invS = 1.0f / (float)Sn;
        float2 cf;
        if (k == 0) { cf.x = Gr * invS; cf.y = 0.f; }
        else        { cf.x = 2.f * Gr * invS; cf.y = 2.f * Gi * invS; }
        g_coef[b][o][k] = cf;
    }
}

// ========= spectral synthesis for a pair of samples (s0, s0+1) =============
__device__ __forceinline__ void synth2(const float2 s_spec[Mn][Cn], const float* s_base,
                                       int s0, float* to0, float* to1) {
    float e0r, e0i;
    sincospif((float)s0 * (1.0f / 32768.0f), &e0i, &e0r);
    const float e1r = e0r * C1R - e0i * S1R;
    const float e1i = e0r * S1R + e0i * C1R;

#pragma unroll
    for (int o = 0; o < Cn; o++) { to0[o] = s_base[o]; to1[o] = s_base[o]; }

    float w0r = e0r, w0i = e0i, w1r = e1r, w1i = e1i;
#pragma unroll
    for (int k = 1; k < Mn; k++) {
#pragma unroll
        for (int o = 0; o < Cn; o++) {
            const float2 cc = s_spec[k][o];
            to0[o] = fmaf(cc.x, w0r, fmaf(cc.y, w0i, to0[o]));
            to1[o] = fmaf(cc.x, w1r, fmaf(cc.y, w1i, to1[o]));
        }
        if (k < Mn - 1) {
            float nr = w0r * e0r - w0i * e0i, ni = w0r * e0i + w0i * e0r;
            w0r = nr; w0i = ni;
            nr = w1r * e1r - w1i * e1i; ni = w1r * e1i + w1i * e1r;
            w1r = nr; w1i = ni;
        }
    }
}

// shared-mem staging of g_coef (R6 style: cheap direct loads)
__device__ __forceinline__ void coef_to_smem(int b, const float* __restrict__ wb,
                                             float2 s_spec[Mn][Cn], float* s_base,
                                             int tid, int nthr) {
    for (int i = tid; i < Cn * Mn; i += nthr) {
        const int o = i >> 4, k = i & 15;
        const float2 cf = g_coef[b][o][k];
        if (k == 0) s_base[o] = cf.x + wb[o];
        else        s_spec[k][o] = make_float2(cf.x, -cf.y);
    }
}

// ---- inverse + 1x1 conv + gelu (layers 1..2), 2 samples/thread -------------
__global__ void __launch_bounds__(256) fno_kinv2(const float* __restrict__ ww,
                                                 const float* __restrict__ wb) {
    __shared__ float2 s_spec[Mn][Cn];   // [k][o] = {cx, -cy}, k>=1
    __shared__ float  s_base[Cn];       // coef[o][0].x + wb[o]
    __shared__ float  s_ww[Cn * Cn];    // w[o][c] at o*Cn+c
    const int b = blockIdx.y;
    const int tid = threadIdx.x;
    coef_to_smem(b, wb, s_spec, s_base, tid, 256);
    for (int i = tid; i < Cn * Cn; i += 256) s_ww[i] = ww[i];
    __syncthreads();

    const int s0 = blockIdx.x * 512 + 2 * tid;   // pair (s0, s0+1)
    float to0[Cn], to1[Cn];
    synth2(s_spec, s_base, s0, to0, to1);

#pragma unroll
    for (int c = 0; c < Cn; c++) {
        const float2 hp = *(const float2*)(g_h + ((size_t)(b * Cn + c)) * Sn + s0);
#pragma unroll
        for (int o = 0; o < Cn; o++) {
            const float wv = s_ww[o * Cn + c];
            to0[o] = fmaf(hp.x, wv, to0[o]);
            to1[o] = fmaf(hp.y, wv, to1[o]);
        }
    }
#pragma unroll
    for (int o = 0; o < Cn; o++) {
        float2 r = make_float2(gelu_fast(to0[o]), gelu_fast(to1[o]));
        *(float2*)(g_h + ((size_t)(b * Cn + o)) * Sn + s0) = r;
    }
}

// ---- layer-0 inverse: h computed on the fly from x/pd/fc0 -----------------
__global__ void __launch_bounds__(256) fno_kinv2_l0(const float* __restrict__ ww,
                                                    const float* __restrict__ wb,
                                                    const float* __restrict__ x,
                                                    const float* __restrict__ pd,
                                                    const float* __restrict__ fc0w,
                                                    const float* __restrict__ fc0b) {
    __shared__ float2 s_spec[Mn][Cn];
    __shared__ float  s_base[Cn];
    __shared__ float  s_ww[Cn * Cn];
    __shared__ float  s_f0w[2 * Cn];
    __shared__ float  s_f0b[Cn];
    const int b = blockIdx.y;
    const int tid = threadIdx.x;
    coef_to_smem(b, wb, s_spec, s_base, tid, 256);
    for (int i = tid; i < Cn * Cn; i += 256) s_ww[i] = ww[i];
    if (tid < 2 * Cn) s_f0w[tid] = fc0w[tid];
    if (tid < Cn) s_f0b[tid] = fc0b[tid];
    __syncthreads();

    const int s0 = blockIdx.x * 512 + 2 * tid;
    float to0[Cn], to1[Cn];
    synth2(s_spec, s_base, s0, to0, to1);

    const float invm = g_invmaxv;
    const float2 xp = *(const float2*)(x + (size_t)b * Sn + s0);
    const float2 pp = *(const float2*)(pd + s0);
    const float gr0 = pp.x * invm, gr1 = pp.y * invm;
#pragma unroll
    for (int c = 0; c < Cn; c++) {
        const float w0 = s_f0w[c], w1 = s_f0w[Cn + c], bc = s_f0b[c];
        const float h0 = fmaf(xp.x, w0, fmaf(gr0, w1, bc));
        const float h1 = fmaf(xp.y, w0, fmaf(gr1, w1, bc));
#pragma unroll
        for (int o = 0; o < Cn; o++) {
            const float wv = s_ww[o * Cn + c];
            to0[o] = fmaf(h0, wv, to0[o]);
            to1[o] = fmaf(h1, wv, to1[o]);
        }
    }
#pragma unroll
    for (int o = 0; o < Cn; o++) {
        float2 r = make_float2(gelu_fast(to0[o]), gelu_fast(to1[o]));
        *(float2*)(g_h + ((size_t)(b * Cn + o)) * Sn + s0) = r;
    }
}

// ---- final: layer-3 inverse+conv (no gelu) -> fc1 -> gelu -> fc2, 2 samples
__global__ void __launch_bounds__(256) fno_kfinal2(const float* __restrict__ ww,
                                                   const float* __restrict__ wb,
                                                   const float* __restrict__ fc1w,
                                                   const float* __restrict__ fc1b,
                                                   const float* __restrict__ fc2w,
                                                   const float* __restrict__ fc2b,
                                                   float* __restrict__ out) {
    __shared__ float2 s_spec[Mn][Cn];
    __shared__ float  s_base[Cn];
    __shared__ float  s_ww[Cn * Cn];
    __shared__ float4 s_fc1[Cn][Hn / 4];
    __shared__ float4 s_fc1b[Hn / 4];
    __shared__ float4 s_fc2[Hn / 4];
    const int b = blockIdx.y;
    const int tid = threadIdx.x;
    coef_to_smem(b, wb, s_spec, s_base, tid, 256);
    for (int i = tid; i < Cn * Cn; i += 256) s_ww[i] = ww[i];
    for (int i = tid; i < Cn * (Hn / 4); i += 256) {
        const int c = i / (Hn / 4), h4 = i % (Hn / 4);
        s_fc1[c][h4] = make_float4(fc1w[c * Hn + 4 * h4 + 0], fc1w[c * Hn + 4 * h4 + 1],
                                   fc1w[c * Hn + 4 * h4 + 2], fc1w[c * Hn + 4 * h4 + 3]);
    }
    if (tid < Hn / 4) {
        s_fc1b[tid] = make_float4(fc1b[4 * tid], fc1b[4 * tid + 1], fc1b[4 * tid + 2], fc1b[4 * tid + 3]);
        s_fc2[tid]  = make_float4(fc2w[4 * tid], fc2w[4 * tid + 1], fc2w[4 * tid + 2], fc2w[4 * tid + 3]);
    }
    __syncthreads();

    const int s0 = blockIdx.x * 512 + 2 * tid;
    float to0[Cn], to1[Cn];
    synth2(s_spec, s_base, s0, to0, to1);

#pragma unroll
    for (int c = 0; c < Cn; c++) {
        const float2 hp = *(const float2*)(g_h + ((size_t)(b * Cn + c)) * Sn + s0);
#pragma unroll
        for (int o = 0; o < Cn; o++) {
            const float wv = s_ww[o * Cn + c];
            to0[o] = fmaf(hp.x, wv, to0[o]);
            to1[o] = fmaf(hp.y, wv, to1[o]);
        }
    }
    // layer 3: NO gelu. fc1 -> gelu -> fc2 for both samples.
    const float f2b = fc2b[0];
    float res0 = f2b, res1 = f2b;
#pragma unroll 4
    for (int h4 = 0; h4 < Hn / 4; h4++) {
        const float4 bb = s_fc1b[h4];
        float a0x = bb.x, a0y = bb.y, a0z = bb.z, a0w = bb.w;
        float a1x = bb.x, a1y = bb.y, a1z = bb.z, a1w = bb.w;
#pragma unroll
        for (int c = 0; c < Cn; c++) {
            const float4 w4 = s_fc1[c][h4];
            a0x = fmaf(to0[c], w4.x, a0x);
            a0y = fmaf(to0[c], w4.y, a0y);
            a0z = fmaf(to0[c], w4.z, a0z);
            a0w = fmaf(to0[c], w4.w, a0w);
            a1x = fmaf(to1[c], w4.x, a1x);
            a1y = fmaf(to1[c], w4.y, a1y);
            a1z = fmaf(to1[c], w4.z, a1z);
            a1w = fmaf(to1[c], w4.w, a1w);
        }
        const float4 f2 = s_fc2[h4];
        res0 += gelu_fast(a0x) * f2.x + gelu_fast(a0y) * f2.y
              + gelu_fast(a0z) * f2.z + gelu_fast(a0w) * f2.w;
        res1 += gelu_fast(a1x) * f2.x + gelu_fast(a1y) * f2.y
              + gelu_fast(a1z) * f2.z + gelu_fast(a1w) * f2.w;
    }
    *(float2*)(out + (size_t)b * Sn + s0) = make_float2(res0, res1);
}

// ------------------------------------------------------------------ launch
extern "C" void kernel_launch(void* const* d_in, const int* in_sizes, int n_in,
                              void* d_out, int out_size) {
    const float* x  = (const float*)d_in[0];
    const float* pd = (const float*)d_in[1];
    const float* fc0w = (const float*)d_in[2];
    const float* fc0b = (const float*)d_in[3];
    const float *fc1w, *fc1b, *fc2w, *fc2b;
    const float *sre[4], *sim[4], *lww[4], *lwb[4];

    if (in_sizes[4] == Cn * Hn) {
        fc1w = (const float*)d_in[4]; fc1b = (const float*)d_in[5];
        fc2w = (const float*)d_in[6]; fc2b = (const float*)d_in[7];
        for (int l = 0; l < 4; l++) {
            sre[l] = (const float*)d_in[8 + 4 * l];
            sim[l] = (const float*)d_in[9 + 4 * l];
            lww[l] = (const float*)d_in[10 + 4 * l];
            lwb[l] = (const float*)d_in[11 + 4 * l];
        }
    } else {
        for (int l = 0; l < 4; l++) {
            sre[l] = (const float*)d_in[4 + 4 * l];
            sim[l] = (const float*)d_in[5 + 4 * l];
            lww[l] = (const float*)d_in[6 + 4 * l];
            lwb[l] = (const float*)d_in[7 + 4 * l];
        }
        fc1w = (const float*)d_in[20]; fc1b = (const float*)d_in[21];
        fc2w = (const float*)d_in[22]; fc2b = (const float*)d_in[23];
    }

    float* out = (float*)d_out;
    const dim3 gInv(Sn / 512, Bn);
    const dim3 gMix(Bn, Cn);

    fno_kmax<<<1, 1024>>>(pd);

    // layer 0: forward DFT + inverse both compute fc0's h on the fly
    fno_kfwd0<<<dim3(2, Cn, Bn), 256>>>(x, pd, fc0w, fc0b);
    fno_kmix<<<gMix, 32>>>(sre[0], sim[0]);
    fno_kinv2_l0<<<gInv, 256>>>(lww[0], lwb[0], x, pd, fc0w, fc0b);

    for (int l = 1; l < 3; l++) {
        fno_kfwd<<<dim3(2, Cn, Bn), 256>>>();
        fno_kmix<<<gMix, 32>>>(sre[l], sim[l]);
        fno_kinv2<<<gInv, 256>>>(lww[l], lwb[l]);
    }
    fno_kfwd<<<dim3(2, Cn, Bn), 256>>>();
    fno_kmix<<<gMix, 32>>>(sre[3], sim[3]);
    fno_kfinal2<<<gInv, 256>>>(lww[3], lwb[3], fc1w, fc1b, fc2w, fc2b, out);
}

// round 10
// speedup vs baseline: 1.2601x; 1.0851x over previous
#include <cuda_runtime.h>
#include <math.h>

#define Bn 32
#define Cn 20
#define Sn 65536
#define Mn 16
#define Qn 4096
#define Hn 128

// Scratch (device globals; allocation-free rule)
__device__ float  g_h[(size_t)Bn * Cn * Sn];          // (B, C, S) ~168MB
__device__ float  g_partR[Bn][Cn][2][Mn];
__device__ float  g_partI[Bn][Cn][2][Mn];
__device__ float2 g_coef[Bn][Cn][Mn];
__device__ float  g_maxv;
__device__ float  g_invmaxv;

// Fast gelu: A&S 7.1.28 erf approximation, |eps| <= 3e-7, branch-free.
__device__ __forceinline__ float fast_rcp(float x) {
    float r; asm("rcp.approx.f32 %0, %1;" : "=f"(r) : "f"(x)); return r;
}
__device__ __forceinline__ float gelu_fast(float x) {
    const float u = fabsf(x) * 0.7071067811865476f;
    float p = fmaf(0.0000430638f, u, 0.0002765672f);
    p = fmaf(p, u, 0.0001520143f);
    p = fmaf(p, u, 0.0092705272f);
    p = fmaf(p, u, 0.0422820123f);
    p = fmaf(p, u, 0.0705230784f);
    p = fmaf(p, u, 1.0f);
    float r = fast_rcp(p);
    r = r * r; r = r * r; r = r * r; r = r * r;   // ^16
    const float erf_v = copysignf(1.0f - r, x);
    return 0.5f * x * (1.0f + erf_v);
}

// rotation between sample s and s+1: e^{+2pi i/65536}
#define C1R 0.9999999954025773f
#define S1R 9.587379909597734e-5f

// ------------------------------------------------------------------ max
__global__ void fno_kmax(const float* __restrict__ p) {
    __shared__ float sm[1024];
    float m = -1e30f;
    for (int i = threadIdx.x; i < Sn; i += 1024) m = fmaxf(m, p[i]);
    sm[threadIdx.x] = m;
    __syncthreads();
    for (int off = 512; off; off >>= 1) {
        if (threadIdx.x < off) sm[threadIdx.x] = fmaxf(sm[threadIdx.x], sm[threadIdx.x + off]);
        __syncthreads();
    }
    if (threadIdx.x == 0) { g_maxv = sm[0]; g_invmaxv = 1.0f / sm[0]; }
}

// ================= forward truncated DFT (16 modes) ========================
__device__ __forceinline__ void dft16_accum(const float hp[16], float zr, float zi,
                                            float* Fr, float* Fi) {
    const float C16[16] = { 1.f,  0.9238795325112867f,  0.7071067811865476f,  0.3826834323650898f,
                            0.f, -0.3826834323650898f, -0.7071067811865476f, -0.9238795325112867f,
                           -1.f, -0.9238795325112867f, -0.7071067811865476f, -0.3826834323650898f,
                            0.f,  0.3826834323650898f,  0.7071067811865476f,  0.9238795325112867f };
    const float S16[16] = { 0.f,  0.3826834323650898f,  0.7071067811865476f,  0.9238795325112867f,
                            1.f,  0.9238795325112867f,  0.7071067811865476f,  0.3826834323650898f,
                            0.f, -0.3826834323650898f, -0.7071067811865476f, -0.9238795325112867f,
                           -1.f, -0.9238795325112867f, -0.7071067811865476f, -0.3826834323650898f };
    float u[8], dd[8];
#pragma unroll
    for (int p = 0; p < 8; p++) { u[p] = hp[p] + hp[p + 8]; dd[p] = hp[p] - hp[p + 8]; }
    float BR[16], BI[16];
#pragma unroll
    for (int j = 0; j <= 4; j++) {
        float ar = 0.f, ai = 0.f;
#pragma unroll
        for (int p = 0; p < 8; p++) {
            const int m = (2 * j * p) & 15;
            ar += u[p] * C16[m];
            ai -= u[p] * S16[m];
        }
        BR[2 * j] = ar; BI[2 * j] = ai;
    }
#pragma unroll
    for (int k = 1; k < 8; k += 2) {
        float ar = 0.f, ai = 0.f;
#pragma unroll
        for (int p = 0; p < 8; p++) {
            const int m = (k * p) & 15;
            ar += dd[p] * C16[m];
            ai -= dd[p] * S16[m];
        }
        BR[k] = ar; BI[k] = ai;
    }
#pragma unroll
    for (int k = 9; k < 16; k++) { BR[k] = BR[16 - k]; BI[k] = -BI[16 - k]; }

    Fr[0] += BR[0];
    Fi[0] += BI[0];
    float wr = zr, wi = zi;
#pragma unroll
    for (int k = 1; k < 16; k++) {
        Fr[k] += BR[k] * wr - BI[k] * wi;
        Fi[k] += BR[k] * wi + BI[k] * wr;
        const float nwr = wr * zr - wi * zi;
        const float nwi = wr * zi + wi * zr;
        wr = nwr; wi = nwi;
    }
}

__device__ __forceinline__ void dft16_reduce_store(float* Fr, float* Fi,
                                                   int b, int c, int qc, int tid) {
#pragma unroll
    for (int off = 16; off; off >>= 1) {
#pragma unroll
        for (int k = 0; k < Mn; k++) {
            Fr[k] += __shfl_down_sync(0xffffffffu, Fr[k], off);
            Fi[k] += __shfl_down_sync(0xffffffffu, Fi[k], off);
        }
    }
    __shared__ float redR[8][Mn], redI[8][Mn];
    const int warp = tid >> 5, lane = tid & 31;
    if (lane == 0) {
#pragma unroll
        for (int k = 0; k < Mn; k++) { redR[warp][k] = Fr[k]; redI[warp][k] = Fi[k]; }
    }
    __syncthreads();
    if (tid < Mn) {
        float ar = 0.f, ai = 0.f;
#pragma unroll
        for (int w = 0; w < 8; w++) { ar += redR[w][tid]; ai += redI[w][tid]; }
        g_partR[b][c][qc][tid] = ar;
        g_partI[b][c][qc][tid] = ai;
    }
}

// generic forward DFT: reads g_h (2x unrolled for MLP)
__global__ void __launch_bounds__(256) fno_kfwd() {
    const int qc = blockIdx.x, c = blockIdx.y, b = blockIdx.z;
    const float* __restrict__ row = g_h + ((size_t)(b * Cn + c)) * Sn;
    const int tid = threadIdx.x;
    const int q0 = qc * 2048 + tid;

    float Fr[Mn], Fi[Mn];
#pragma unroll
    for (int k = 0; k < Mn; k++) { Fr[k] = 0.f; Fi[k] = 0.f; }
    float zr, zi;
    sincospif(-(float)q0 * (1.0f / 32768.0f), &zi, &zr);
    const float Rr =  0.9996988186962042f;
    const float Ri = -0.0245412285229123f;

    for (int it = 0; it < 8; it += 2) {
        const int qa = q0 + it * 256;
        const int qb = qa + 256;
        float hpa[16], hpb[16];
#pragma unroll
        for (int p = 0; p < 16; p++) hpa[p] = row[qa + p * Qn];
#pragma unroll
        for (int p = 0; p < 16; p++) hpb[p] = row[qb + p * Qn];
        dft16_accum(hpa, zr, zi, Fr, Fi);
        {
            const float nzr = zr * Rr - zi * Ri;
            const float nzi = zr * Ri + zi * Rr;
            zr = nzr; zi = nzi;
        }
        dft16_accum(hpb, zr, zi, Fr, Fi);
        {
            const float nzr = zr * Rr - zi * Ri;
            const float nzi = zr * Ri + zi * Rr;
            zr = nzr; zi = nzi;
        }
    }
    dft16_reduce_store(Fr, Fi, b, c, qc, tid);
}

// layer-0 forward DFT: computes h on the fly from x, point_data, fc0 (2x unrolled)
__global__ void __launch_bounds__(256) fno_kfwd0(const float* __restrict__ x,
                                                 const float* __restrict__ pd,
                                                 const float* __restrict__ fc0w,
                                                 const float* __restrict__ fc0b) {
    const int qc = blockIdx.x, c = blockIdx.y, b = blockIdx.z;
    const int tid = threadIdx.x;
    const int q0 = qc * 2048 + tid;
    const float w0 = fc0w[c], w1 = fc0w[Cn + c], bc = fc0b[c];
    const float invm = g_invmaxv;
    const float* __restrict__ xrow = x + (size_t)b * Sn;

    float Fr[Mn], Fi[Mn];
#pragma unroll
    for (int k = 0; k < Mn; k++) { Fr[k] = 0.f; Fi[k] = 0.f; }
    float zr, zi;
    sincospif(-(float)q0 * (1.0f / 32768.0f), &zi, &zr);
    const float Rr =  0.9996988186962042f;
    const float Ri = -0.0245412285229123f;

    for (int it = 0; it < 8; it += 2) {
        const int qa = q0 + it * 256;
        const int qb = qa + 256;
        float xa[16], pa[16], xb[16], pb[16];
#pragma unroll
        for (int p = 0; p < 16; p++) { xa[p] = xrow[qa + p * Qn]; pa[p] = pd[qa + p * Qn]; }
#pragma unroll
        for (int p = 0; p < 16; p++) { xb[p] = xrow[qb + p * Qn]; pb[p] = pd[qb + p * Qn]; }
        float hpa[16], hpb[16];
#pragma unroll
        for (int p = 0; p < 16; p++) hpa[p] = fmaf(xa[p], w0, fmaf(pa[p] * invm, w1, bc));
#pragma unroll
        for (int p = 0; p < 16; p++) hpb[p] = fmaf(xb[p], w0, fmaf(pb[p] * invm, w1, bc));
        dft16_accum(hpa, zr, zi, Fr, Fi);
        {
            const float nzr = zr * Rr - zi * Ri;
            const float nzi = zr * Ri + zi * Rr;
            zr = nzr; zi = nzi;
        }
        dft16_accum(hpb, zr, zi, Fr, Fi);
        {
            const float nzr = zr * Rr - zi * Ri;
            const float nzi = zr * Ri + zi * Rr;
            zr = nzr; zi = nzi;
        }
    }
    dft16_reduce_store(Fr, Fi, b, c, qc, tid);
}

// ------------------------------------------------------------------ mode mixing
__global__ void fno_kmix(const float* __restrict__ sre, const float* __restrict__ sim) {
    const int b = blockIdx.x, o = blockIdx.y;
    const int tid = threadIdx.x;
    const int k = tid & 15, ih = tid >> 4;
    float Gr = 0.f, Gi = 0.f;
#pragma unroll
    for (int j = 0; j < Cn / 2; j++) {
        const int i = ih * (Cn / 2) + j;
        const float fr = g_partR[b][i][0][k] + g_partR[b][i][1][k];
        const float fi = g_partI[b][i][0][k] + g_partI[b][i][1][k];
        const float wr = sre[i * (Cn * Mn) + o * Mn + k];
        const float wi = sim[i * (Cn * Mn) + o * Mn + k];
        Gr += fr * wr - fi * wi;
        Gi += fr * wi + fi * wr;
    }
    Gr += __shfl_down_sync(0xffffffffu, Gr, 16);
    Gi += __shfl_down_sync(0xffffffffu, Gi, 16);
    if (tid < 16) {
        const float invS = 1.0f / (float)Sn;
        float2 cf;
        if (k == 0) { cf.x = Gr * invS; cf.y = 0.f; }
        else        { cf.x = 2.f * Gr * invS; cf.y = 2.f * Gi * invS; }
        g_coef[b][o][k] = cf;
    }
}

// ===== shared staging: spectral coefs packed float4 (o-pairs), conv wT =====
// s_spec4[k][j] = {cx(2j), -cy(2j), cx(2j+1), -cy(2j+1)}, k >= 1
__device__ __forceinline__ void coef_to_smem4(int b, const float* __restrict__ wb,
                                              float4 s_spec4[Mn][Cn / 2], float* s_base,
                                              int tid, int nthr) {
    float* specf = (float*)s_spec4;
    for (int i = tid; i < Cn * Mn; i += nthr) {
        const int o = i >> 4, k = i & 15;
        const float2 cf = g_coef[b][o][k];
        if (k == 0) s_base[o] = cf.x + wb[o];
        else {
            const int idx = k * (Cn * 2) + (o >> 1) * 4 + (o & 1) * 2;
            specf[idx]     = cf.x;
            specf[idx + 1] = -cf.y;
        }
    }
}

// transposed conv weights: s_wwT[c][o] = ww[o*Cn+c]  (o-contiguous rows)
__device__ __forceinline__ void ww_to_smemT(const float* __restrict__ ww,
                                            float s_wwT[Cn][Cn], int tid, int nthr) {
    for (int i = tid; i < Cn * Cn; i += nthr) {
        const int o = i / Cn, c = i % Cn;
        s_wwT[c][o] = ww[i];
    }
}

// ========= spectral synthesis for a pair of samples (s0, s0+1) =============
__device__ __forceinline__ void synth2(const float4 s_spec4[Mn][Cn / 2], const float* s_base,
                                       int s0, float* to0, float* to1) {
    float e0r, e0i;
    sincospif((float)s0 * (1.0f / 32768.0f), &e0i, &e0r);
    const float e1r = e0r * C1R - e0i * S1R;
    const float e1i = e0r * S1R + e0i * C1R;

#pragma unroll
    for (int o = 0; o < Cn; o++) { to0[o] = s_base[o]; to1[o] = s_base[o]; }

    float w0r = e0r, w0i = e0i, w1r = e1r, w1i = e1i;
#pragma unroll
    for (int k = 1; k < Mn; k++) {
#pragma unroll
        for (int j = 0; j < Cn / 2; j++) {
            const float4 cc = s_spec4[k][j];
            to0[2 * j]     = fmaf(cc.x, w0r, fmaf(cc.y, w0i, to0[2 * j]));
            to1[2 * j]     = fmaf(cc.x, w1r, fmaf(cc.y, w1i, to1[2 * j]));
            to0[2 * j + 1] = fmaf(cc.z, w0r, fmaf(cc.w, w0i, to0[2 * j + 1]));
            to1[2 * j + 1] = fmaf(cc.z, w1r, fmaf(cc.w, w1i, to1[2 * j + 1]));
        }
        if (k < Mn - 1) {
            float nr = w0r * e0r - w0i * e0i, ni = w0r * e0i + w0i * e0r;
            w0r = nr; w0i = ni;
            nr = w1r * e1r - w1i * e1i; ni = w1r * e1i + w1i * e1r;
            w1r = nr; w1i = ni;
        }
    }
}

// conv accumulation using transposed float4 weights
__device__ __forceinline__ void conv_acc(const float s_wwT[Cn][Cn],
                                         float h0, float h1, int c,
                                         float* to0, float* to1) {
    const float4* wrow = (const float4*)s_wwT[c];
#pragma unroll
    for (int j = 0; j < Cn / 4; j++) {
        const float4 w4 = wrow[j];
        to0[4 * j + 0] = fmaf(h0, w4.x, to0[4 * j + 0]);
        to1[4 * j + 0] = fmaf(h1, w4.x, to1[4 * j + 0]);
        to0[4 * j + 1] = fmaf(h0, w4.y, to0[4 * j + 1]);
        to1[4 * j + 1] = fmaf(h1, w4.y, to1[4 * j + 1]);
        to0[4 * j + 2] = fmaf(h0, w4.z, to0[4 * j + 2]);
        to1[4 * j + 2] = fmaf(h1, w4.z, to1[4 * j + 2]);
        to0[4 * j + 3] = fmaf(h0, w4.w, to0[4 * j + 3]);
        to1[4 * j + 3] = fmaf(h1, w4.w, to1[4 * j + 3]);
    }
}

// ---- inverse + 1x1 conv + gelu (layers 1..2), 2 samples/thread -------------
__global__ void __launch_bounds__(256) fno_kinv2(const float* __restrict__ ww,
                                                 const float* __restrict__ wb) {
    __shared__ float4 s_spec4[Mn][Cn / 2];
    __shared__ float  s_base[Cn];
    __shared__ float  s_wwT[Cn][Cn];
    const int b = blockIdx.y;
    const int tid = threadIdx.x;
    coef_to_smem4(b, wb, s_spec4, s_base, tid, 256);
    ww_to_smemT(ww, s_wwT, tid, 256);
    __syncthreads();

    const int s0 = blockIdx.x * 512 + 2 * tid;   // pair (s0, s0+1)
    float to0[Cn], to1[Cn];
    synth2(s_spec4, s_base, s0, to0, to1);

#pragma unroll
    for (int c = 0; c < Cn; c++) {
        const float2 hp = *(const float2*)(g_h + ((size_t)(b * Cn + c)) * Sn + s0);
        conv_acc(s_wwT, hp.x, hp.y, c, to0, to1);
    }
#pragma unroll
    for (int o = 0; o < Cn; o++) {
        float2 r = make_float2(gelu_fast(to0[o]), gelu_fast(to1[o]));
        *(float2*)(g_h + ((size_t)(b * Cn + o)) * Sn + s0) = r;
    }
}

// ---- layer-0 inverse: h computed on the fly from x/pd/fc0 -----------------
__global__ void __launch_bounds__(256) fno_kinv2_l0(const float* __restrict__ ww,
                                                    const float* __restrict__ wb,
                                                    const float* __restrict__ x,
                                                    const float* __restrict__ pd,
                                                    const float* __restrict__ fc0w,
                                                    const float* __restrict__ fc0b) {
    __shared__ float4 s_spec4[Mn][Cn / 2];
    __shared__ float  s_base[Cn];
    __shared__ float  s_wwT[Cn][Cn];
    __shared__ float  s_f0w[2 * Cn];
    __shared__ float  s_f0b[Cn];
    const int b = blockIdx.y;
    const int tid = threadIdx.x;
    coef_to_smem4(b, wb, s_spec4, s_base, tid, 256);
    ww_to_smemT(ww, s_wwT, tid, 256);
    if (tid < 2 * Cn) s_f0w[tid] = fc0w[tid];
    if (tid < Cn) s_f0b[tid] = fc0b[tid];
    __syncthreads();

    const int s0 = blockIdx.x * 512 + 2 * tid;
    float to0[Cn], to1[Cn];
    synth2(s_spec4, s_base, s0, to0, to1);

    const float invm = g_invmaxv;
    const float2 xp = *(const float2*)(x + (size_t)b * Sn + s0);
    const float2 pp = *(const float2*)(pd + s0);
    const float gr0 = pp.x * invm, gr1 = pp.y * invm;
#pragma unroll
    for (int c = 0; c < Cn; c++) {
        const float w0 = s_f0w[c], w1 = s_f0w[Cn + c], bc = s_f0b[c];
        const float h0 = fmaf(xp.x, w0, fmaf(gr0, w1, bc));
        const float h1 = fmaf(xp.y, w0, fmaf(gr1, w1, bc));
        conv_acc(s_wwT, h0, h1, c, to0, to1);
    }
#pragma unroll
    for (int o = 0; o < Cn; o++) {
        float2 r = make_float2(gelu_fast(to0[o]), gelu_fast(to1[o]));
        *(float2*)(g_h + ((size_t)(b * Cn + o)) * Sn + s0) = r;
    }
}

// ---- final: layer-3 inverse+conv (no gelu) -> fc1 -> gelu -> fc2, 2 samples
__global__ void __launch_bounds__(256) fno_kfinal2(const float* __restrict__ ww,
                                                   const float* __restrict__ wb,
                                                   const float* __restrict__ fc1w,
                                                   const float* __restrict__ fc1b,
                                                   const float* __restrict__ fc2w,
                                                   const float* __restrict__ fc2b,
                                                   float* __restrict__ out) {
    __shared__ float4 s_spec4[Mn][Cn / 2];
    __shared__ float  s_base[Cn];
    __shared__ float  s_wwT[Cn][Cn];
    __shared__ float4 s_fc1[Cn][Hn / 4];
    __shared__ float4 s_fc1b[Hn / 4];
    __shared__ float4 s_fc2[Hn / 4];
    const int b = blockIdx.y;
    const int tid = threadIdx.x;
    coef_to_smem4(b, wb, s_spec4, s_base, tid, 256);
    ww_to_smemT(ww, s_wwT, tid, 256);
    for (int i = tid; i < Cn * (Hn / 4); i += 256) {
        const int c = i / (Hn / 4), h4 = i % (Hn / 4);
        s_fc1[c][h4] = make_float4(fc1w[c * Hn + 4 * h4 + 0], fc1w[c * Hn + 4 * h4 + 1],
                                   fc1w[c * Hn + 4 * h4 + 2], fc1w[c * Hn + 4 * h4 + 3]);
    }
    if (tid < Hn / 4) {
        s_fc1b[tid] = make_float4(fc1b[4 * tid], fc1b[4 * tid + 1], fc1b[4 * tid + 2], fc1b[4 * tid + 3]);
        s_fc2[tid]  = make_float4(fc2w[4 * tid], fc2w[4 * tid + 1], fc2w[4 * tid + 2], fc2w[4 * tid + 3]);
    }
    __syncthreads();

    const int s0 = blockIdx.x * 512 + 2 * tid;
    float to0[Cn], to1[Cn];
    synth2(s_spec4, s_base, s0, to0, to1);

#pragma unroll
    for (int c = 0; c < Cn; c++) {
        const float2 hp = *(const float2*)(g_h + ((size_t)(b * Cn + c)) * Sn + s0);
        conv_acc(s_wwT, hp.x, hp.y, c, to0, to1);
    }
    // layer 3: NO gelu. fc1 -> gelu -> fc2 for both samples.
    const float f2b = fc2b[0];
    float res0 = f2b, res1 = f2b;
#pragma unroll 4
    for (int h4 = 0; h4 < Hn / 4; h4++) {
        const float4 bb = s_fc1b[h4];
        float a0x = bb.x, a0y = bb.y, a0z = bb.z, a0w = bb.w;
        float a1x = bb.x, a1y = bb.y, a1z = bb.z, a1w = bb.w;
#pragma unroll
        for (int c = 0; c < Cn; c++) {
            const float4 w4 = s_fc1[c][h4];
            a0x = fmaf(to0[c], w4.x, a0x);
            a0y = fmaf(to0[c], w4.y, a0y);
            a0z = fmaf(to0[c], w4.z, a0z);
            a0w = fmaf(to0[c], w4.w, a0w);
            a1x = fmaf(to1[c], w4.x, a1x);
            a1y = fmaf(to1[c], w4.y, a1y);
            a1z = fmaf(to1[c], w4.z, a1z);
            a1w = fmaf(to1[c], w4.w, a1w);
        }
        const float4 f2 = s_fc2[h4];
        res0 += gelu_fast(a0x) * f2.x + gelu_fast(a0y) * f2.y
              + gelu_fast(a0z) * f2.z + gelu_fast(a0w) * f2.w;
        res1 += gelu_fast(a1x) * f2.x + gelu_fast(a1y) * f2.y
              + gelu_fast(a1z) * f2.z + gelu_fast(a1w) * f2.w;
    }
    *(float2*)(out + (size_t)b * Sn + s0) = make_float2(res0, res1);
}

// ------------------------------------------------------------------ launch
extern "C" void kernel_launch(void* const* d_in, const int* in_sizes, int n_in,
                              void* d_out, int out_size) {
    const float* x  = (const float*)d_in[0];
    const float* pd = (const float*)d_in[1];
    const float* fc0w = (const float*)d_in[2];
    const float* fc0b = (const float*)d_in[3];
    const float *fc1w, *fc1b, *fc2w, *fc2b;
    const float *sre[4], *sim[4], *lww[4], *lwb[4];

    if (in_sizes[4] == Cn * Hn) {
        fc1w = (const float*)d_in[4]; fc1b = (const float*)d_in[5];
        fc2w = (const float*)d_in[6]; fc2b = (const float*)d_in[7];
        for (int l = 0; l < 4; l++) {
            sre[l] = (const float*)d_in[8 + 4 * l];
            sim[l] = (const float*)d_in[9 + 4 * l];
            lww[l] = (const float*)d_in[10 + 4 * l];
            lwb[l] = (const float*)d_in[11 + 4 * l];
        }
    } else {
        for (int l = 0; l < 4; l++) {
            sre[l] = (const float*)d_in[4 + 4 * l];
            sim[l] = (const float*)d_in[5 + 4 * l];
            lww[l] = (const float*)d_in[6 + 4 * l];
            lwb[l] = (const float*)d_in[7 + 4 * l];
        }
        fc1w = (const float*)d_in[20]; fc1b = (const float*)d_in[21];
        fc2w = (const float*)d_in[22]; fc2b = (const float*)d_in[23];
    }

    float* out = (float*)d_out;
    const dim3 gInv(Sn / 512, Bn);
    const dim3 gMix(Bn, Cn);

    fno_kmax<<<1, 1024>>>(pd);

    // layer 0: forward DFT + inverse both compute fc0's h on the fly
    fno_kfwd0<<<dim3(2, Cn, Bn), 256>>>(x, pd, fc0w, fc0b);
    fno_kmix<<<gMix, 32>>>(sre[0], sim[0]);
    fno_kinv2_l0<<<gInv, 256>>>(lww[0], lwb[0], x, pd, fc0w, fc0b);

    for (int l = 1; l < 3; l++) {
        fno_kfwd<<<dim3(2, Cn, Bn), 256>>>();
        fno_kmix<<<gMix, 32>>>(sre[l], sim[l]);
        fno_kinv2<<<gInv, 256>>>(lww[l], lwb[l]);
    }
    fno_kfwd<<<dim3(2, Cn, Bn), 256>>>();
    fno_kmix<<<gMix, 32>>>(sre[3], sim[3]);
    fno_kfinal2<<<gInv, 256>>>(lww[3], lwb[3], fc1w, fc1b, fc2w, fc2b, out);
}

// round 11
// speedup vs baseline: 1.3586x; 1.0782x over previous
#include <cuda_runtime.h>
#include <math.h>

#define Bn 32
#define Cn 20
#define Sn 65536
#define Mn 16
#define Qn 4096
#define Hn 128

// Scratch (device globals; allocation-free rule)
__device__ float  g_h[(size_t)Bn * Cn * Sn];          // (B, C, S) ~168MB
__device__ float  g_partR[Bn][Cn][2][Mn];
__device__ float  g_partI[Bn][Cn][2][Mn];
__device__ float2 g_coef[Bn][Cn][Mn];
__device__ float  g_maxv;
__device__ float  g_invmaxv;

// Fast gelu: A&S 7.1.28 erf approximation, |eps| <= 3e-7, branch-free.
__device__ __forceinline__ float fast_rcp(float x) {
    float r; asm("rcp.approx.f32 %0, %1;" : "=f"(r) : "f"(x)); return r;
}
__device__ __forceinline__ float gelu_fast(float x) {
    const float u = fabsf(x) * 0.7071067811865476f;
    float p = fmaf(0.0000430638f, u, 0.0002765672f);
    p = fmaf(p, u, 0.0001520143f);
    p = fmaf(p, u, 0.0092705272f);
    p = fmaf(p, u, 0.0422820123f);
    p = fmaf(p, u, 0.0705230784f);
    p = fmaf(p, u, 1.0f);
    float r = fast_rcp(p);
    r = r * r; r = r * r; r = r * r; r = r * r;   // ^16
    const float erf_v = copysignf(1.0f - r, x);
    return 0.5f * x * (1.0f + erf_v);
}

__device__ __forceinline__ float to_tf32(float x) {
    float r; asm("cvt.rna.tf32.f32 %0, %1;" : "=f"(r) : "f"(x)); return r;
}

// rotation between sample s and s+1: e^{+2pi i/65536}
#define C1R 0.9999999954025773f
#define S1R 9.587379909597734e-5f

// ------------------------------------------------------------------ max
__global__ void fno_kmax(const float* __restrict__ p) {
    __shared__ float sm[1024];
    float m = -1e30f;
    for (int i = threadIdx.x; i < Sn; i += 1024) m = fmaxf(m, p[i]);
    sm[threadIdx.x] = m;
    __syncthreads();
    for (int off = 512; off; off >>= 1) {
        if (threadIdx.x < off) sm[threadIdx.x] = fmaxf(sm[threadIdx.x], sm[threadIdx.x + off]);
        __syncthreads();
    }
    if (threadIdx.x == 0) { g_maxv = sm[0]; g_invmaxv = 1.0f / sm[0]; }
}

// ================= forward truncated DFT (16 modes) ========================
__device__ __forceinline__ void dft16_accum(const float hp[16], float zr, float zi,
                                            float* Fr, float* Fi) {
    const float C16[16] = { 1.f,  0.9238795325112867f,  0.7071067811865476f,  0.3826834323650898f,
                            0.f, -0.3826834323650898f, -0.7071067811865476f, -0.9238795325112867f,
                           -1.f, -0.9238795325112867f, -0.7071067811865476f, -0.3826834323650898f,
                            0.f,  0.3826834323650898f,  0.7071067811865476f,  0.9238795325112867f };
    const float S16[16] = { 0.f,  0.3826834323650898f,  0.7071067811865476f,  0.9238795325112867f,
                            1.f,  0.9238795325112867f,  0.7071067811865476f,  0.3826834323650898f,
                            0.f, -0.3826834323650898f, -0.7071067811865476f, -0.9238795325112867f,
                           -1.f, -0.9238795325112867f, -0.7071067811865476f, -0.3826834323650898f };
    float u[8], dd[8];
#pragma unroll
    for (int p = 0; p < 8; p++) { u[p] = hp[p] + hp[p + 8]; dd[p] = hp[p] - hp[p + 8]; }
    float BR[16], BI[16];
#pragma unroll
    for (int j = 0; j <= 4; j++) {
        float ar = 0.f, ai = 0.f;
#pragma unroll
        for (int p = 0; p < 8; p++) {
            const int m = (2 * j * p) & 15;
            ar += u[p] * C16[m];
            ai -= u[p] * S16[m];
        }
        BR[2 * j] = ar; BI[2 * j] = ai;
    }
#pragma unroll
    for (int k = 1; k < 8; k += 2) {
        float ar = 0.f, ai = 0.f;
#pragma unroll
        for (int p = 0; p < 8; p++) {
            const int m = (k * p) & 15;
            ar += dd[p] * C16[m];
            ai -= dd[p] * S16[m];
        }
        BR[k] = ar; BI[k] = ai;
    }
#pragma unroll
    for (int k = 9; k < 16; k++) { BR[k] = BR[16 - k]; BI[k] = -BI[16 - k]; }

    Fr[0] += BR[0];
    Fi[0] += BI[0];
    float wr = zr, wi = zi;
#pragma unroll
    for (int k = 1; k < 16; k++) {
        Fr[k] += BR[k] * wr - BI[k] * wi;
        Fi[k] += BR[k] * wi + BI[k] * wr;
        const float nwr = wr * zr - wi * zi;
        const float nwi = wr * zi + wi * zr;
        wr = nwr; wi = nwi;
    }
}

__device__ __forceinline__ void dft16_reduce_store(float* Fr, float* Fi,
                                                   int b, int c, int qc, int tid) {
#pragma unroll
    for (int off = 16; off; off >>= 1) {
#pragma unroll
        for (int k = 0; k < Mn; k++) {
            Fr[k] += __shfl_down_sync(0xffffffffu, Fr[k], off);
            Fi[k] += __shfl_down_sync(0xffffffffu, Fi[k], off);
        }
    }
    __shared__ float redR[8][Mn], redI[8][Mn];
    const int warp = tid >> 5, lane = tid & 31;
    if (lane == 0) {
#pragma unroll
        for (int k = 0; k < Mn; k++) { redR[warp][k] = Fr[k]; redI[warp][k] = Fi[k]; }
    }
    __syncthreads();
    if (tid < Mn) {
        float ar = 0.f, ai = 0.f;
#pragma unroll
        for (int w = 0; w < 8; w++) { ar += redR[w][tid]; ai += redI[w][tid]; }
        g_partR[b][c][qc][tid] = ar;
        g_partI[b][c][qc][tid] = ai;
    }
}

// generic forward DFT: reads g_h (2x unrolled for MLP)
__global__ void __launch_bounds__(256) fno_kfwd() {
    const int qc = blockIdx.x, c = blockIdx.y, b = blockIdx.z;
    const float* __restrict__ row = g_h + ((size_t)(b * Cn + c)) * Sn;
    const int tid = threadIdx.x;
    const int q0 = qc * 2048 + tid;

    float Fr[Mn], Fi[Mn];
#pragma unroll
    for (int k = 0; k < Mn; k++) { Fr[k] = 0.f; Fi[k] = 0.f; }
    float zr, zi;
    sincospif(-(float)q0 * (1.0f / 32768.0f), &zi, &zr);
    const float Rr =  0.9996988186962042f;
    const float Ri = -0.0245412285229123f;

    for (int it = 0; it < 8; it += 2) {
        const int qa = q0 + it * 256;
        const int qb = qa + 256;
        float hpa[16], hpb[16];
#pragma unroll
        for (int p = 0; p < 16; p++) hpa[p] = row[qa + p * Qn];
#pragma unroll
        for (int p = 0; p < 16; p++) hpb[p] = row[qb + p * Qn];
        dft16_accum(hpa, zr, zi, Fr, Fi);
        {
            const float nzr = zr * Rr - zi * Ri;
            const float nzi = zr * Ri + zi * Rr;
            zr = nzr; zi = nzi;
        }
        dft16_accum(hpb, zr, zi, Fr, Fi);
        {
            const float nzr = zr * Rr - zi * Ri;
            const float nzi = zr * Ri + zi * Rr;
            zr = nzr; zi = nzi;
        }
    }
    dft16_reduce_store(Fr, Fi, b, c, qc, tid);
}

// layer-0 forward DFT: computes h on the fly from x, point_data, fc0 (2x unrolled)
__global__ void __launch_bounds__(256) fno_kfwd0(const float* __restrict__ x,
                                                 const float* __restrict__ pd,
                                                 const float* __restrict__ fc0w,
                                                 const float* __restrict__ fc0b) {
    const int qc = blockIdx.x, c = blockIdx.y, b = blockIdx.z;
    const int tid = threadIdx.x;
    const int q0 = qc * 2048 + tid;
    const float w0 = fc0w[c], w1 = fc0w[Cn + c], bc = fc0b[c];
    const float invm = g_invmaxv;
    const float* __restrict__ xrow = x + (size_t)b * Sn;

    float Fr[Mn], Fi[Mn];
#pragma unroll
    for (int k = 0; k < Mn; k++) { Fr[k] = 0.f; Fi[k] = 0.f; }
    float zr, zi;
    sincospif(-(float)q0 * (1.0f / 32768.0f), &zi, &zr);
    const float Rr =  0.9996988186962042f;
    const float Ri = -0.0245412285229123f;

    for (int it = 0; it < 8; it += 2) {
        const int qa = q0 + it * 256;
        const int qb = qa + 256;
        float xa[16], pa[16], xb[16], pb[16];
#pragma unroll
        for (int p = 0; p < 16; p++) { xa[p] = xrow[qa + p * Qn]; pa[p] = pd[qa + p * Qn]; }
#pragma unroll
        for (int p = 0; p < 16; p++) { xb[p] = xrow[qb + p * Qn]; pb[p] = pd[qb + p * Qn]; }
        float hpa[16], hpb[16];
#pragma unroll
        for (int p = 0; p < 16; p++) hpa[p] = fmaf(xa[p], w0, fmaf(pa[p] * invm, w1, bc));
#pragma unroll
        for (int p = 0; p < 16; p++) hpb[p] = fmaf(xb[p], w0, fmaf(pb[p] * invm, w1, bc));
        dft16_accum(hpa, zr, zi, Fr, Fi);
        {
            const float nzr = zr * Rr - zi * Ri;
            const float nzi = zr * Ri + zi * Rr;
            zr = nzr; zi = nzi;
        }
        dft16_accum(hpb, zr, zi, Fr, Fi);
        {
            const float nzr = zr * Rr - zi * Ri;
            const float nzi = zr * Ri + zi * Rr;
            zr = nzr; zi = nzi;
        }
    }
    dft16_reduce_store(Fr, Fi, b, c, qc, tid);
}

// ------------------------------------------------------------------ mode mixing
__global__ void fno_kmix(const float* __restrict__ sre, const float* __restrict__ sim) {
    const int b = blockIdx.x, o = blockIdx.y;
    const int tid = threadIdx.x;
    const int k = tid & 15, ih = tid >> 4;
    float Gr = 0.f, Gi = 0.f;
#pragma unroll
    for (int j = 0; j < Cn / 2; j++) {
        const int i = ih * (Cn / 2) + j;
        const float fr = g_partR[b][i][0][k] + g_partR[b][i][1][k];
        const float fi = g_partI[b][i][0][k] + g_partI[b][i][1][k];
        const float wr = sre[i * (Cn * Mn) + o * Mn + k];
        const float wi = sim[i * (Cn * Mn) + o * Mn + k];
        Gr += fr * wr - fi * wi;
        Gi += fr * wi + fi * wr;
    }
    Gr += __shfl_down_sync(0xffffffffu, Gr, 16);
    Gi += __shfl_down_sync(0xffffffffu, Gi, 16);
    if (tid < 16) {
        const float invS = 1.0f / (float)Sn;
        float2 cf;
        if (k == 0) { cf.x = Gr * invS; cf.y = 0.f; }
        else        { cf.x = 2.f * Gr * invS; cf.y = 2.f * Gi * invS; }
        g_coef[b][o][k] = cf;
    }
}

// ===== shared staging: spectral coefs packed float4 (o-pairs), conv wT =====
__device__ __forceinline__ void coef_to_smem4(int b, const float* __restrict__ wb,
                                              float4 s_spec4[Mn][Cn / 2], float* s_base,
                                              int tid, int nthr) {
    float* specf = (float*)s_spec4;
    for (int i = tid; i < Cn * Mn; i += nthr) {
        const int o = i >> 4, k = i & 15;
        const float2 cf = g_coef[b][o][k];
        if (k == 0) s_base[o] = cf.x + wb[o];
        else {
            const int idx = k * (Cn * 2) + (o >> 1) * 4 + (o & 1) * 2;
            specf[idx]     = cf.x;
            specf[idx + 1] = -cf.y;
        }
    }
}

__device__ __forceinline__ void ww_to_smemT(const float* __restrict__ ww,
                                            float s_wwT[Cn][Cn], int tid, int nthr) {
    for (int i = tid; i < Cn * Cn; i += nthr) {
        const int o = i / Cn, c = i % Cn;
        s_wwT[c][o] = ww[i];
    }
}

// ========= spectral synthesis for a pair of samples (s0, s0+1) =============
__device__ __forceinline__ void synth2(const float4 s_spec4[Mn][Cn / 2], const float* s_base,
                                       int s0, float* to0, float* to1) {
    float e0r, e0i;
    sincospif((float)s0 * (1.0f / 32768.0f), &e0i, &e0r);
    const float e1r = e0r * C1R - e0i * S1R;
    const float e1i = e0r * S1R + e0i * C1R;

#pragma unroll
    for (int o = 0; o < Cn; o++) { to0[o] = s_base[o]; to1[o] = s_base[o]; }

    float w0r = e0r, w0i = e0i, w1r = e1r, w1i = e1i;
#pragma unroll
    for (int k = 1; k < Mn; k++) {
#pragma unroll
        for (int j = 0; j < Cn / 2; j++) {
            const float4 cc = s_spec4[k][j];
            to0[2 * j]     = fmaf(cc.x, w0r, fmaf(cc.y, w0i, to0[2 * j]));
            to1[2 * j]     = fmaf(cc.x, w1r, fmaf(cc.y, w1i, to1[2 * j]));
            to0[2 * j + 1] = fmaf(cc.z, w0r, fmaf(cc.w, w0i, to0[2 * j + 1]));
            to1[2 * j + 1] = fmaf(cc.z, w1r, fmaf(cc.w, w1i, to1[2 * j + 1]));
        }
        if (k < Mn - 1) {
            float nr = w0r * e0r - w0i * e0i, ni = w0r * e0i + w0i * e0r;
            w0r = nr; w0i = ni;
            nr = w1r * e1r - w1i * e1i; ni = w1r * e1i + w1i * e1r;
            w1r = nr; w1i = ni;
        }
    }
}

// conv accumulation using transposed float4 weights
__device__ __forceinline__ void conv_acc(const float s_wwT[Cn][Cn],
                                         float h0, float h1, int c,
                                         float* to0, float* to1) {
    const float4* wrow = (const float4*)s_wwT[c];
#pragma unroll
    for (int j = 0; j < Cn / 4; j++) {
        const float4 w4 = wrow[j];
        to0[4 * j + 0] = fmaf(h0, w4.x, to0[4 * j + 0]);
        to1[4 * j + 0] = fmaf(h1, w4.x, to1[4 * j + 0]);
        to0[4 * j + 1] = fmaf(h0, w4.y, to0[4 * j + 1]);
        to1[4 * j + 1] = fmaf(h1, w4.y, to1[4 * j + 1]);
        to0[4 * j + 2] = fmaf(h0, w4.z, to0[4 * j + 2]);
        to1[4 * j + 2] = fmaf(h1, w4.z, to1[4 * j + 2]);
        to0[4 * j + 3] = fmaf(h0, w4.w, to0[4 * j + 3]);
        to1[4 * j + 3] = fmaf(h1, w4.w, to1[4 * j + 3]);
    }
}

// ---- inverse + 1x1 conv + gelu (layers 1..2), 2 samples/thread -------------
__global__ void __launch_bounds__(256) fno_kinv2(const float* __restrict__ ww,
                                                 const float* __restrict__ wb) {
    __shared__ float4 s_spec4[Mn][Cn / 2];
    __shared__ float  s_base[Cn];
    __shared__ float  s_wwT[Cn][Cn];
    const int b = blockIdx.y;
    const int tid = threadIdx.x;
    coef_to_smem4(b, wb, s_spec4, s_base, tid, 256);
    ww_to_smemT(ww, s_wwT, tid, 256);
    __syncthreads();

    const int s0 = blockIdx.x * 512 + 2 * tid;   // pair (s0, s0+1)
    float to0[Cn], to1[Cn];
    synth2(s_spec4, s_base, s0, to0, to1);

#pragma unroll
    for (int c = 0; c < Cn; c++) {
        const float2 hp = *(const float2*)(g_h + ((size_t)(b * Cn + c)) * Sn + s0);
        conv_acc(s_wwT, hp.x, hp.y, c, to0, to1);
    }
#pragma unroll
    for (int o = 0; o < Cn; o++) {
        float2 r = make_float2(gelu_fast(to0[o]), gelu_fast(to1[o]));
        *(float2*)(g_h + ((size_t)(b * Cn + o)) * Sn + s0) = r;
    }
}

// ---- layer-0 inverse: h computed on the fly from x/pd/fc0 -----------------
__global__ void __launch_bounds__(256) fno_kinv2_l0(const float* __restrict__ ww,
                                                    const float* __restrict__ wb,
                                                    const float* __restrict__ x,
                                                    const float* __restrict__ pd,
                                                    const float* __restrict__ fc0w,
                                                    const float* __restrict__ fc0b) {
    __shared__ float4 s_spec4[Mn][Cn / 2];
    __shared__ float  s_base[Cn];
    __shared__ float  s_wwT[Cn][Cn];
    __shared__ float  s_f0w[2 * Cn];
    __shared__ float  s_f0b[Cn];
    const int b = blockIdx.y;
    const int tid = threadIdx.x;
    coef_to_smem4(b, wb, s_spec4, s_base, tid, 256);
    ww_to_smemT(ww, s_wwT, tid, 256);
    if (tid < 2 * Cn) s_f0w[tid] = fc0w[tid];
    if (tid < Cn) s_f0b[tid] = fc0b[tid];
    __syncthreads();

    const int s0 = blockIdx.x * 512 + 2 * tid;
    float to0[Cn], to1[Cn];
    synth2(s_spec4, s_base, s0, to0, to1);

    const float invm = g_invmaxv;
    const float2 xp = *(const float2*)(x + (size_t)b * Sn + s0);
    const float2 pp = *(const float2*)(pd + s0);
    const float gr0 = pp.x * invm, gr1 = pp.y * invm;
#pragma unroll
    for (int c = 0; c < Cn; c++) {
        const float w0 = s_f0w[c], w1 = s_f0w[Cn + c], bc = s_f0b[c];
        const float h0 = fmaf(xp.x, w0, fmaf(gr0, w1, bc));
        const float h1 = fmaf(xp.y, w0, fmaf(gr1, w1, bc));
        conv_acc(s_wwT, h0, h1, c, to0, to1);
    }
#pragma unroll
    for (int o = 0; o < Cn; o++) {
        float2 r = make_float2(gelu_fast(to0[o]), gelu_fast(to1[o]));
        *(float2*)(g_h + ((size_t)(b * Cn + o)) * Sn + s0) = r;
    }
}

// ---- final: layer-3 inverse+conv (no gelu) -> fc1 (tf32 MMA) -> gelu -> fc2
__global__ void __launch_bounds__(256) fno_kfinal2(const float* __restrict__ ww,
                                                   const float* __restrict__ wb,
                                                   const float* __restrict__ fc1w,
                                                   const float* __restrict__ fc1b,
                                                   const float* __restrict__ fc2w,
                                                   const float* __restrict__ fc2b,
                                                   float* __restrict__ out) {
    __shared__ float4 s_spec4[Mn][Cn / 2];
    __shared__ float  s_base[Cn];
    __shared__ float  s_wwT[Cn][Cn];
    __shared__ float  s_toT[Cn][520];      // transposed to-values (tf32), pad 520 (bank-clean A frags)
    __shared__ float  s_fc1w[Cn][136];     // fc1 weights k-major (tf32), pad 136 (bank-clean B frags)
    __shared__ float  s_fc1b[Hn];
    __shared__ float  s_fc2[Hn];
    const int b = blockIdx.y;
    const int tid = threadIdx.x;
    coef_to_smem4(b, wb, s_spec4, s_base, tid, 256);
    ww_to_smemT(ww, s_wwT, tid, 256);
    for (int i = tid; i < Cn * Hn; i += 256) {
        const int c = i / Hn, n = i % Hn;
        s_fc1w[c][n] = to_tf32(fc1w[i]);
    }
    if (tid < Hn) { s_fc1b[tid] = fc1b[tid]; s_fc2[tid] = fc2w[tid]; }
    __syncthreads();

    const int s0 = blockIdx.x * 512 + 2 * tid;
    float to0[Cn], to1[Cn];
    synth2(s_spec4, s_base, s0, to0, to1);

#pragma unroll
    for (int c = 0; c < Cn; c++) {
        const float2 hp = *(const float2*)(g_h + ((size_t)(b * Cn + c)) * Sn + s0);
        conv_acc(s_wwT, hp.x, hp.y, c, to0, to1);
    }
    // layer 3 output (NO gelu) -> stage to smem transposed, tf32-rounded.
    const int ls = 2 * tid;   // block-local sample
#pragma unroll
    for (int c = 0; c < Cn; c++) {
        *(float2*)(&s_toT[c][ls]) = make_float2(to_tf32(to0[c]), to_tf32(to1[c]));
    }
    __syncwarp();   // warp w's threads wrote exactly warp w's 64 samples

    // fc1 via mma.sync m16n8k4 tf32: warp owns 64 samples = 4 M-tiles of 16.
    const int w = tid >> 5, lane = tid & 31;
    const int gq = lane >> 2;   // groupID 0..7
    const int qi = lane & 3;    // quad index 0..3
    const int sbase = w * 64;

    // preload all A fragments: [mtile][kstep][2]
    float afr[4][5][2];
#pragma unroll
    for (int mt = 0; mt < 4; mt++)
#pragma unroll
        for (int ks = 0; ks < 5; ks++) {
            afr[mt][ks][0] = s_toT[ks * 4 + qi][sbase + mt * 16 + gq];
            afr[mt][ks][1] = s_toT[ks * 4 + qi][sbase + mt * 16 + gq + 8];
        }

    float res[4][2];
#pragma unroll
    for (int mt = 0; mt < 4; mt++) { res[mt][0] = 0.f; res[mt][1] = 0.f; }

#pragma unroll 2
    for (int nt = 0; nt < 16; nt++) {
        float bfr[5];
#pragma unroll
        for (int ks = 0; ks < 5; ks++) bfr[ks] = s_fc1w[ks * 4 + qi][nt * 8 + gq];
        const int c0 = nt * 8 + 2 * qi;
        const float b0v = s_fc1b[c0], b1v = s_fc1b[c0 + 1];
        const float f20 = s_fc2[c0],  f21 = s_fc2[c0 + 1];
#pragma unroll
        for (int mt = 0; mt < 4; mt++) {
            float d0 = b0v, d1 = b1v, d2 = b0v, d3 = b1v;
#pragma unroll
            for (int ks = 0; ks < 5; ks++) {
                asm volatile(
                    "mma.sync.aligned.m16n8k4.row.col.f32.tf32.tf32.f32 "
                    "{%0,%1,%2,%3}, {%4,%5}, {%6}, {%0,%1,%2,%3};"
                    : "+f"(d0), "+f"(d1), "+f"(d2), "+f"(d3)
                    : "r"(__float_as_uint(afr[mt][ks][0])),
                      "r"(__float_as_uint(afr[mt][ks][1])),
                      "r"(__float_as_uint(bfr[ks])));
            }
            res[mt][0] += gelu_fast(d0) * f20 + gelu_fast(d1) * f21;
            res[mt][1] += gelu_fast(d2) * f20 + gelu_fast(d3) * f21;
        }
    }

    // quad reduction (lanes qi=0..3 hold disjoint column partials of same rows)
    const float f2b = fc2b[0];
    float* orow = out + (size_t)b * Sn + blockIdx.x * 512;
#pragma unroll
    for (int mt = 0; mt < 4; mt++) {
#pragma unroll
        for (int hh = 0; hh < 2; hh++) {
            float v = res[mt][hh];
            v += __shfl_xor_sync(0xffffffffu, v, 1);
            v += __shfl_xor_sync(0xffffffffu, v, 2);
            if (qi == 0) {
                orow[sbase + mt * 16 + gq + hh * 8] = v + f2b;
            }
        }
    }
}

// ------------------------------------------------------------------ launch
extern "C" void kernel_launch(void* const* d_in, const int* in_sizes, int n_in,
                              void* d_out, int out_size) {
    const float* x  = (const float*)d_in[0];
    const float* pd = (const float*)d_in[1];
    const float* fc0w = (const float*)d_in[2];
    const float* fc0b = (const float*)d_in[3];
    const float *fc1w, *fc1b, *fc2w, *fc2b;
    const float *sre[4], *sim[4], *lww[4], *lwb[4];

    if (in_sizes[4] == Cn * Hn) {
        fc1w = (const float*)d_in[4]; fc1b = (const float*)d_in[5];
        fc2w = (const float*)d_in[6]; fc2b = (const float*)d_in[7];
        for (int l = 0; l < 4; l++) {
            sre[l] = (const float*)d_in[8 + 4 * l];
            sim[l] = (const float*)d_in[9 + 4 * l];
            lww[l] = (const float*)d_in[10 + 4 * l];
            lwb[l] = (const float*)d_in[11 + 4 * l];
        }
    } else {
        for (int l = 0; l < 4; l++) {
            sre[l] = (const float*)d_in[4 + 4 * l];
            sim[l] = (const float*)d_in[5 + 4 * l];
            lww[l] = (const float*)d_in[6 + 4 * l];
            lwb[l] = (const float*)d_in[7 + 4 * l];
        }
        fc1w = (const float*)d_in[20]; fc1b = (const float*)d_in[21];
        fc2w = (const float*)d_in[22]; fc2b = (const float*)d_in[23];
    }

    float* out = (float*)d_out;
    const dim3 gInv(Sn / 512, Bn);
    const dim3 gMix(Bn, Cn);

    fno_kmax<<<1, 1024>>>(pd);

    // layer 0: forward DFT + inverse both compute fc0's h on the fly
    fno_kfwd0<<<dim3(2, Cn, Bn), 256>>>(x, pd, fc0w, fc0b);
    fno_kmix<<<gMix, 32>>>(sre[0], sim[0]);
    fno_kinv2_l0<<<gInv, 256>>>(lww[0], lwb[0], x, pd, fc0w, fc0b);

    for (int l = 1; l < 3; l++) {
        fno_kfwd<<<dim3(2, Cn, Bn), 256>>>();
        fno_kmix<<<gMix, 32>>>(sre[l], sim[l]);
        fno_kinv2<<<gInv, 256>>>(lww[l], lwb[l]);
    }
    fno_kfwd<<<dim3(2, Cn, Bn), 256>>>();
    fno_kmix<<<gMix, 32>>>(sre[3], sim[3]);
    fno_kfinal2<<<gInv, 256>>>(lww[3], lwb[3], fc1w, fc1b, fc2w, fc2b, out);
}

// round 12
// speedup vs baseline: 1.4492x; 1.0667x over previous
#include <cuda_runtime.h>
#include <math.h>

#define Bn 32
#define Cn 20
#define Sn 65536
#define Mn 16
#define Qn 4096
#define Hn 128

// Scratch (device globals; allocation-free rule)
__device__ float  g_h[(size_t)Bn * Cn * Sn];          // (B, C, S) ~168MB
__device__ float  g_partR[Bn][Cn][2][Mn];
__device__ float  g_partI[Bn][Cn][2][Mn];
__device__ float2 g_coef[Bn][Cn][Mn];
__device__ float  g_maxv;
__device__ float  g_invmaxv;

// Fast gelu: A&S 7.1.28 erf approximation, |eps| <= 3e-7, branch-free.
__device__ __forceinline__ float fast_rcp(float x) {
    float r; asm("rcp.approx.f32 %0, %1;" : "=f"(r) : "f"(x)); return r;
}
__device__ __forceinline__ float gelu_fast(float x) {
    const float u = fabsf(x) * 0.7071067811865476f;
    float p = fmaf(0.0000430638f, u, 0.0002765672f);
    p = fmaf(p, u, 0.0001520143f);
    p = fmaf(p, u, 0.0092705272f);
    p = fmaf(p, u, 0.0422820123f);
    p = fmaf(p, u, 0.0705230784f);
    p = fmaf(p, u, 1.0f);
    float r = fast_rcp(p);
    r = r * r; r = r * r; r = r * r; r = r * r;   // ^16
    const float erf_v = copysignf(1.0f - r, x);
    return 0.5f * x * (1.0f + erf_v);
}

// Cheaper gelu for the FINAL layer only: A&S 7.1.27, |eps_erf| <= 5e-4.
__device__ __forceinline__ float gelu_cheap(float x) {
    const float u = fabsf(x) * 0.7071067811865476f;
    float p = fmaf(0.078108f, u, 0.000972f);
    p = fmaf(p, u, 0.230389f);
    p = fmaf(p, u, 0.278393f);
    p = fmaf(p, u, 1.0f);
    float r = fast_rcp(p);
    r = r * r; r = r * r;                         // ^4
    const float erf_v = copysignf(1.0f - r, x);
    return 0.5f * x * (1.0f + erf_v);
}

__device__ __forceinline__ float to_tf32(float x) {
    float r; asm("cvt.rna.tf32.f32 %0, %1;" : "=f"(r) : "f"(x)); return r;
}

// rotation between sample s and s+1: e^{+2pi i/65536}
#define C1R 0.9999999954025773f
#define S1R 9.587379909597734e-5f

// ------------------------------------------------------------------ max
__global__ void fno_kmax(const float* __restrict__ p) {
    __shared__ float sm[1024];
    float m = -1e30f;
    for (int i = threadIdx.x; i < Sn; i += 1024) m = fmaxf(m, p[i]);
    sm[threadIdx.x] = m;
    __syncthreads();
    for (int off = 512; off; off >>= 1) {
        if (threadIdx.x < off) sm[threadIdx.x] = fmaxf(sm[threadIdx.x], sm[threadIdx.x + off]);
        __syncthreads();
    }
    if (threadIdx.x == 0) { g_maxv = sm[0]; g_invmaxv = 1.0f / sm[0]; }
}

// ================= forward truncated DFT (16 modes) ========================
__device__ __forceinline__ void dft16_accum(const float hp[16], float zr, float zi,
                                            float* Fr, float* Fi) {
    const float C16[16] = { 1.f,  0.9238795325112867f,  0.7071067811865476f,  0.3826834323650898f,
                            0.f, -0.3826834323650898f, -0.7071067811865476f, -0.9238795325112867f,
                           -1.f, -0.9238795325112867f, -0.7071067811865476f, -0.3826834323650898f,
                            0.f,  0.3826834323650898f,  0.7071067811865476f,  0.9238795325112867f };
    const float S16[16] = { 0.f,  0.3826834323650898f,  0.7071067811865476f,  0.9238795325112867f,
                            1.f,  0.9238795325112867f,  0.7071067811865476f,  0.3826834323650898f,
                            0.f, -0.3826834323650898f, -0.7071067811865476f, -0.9238795325112867f,
                           -1.f, -0.9238795325112867f, -0.7071067811865476f, -0.3826834323650898f };
    float u[8], dd[8];
#pragma unroll
    for (int p = 0; p < 8; p++) { u[p] = hp[p] + hp[p + 8]; dd[p] = hp[p] - hp[p + 8]; }
    float BR[16], BI[16];
#pragma unroll
    for (int j = 0; j <= 4; j++) {
        float ar = 0.f, ai = 0.f;
#pragma unroll
        for (int p = 0; p < 8; p++) {
            const int m = (2 * j * p) & 15;
            ar += u[p] * C16[m];
            ai -= u[p] * S16[m];
        }
        BR[2 * j] = ar; BI[2 * j] = ai;
    }
#pragma unroll
    for (int k = 1; k < 8; k += 2) {
        float ar = 0.f, ai = 0.f;
#pragma unroll
        for (int p = 0; p < 8; p++) {
            const int m = (k * p) & 15;
            ar += dd[p] * C16[m];
            ai -= dd[p] * S16[m];
        }
        BR[k] = ar; BI[k] = ai;
    }
#pragma unroll
    for (int k = 9; k < 16; k++) { BR[k] = BR[16 - k]; BI[k] = -BI[16 - k]; }

    Fr[0] += BR[0];
    Fi[0] += BI[0];
    float wr = zr, wi = zi;
#pragma unroll
    for (int k = 1; k < 16; k++) {
        Fr[k] += BR[k] * wr - BI[k] * wi;
        Fi[k] += BR[k] * wi + BI[k] * wr;
        const float nwr = wr * zr - wi * zi;
        const float nwi = wr * zi + wi * zr;
        wr = nwr; wi = nwi;
    }
}

__device__ __forceinline__ void dft16_reduce_store(float* Fr, float* Fi,
                                                   int b, int c, int qc, int tid) {
#pragma unroll
    for (int off = 16; off; off >>= 1) {
#pragma unroll
        for (int k = 0; k < Mn; k++) {
            Fr[k] += __shfl_down_sync(0xffffffffu, Fr[k], off);
            Fi[k] += __shfl_down_sync(0xffffffffu, Fi[k], off);
        }
    }
    __shared__ float redR[8][Mn], redI[8][Mn];
    const int warp = tid >> 5, lane = tid & 31;
    if (lane == 0) {
#pragma unroll
        for (int k = 0; k < Mn; k++) { redR[warp][k] = Fr[k]; redI[warp][k] = Fi[k]; }
    }
    __syncthreads();
    if (tid < Mn) {
        float ar = 0.f, ai = 0.f;
#pragma unroll
        for (int w = 0; w < 8; w++) { ar += redR[w][tid]; ai += redI[w][tid]; }
        g_partR[b][c][qc][tid] = ar;
        g_partI[b][c][qc][tid] = ai;
    }
}

// generic forward DFT: reads g_h (2x unrolled for MLP)
__global__ void __launch_bounds__(256) fno_kfwd() {
    const int qc = blockIdx.x, c = blockIdx.y, b = blockIdx.z;
    const float* __restrict__ row = g_h + ((size_t)(b * Cn + c)) * Sn;
    const int tid = threadIdx.x;
    const int q0 = qc * 2048 + tid;

    float Fr[Mn], Fi[Mn];
#pragma unroll
    for (int k = 0; k < Mn; k++) { Fr[k] = 0.f; Fi[k] = 0.f; }
    float zr, zi;
    sincospif(-(float)q0 * (1.0f / 32768.0f), &zi, &zr);
    const float Rr =  0.9996988186962042f;
    const float Ri = -0.0245412285229123f;

    for (int it = 0; it < 8; it += 2) {
        const int qa = q0 + it * 256;
        const int qb = qa + 256;
        float hpa[16], hpb[16];
#pragma unroll
        for (int p = 0; p < 16; p++) hpa[p] = row[qa + p * Qn];
#pragma unroll
        for (int p = 0; p < 16; p++) hpb[p] = row[qb + p * Qn];
        dft16_accum(hpa, zr, zi, Fr, Fi);
        {
            const float nzr = zr * Rr - zi * Ri;
            const float nzi = zr * Ri + zi * Rr;
            zr = nzr; zi = nzi;
        }
        dft16_accum(hpb, zr, zi, Fr, Fi);
        {
            const float nzr = zr * Rr - zi * Ri;
            const float nzi = zr * Ri + zi * Rr;
            zr = nzr; zi = nzi;
        }
    }
    dft16_reduce_store(Fr, Fi, b, c, qc, tid);
}

// layer-0 forward DFT: computes h on the fly from x, point_data, fc0 (2x unrolled)
__global__ void __launch_bounds__(256) fno_kfwd0(const float* __restrict__ x,
                                                 const float* __restrict__ pd,
                                                 const float* __restrict__ fc0w,
                                                 const float* __restrict__ fc0b) {
    const int qc = blockIdx.x, c = blockIdx.y, b = blockIdx.z;
    const int tid = threadIdx.x;
    const int q0 = qc * 2048 + tid;
    const float w0 = fc0w[c], w1 = fc0w[Cn + c], bc = fc0b[c];
    const float invm = g_invmaxv;
    const float* __restrict__ xrow = x + (size_t)b * Sn;

    float Fr[Mn], Fi[Mn];
#pragma unroll
    for (int k = 0; k < Mn; k++) { Fr[k] = 0.f; Fi[k] = 0.f; }
    float zr, zi;
    sincospif(-(float)q0 * (1.0f / 32768.0f), &zi, &zr);
    const float Rr =  0.9996988186962042f;
    const float Ri = -0.0245412285229123f;

    for (int it = 0; it < 8; it += 2) {
        const int qa = q0 + it * 256;
        const int qb = qa + 256;
        float xa[16], pa[16], xb[16], pb[16];
#pragma unroll
        for (int p = 0; p < 16; p++) { xa[p] = xrow[qa + p * Qn]; pa[p] = pd[qa + p * Qn]; }
#pragma unroll
        for (int p = 0; p < 16; p++) { xb[p] = xrow[qb + p * Qn]; pb[p] = pd[qb + p * Qn]; }
        float hpa[16], hpb[16];
#pragma unroll
        for (int p = 0; p < 16; p++) hpa[p] = fmaf(xa[p], w0, fmaf(pa[p] * invm, w1, bc));
#pragma unroll
        for (int p = 0; p < 16; p++) hpb[p] = fmaf(xb[p], w0, fmaf(pb[p] * invm, w1, bc));
        dft16_accum(hpa, zr, zi, Fr, Fi);
        {
            const float nzr = zr * Rr - zi * Ri;
            const float nzi = zr * Ri + zi * Rr;
            zr = nzr; zi = nzi;
        }
        dft16_accum(hpb, zr, zi, Fr, Fi);
        {
            const float nzr = zr * Rr - zi * Ri;
            const float nzi = zr * Ri + zi * Rr;
            zr = nzr; zi = nzi;
        }
    }
    dft16_reduce_store(Fr, Fi, b, c, qc, tid);
}

// ------------------------------------------------------------------ mode mixing
__global__ void fno_kmix(const float* __restrict__ sre, const float* __restrict__ sim) {
    const int b = blockIdx.x, o = blockIdx.y;
    const int tid = threadIdx.x;
    const int k = tid & 15, ih = tid >> 4;
    float Gr = 0.f, Gi = 0.f;
#pragma unroll
    for (int j = 0; j < Cn / 2; j++) {
        const int i = ih * (Cn / 2) + j;
        const float fr = g_partR[b][i][0][k] + g_partR[b][i][1][k];
        const float fi = g_partI[b][i][0][k] + g_partI[b][i][1][k];
        const float wr = sre[i * (Cn * Mn) + o * Mn + k];
        const float wi = sim[i * (Cn * Mn) + o * Mn + k];
        Gr += fr * wr - fi * wi;
        Gi += fr * wi + fi * wr;
    }
    Gr += __shfl_down_sync(0xffffffffu, Gr, 16);
    Gi += __shfl_down_sync(0xffffffffu, Gi, 16);
    if (tid < 16) {
        const float invS = 1.0f / (float)Sn;
        float2 cf;
        if (k == 0) { cf.x = Gr * invS; cf.y = 0.f; }
        else        { cf.x = 2.f * Gr * invS; cf.y = 2.f * Gi * invS; }
        g_coef[b][o][k] = cf;
    }
}

// ===== shared staging: spectral coefs packed float4 (o-pairs), conv wT =====
__device__ __forceinline__ void coef_to_smem4(int b, const float* __restrict__ wb,
                                              float4 s_spec4[Mn][Cn / 2], float* s_base,
                                              int tid, int nthr) {
    float* specf = (float*)s_spec4;
    for (int i = tid; i < Cn * Mn; i += nthr) {
        const int o = i >> 4, k = i & 15;
        const float2 cf = g_coef[b][o][k];
        if (k == 0) s_base[o] = cf.x + wb[o];
        else {
            const int idx = k * (Cn * 2) + (o >> 1) * 4 + (o & 1) * 2;
            specf[idx]     = cf.x;
            specf[idx + 1] = -cf.y;
        }
    }
}

__device__ __forceinline__ void ww_to_smemT(const float* __restrict__ ww,
                                            float s_wwT[Cn][Cn], int tid, int nthr) {
    for (int i = tid; i < Cn * Cn; i += nthr) {
        const int o = i / Cn, c = i % Cn;
        s_wwT[c][o] = ww[i];
    }
}

// ========= spectral synthesis for a pair of samples (s0, s0+1) =============
__device__ __forceinline__ void synth2(const float4 s_spec4[Mn][Cn / 2], const float* s_base,
                                       int s0, float* to0, float* to1) {
    float e0r, e0i;
    sincospif((float)s0 * (1.0f / 32768.0f), &e0i, &e0r);
    const float e1r = e0r * C1R - e0i * S1R;
    const float e1i = e0r * S1R + e0i * C1R;

#pragma unroll
    for (int o = 0; o < Cn; o++) { to0[o] = s_base[o]; to1[o] = s_base[o]; }

    float w0r = e0r, w0i = e0i, w1r = e1r, w1i = e1i;
#pragma unroll
    for (int k = 1; k < Mn; k++) {
#pragma unroll
        for (int j = 0; j < Cn / 2; j++) {
            const float4 cc = s_spec4[k][j];
            to0[2 * j]     = fmaf(cc.x, w0r, fmaf(cc.y, w0i, to0[2 * j]));
            to1[2 * j]     = fmaf(cc.x, w1r, fmaf(cc.y, w1i, to1[2 * j]));
            to0[2 * j + 1] = fmaf(cc.z, w0r, fmaf(cc.w, w0i, to0[2 * j + 1]));
            to1[2 * j + 1] = fmaf(cc.z, w1r, fmaf(cc.w, w1i, to1[2 * j + 1]));
        }
        if (k < Mn - 1) {
            float nr = w0r * e0r - w0i * e0i, ni = w0r * e0i + w0i * e0r;
            w0r = nr; w0i = ni;
            nr = w1r * e1r - w1i * e1i; ni = w1r * e1i + w1i * e1r;
            w1r = nr; w1i = ni;
        }
    }
}

// conv accumulation using transposed float4 weights
__device__ __forceinline__ void conv_acc(const float s_wwT[Cn][Cn],
                                         float h0, float h1, int c,
                                         float* to0, float* to1) {
    const float4* wrow = (const float4*)s_wwT[c];
#pragma unroll
    for (int j = 0; j < Cn / 4; j++) {
        const float4 w4 = wrow[j];
        to0[4 * j + 0] = fmaf(h0, w4.x, to0[4 * j + 0]);
        to1[4 * j + 0] = fmaf(h1, w4.x, to1[4 * j + 0]);
        to0[4 * j + 1] = fmaf(h0, w4.y, to0[4 * j + 1]);
        to1[4 * j + 1] = fmaf(h1, w4.y, to1[4 * j + 1]);
        to0[4 * j + 2] = fmaf(h0, w4.z, to0[4 * j + 2]);
        to1[4 * j + 2] = fmaf(h1, w4.z, to1[4 * j + 2]);
        to0[4 * j + 3] = fmaf(h0, w4.w, to0[4 * j + 3]);
        to1[4 * j + 3] = fmaf(h1, w4.w, to1[4 * j + 3]);
    }
}

// ---- inverse + 1x1 conv + gelu (layers 1..2), 2 samples/thread -------------
__global__ void __launch_bounds__(256) fno_kinv2(const float* __restrict__ ww,
                                                 const float* __restrict__ wb) {
    __shared__ float4 s_spec4[Mn][Cn / 2];
    __shared__ float  s_base[Cn];
    __shared__ float  s_wwT[Cn][Cn];
    const int b = blockIdx.y;
    const int tid = threadIdx.x;
    coef_to_smem4(b, wb, s_spec4, s_base, tid, 256);
    ww_to_smemT(ww, s_wwT, tid, 256);
    __syncthreads();

    const int s0 = blockIdx.x * 512 + 2 * tid;   // pair (s0, s0+1)
    float to0[Cn], to1[Cn];
    synth2(s_spec4, s_base, s0, to0, to1);

#pragma unroll
    for (int c = 0; c < Cn; c++) {
        const float2 hp = *(const float2*)(g_h + ((size_t)(b * Cn + c)) * Sn + s0);
        conv_acc(s_wwT, hp.x, hp.y, c, to0, to1);
    }
#pragma unroll
    for (int o = 0; o < Cn; o++) {
        float2 r = make_float2(gelu_fast(to0[o]), gelu_fast(to1[o]));
        *(float2*)(g_h + ((size_t)(b * Cn + o)) * Sn + s0) = r;
    }
}

// ---- layer-0 inverse: h computed on the fly from x/pd/fc0 -----------------
__global__ void __launch_bounds__(256) fno_kinv2_l0(const float* __restrict__ ww,
                                                    const float* __restrict__ wb,
                                                    const float* __restrict__ x,
                                                    const float* __restrict__ pd,
                                                    const float* __restrict__ fc0w,
                                                    const float* __restrict__ fc0b) {
    __shared__ float4 s_spec4[Mn][Cn / 2];
    __shared__ float  s_base[Cn];
    __shared__ float  s_wwT[Cn][Cn];
    __shared__ float  s_f0w[2 * Cn];
    __shared__ float  s_f0b[Cn];
    const int b = blockIdx.y;
    const int tid = threadIdx.x;
    coef_to_smem4(b, wb, s_spec4, s_base, tid, 256);
    ww_to_smemT(ww, s_wwT, tid, 256);
    if (tid < 2 * Cn) s_f0w[tid] = fc0w[tid];
    if (tid < Cn) s_f0b[tid] = fc0b[tid];
    __syncthreads();

    const int s0 = blockIdx.x * 512 + 2 * tid;
    float to0[Cn], to1[Cn];
    synth2(s_spec4, s_base, s0, to0, to1);

    const float invm = g_invmaxv;
    const float2 xp = *(const float2*)(x + (size_t)b * Sn + s0);
    const float2 pp = *(const float2*)(pd + s0);
    const float gr0 = pp.x * invm, gr1 = pp.y * invm;
#pragma unroll
    for (int c = 0; c < Cn; c++) {
        const float w0 = s_f0w[c], w1 = s_f0w[Cn + c], bc = s_f0b[c];
        const float h0 = fmaf(xp.x, w0, fmaf(gr0, w1, bc));
        const float h1 = fmaf(xp.y, w0, fmaf(gr1, w1, bc));
        conv_acc(s_wwT, h0, h1, c, to0, to1);
    }
#pragma unroll
    for (int o = 0; o < Cn; o++) {
        float2 r = make_float2(gelu_fast(to0[o]), gelu_fast(to1[o]));
        *(float2*)(g_h + ((size_t)(b * Cn + o)) * Sn + s0) = r;
    }
}

// ---- final: layer-3 inverse+conv (no gelu) -> fc1 (tf32 MMA) -> gelu -> fc2
__global__ void __launch_bounds__(256, 2) fno_kfinal2(const float* __restrict__ ww,
                                                      const float* __restrict__ wb,
                                                      const float* __restrict__ fc1w,
                                                      const float* __restrict__ fc1b,
                                                      const float* __restrict__ fc2w,
                                                      const float* __restrict__ fc2b,
                                                      float* __restrict__ out) {
    __shared__ float4 s_spec4[Mn][Cn / 2];
    __shared__ float  s_base[Cn];
    __shared__ float  s_wwT[Cn][Cn];
    __shared__ float  s_toT[Cn][520];      // transposed to-values (tf32), pad 520
    __shared__ float  s_fc1w[Cn][136];     // fc1 weights k-major (tf32), pad 136
    __shared__ float  s_fc1b[Hn];
    __shared__ float  s_fc2[Hn];
    const int b = blockIdx.y;
    const int tid = threadIdx.x;
    coef_to_smem4(b, wb, s_spec4, s_base, tid, 256);
    ww_to_smemT(ww, s_wwT, tid, 256);
    for (int i = tid; i < Cn * Hn; i += 256) {
        const int c = i / Hn, n = i % Hn;
        s_fc1w[c][n] = to_tf32(fc1w[i]);
    }
    if (tid < Hn) { s_fc1b[tid] = fc1b[tid]; s_fc2[tid] = fc2w[tid]; }
    __syncthreads();

    const int s0 = blockIdx.x * 512 + 2 * tid;
    float to0[Cn], to1[Cn];
    synth2(s_spec4, s_base, s0, to0, to1);

#pragma unroll
    for (int c = 0; c < Cn; c++) {
        const float2 hp = *(const float2*)(g_h + ((size_t)(b * Cn + c)) * Sn + s0);
        conv_acc(s_wwT, hp.x, hp.y, c, to0, to1);
    }
    // layer 3 output (NO gelu) -> stage to smem transposed, tf32-rounded.
    const int ls = 2 * tid;   // block-local sample
#pragma unroll
    for (int c = 0; c < Cn; c++) {
        *(float2*)(&s_toT[c][ls]) = make_float2(to_tf32(to0[c]), to_tf32(to1[c]));
    }
    __syncwarp();   // warp w's threads wrote exactly warp w's 64 samples

    // fc1 via mma.sync m16n8k4 tf32: warp owns 64 samples = 4 M-tiles of 16.
    const int w = tid >> 5, lane = tid & 31;
    const int gq = lane >> 2;   // groupID 0..7
    const int qi = lane & 3;    // quad index 0..3
    const int sbase = w * 64;

    // preload all A fragments: [mtile][kstep][2]
    float afr[4][5][2];
#pragma unroll
    for (int mt = 0; mt < 4; mt++)
#pragma unroll
        for (int ks = 0; ks < 5; ks++) {
            afr[mt][ks][0] = s_toT[ks * 4 + qi][sbase + mt * 16 + gq];
            afr[mt][ks][1] = s_toT[ks * 4 + qi][sbase + mt * 16 + gq + 8];
        }

    float res[4][2];
#pragma unroll
    for (int mt = 0; mt < 4; mt++) { res[mt][0] = 0.f; res[mt][1] = 0.f; }

#pragma unroll 2
    for (int nt = 0; nt < 16; nt++) {
        float bfr[5];
#pragma unroll
        for (int ks = 0; ks < 5; ks++) bfr[ks] = s_fc1w[ks * 4 + qi][nt * 8 + gq];
        const int c0 = nt * 8 + 2 * qi;
        const float b0v = s_fc1b[c0], b1v = s_fc1b[c0 + 1];
        const float f20 = s_fc2[c0],  f21 = s_fc2[c0 + 1];
#pragma unroll
        for (int mt = 0; mt < 4; mt++) {
            float d0 = b0v, d1 = b1v, d2 = b0v, d3 = b1v;
#pragma unroll
            for (int ks = 0; ks < 5; ks++) {
                asm volatile(
                    "mma.sync.aligned.m16n8k4.row.col.f32.tf32.tf32.f32 "
                    "{%0,%1,%2,%3}, {%4,%5}, {%6}, {%0,%1,%2,%3};"
                    : "+f"(d0), "+f"(d1), "+f"(d2), "+f"(d3)
                    : "r"(__float_as_uint(afr[mt][ks][0])),
                      "r"(__float_as_uint(afr[mt][ks][1])),
                      "r"(__float_as_uint(bfr[ks])));
            }
            res[mt][0] += gelu_cheap(d0) * f20 + gelu_cheap(d1) * f21;
            res[mt][1] += gelu_cheap(d2) * f20 + gelu_cheap(d3) * f21;
        }
    }

    // quad reduction (lanes qi=0..3 hold disjoint column partials of same rows)
    const float f2b = fc2b[0];
    float* orow = out + (size_t)b * Sn + blockIdx.x * 512;
#pragma unroll
    for (int mt = 0; mt < 4; mt++) {
#pragma unroll
        for (int hh = 0; hh < 2; hh++) {
            float v = res[mt][hh];
            v += __shfl_xor_sync(0xffffffffu, v, 1);
            v += __shfl_xor_sync(0xffffffffu, v, 2);
            if (qi == 0) {
                orow[sbase + mt * 16 + gq + hh * 8] = v + f2b;
            }
        }
    }
}

// ------------------------------------------------------------------ launch
extern "C" void kernel_launch(void* const* d_in, const int* in_sizes, int n_in,
                              void* d_out, int out_size) {
    const float* x  = (const float*)d_in[0];
    const float* pd = (const float*)d_in[1];
    const float* fc0w = (const float*)d_in[2];
    const float* fc0b = (const float*)d_in[3];
    const float *fc1w, *fc1b, *fc2w, *fc2b;
    const float *sre[4], *sim[4], *lww[4], *lwb[4];

    if (in_sizes[4] == Cn * Hn) {
        fc1w = (const float*)d_in[4]; fc1b = (const float*)d_in[5];
        fc2w = (const float*)d_in[6]; fc2b = (const float*)d_in[7];
        for (int l = 0; l < 4; l++) {
            sre[l] = (const float*)d_in[8 + 4 * l];
            sim[l] = (const float*)d_in[9 + 4 * l];
            lww[l] = (const float*)d_in[10 + 4 * l];
            lwb[l] = (const float*)d_in[11 + 4 * l];
        }
    } else {
        for (int l = 0; l < 4; l++) {
            sre[l] = (const float*)d_in[4 + 4 * l];
            sim[l] = (const float*)d_in[5 + 4 * l];
            lww[l] = (const float*)d_in[6 + 4 * l];
            lwb[l] = (const float*)d_in[7 + 4 * l];
        }
        fc1w = (const float*)d_in[20]; fc1b = (const float*)d_in[21];
        fc2w = (const float*)d_in[22]; fc2b = (const float*)d_in[23];
    }

    float* out = (float*)d_out;
    const dim3 gInv(Sn / 512, Bn);
    const dim3 gMix(Bn, Cn);

    fno_kmax<<<1, 1024>>>(pd);

    // layer 0: forward DFT + inverse both compute fc0's h on the fly
    fno_kfwd0<<<dim3(2, Cn, Bn), 256>>>(x, pd, fc0w, fc0b);
    fno_kmix<<<gMix, 32>>>(sre[0], sim[0]);
    fno_kinv2_l0<<<gInv, 256>>>(lww[0], lwb[0], x, pd, fc0w, fc0b);

    for (int l = 1; l < 3; l++) {
        fno_kfwd<<<dim3(2, Cn, Bn), 256>>>();
        fno_kmix<<<gMix, 32>>>(sre[l], sim[l]);
        fno_kinv2<<<gInv, 256>>>(lww[l], lwb[l]);
    }
    fno_kfwd<<<dim3(2, Cn, Bn), 256>>>();
    fno_kmix<<<gMix, 32>>>(sre[3], sim[3]);
    fno_kfinal2<<<gInv, 256>>>(lww[3], lwb[3], fc1w, fc1b, fc2w, fc2b, out);
}

// round 14
// speedup vs baseline: 1.4657x; 1.0114x over previous
#include <cuda_runtime.h>
#include <math.h>

#define Bn 32
#define Cn 20
#define Sn 65536
#define Mn 16
#define Qn 4096
#define Hn 128

// Scratch (device globals; allocation-free rule)
__device__ float  g_h[(size_t)Bn * Cn * Sn];          // (B, C, S) ~168MB
__device__ float  g_partR[Bn][Cn][2][Mn];
__device__ float  g_partI[Bn][Cn][2][Mn];
__device__ float2 g_coef[Bn][Cn][Mn];
__device__ float  g_maxv;
__device__ float  g_invmaxv;

// Fast gelu: A&S 7.1.28 erf approximation, |eps| <= 3e-7, branch-free.
__device__ __forceinline__ float fast_rcp(float x) {
    float r; asm("rcp.approx.f32 %0, %1;" : "=f"(r) : "f"(x)); return r;
}
__device__ __forceinline__ float gelu_fast(float x) {
    const float u = fabsf(x) * 0.7071067811865476f;
    float p = fmaf(0.0000430638f, u, 0.0002765672f);
    p = fmaf(p, u, 0.0001520143f);
    p = fmaf(p, u, 0.0092705272f);
    p = fmaf(p, u, 0.0422820123f);
    p = fmaf(p, u, 0.0705230784f);
    p = fmaf(p, u, 1.0f);
    float r = fast_rcp(p);
    r = r * r; r = r * r; r = r * r; r = r * r;   // ^16
    const float erf_v = copysignf(1.0f - r, x);
    return 0.5f * x * (1.0f + erf_v);
}

// Cheaper gelu for the FINAL layer only: A&S 7.1.27, |eps_erf| <= 5e-4.
__device__ __forceinline__ float gelu_cheap(float x) {
    const float u = fabsf(x) * 0.7071067811865476f;
    float p = fmaf(0.078108f, u, 0.000972f);
    p = fmaf(p, u, 0.230389f);
    p = fmaf(p, u, 0.278393f);
    p = fmaf(p, u, 1.0f);
    float r = fast_rcp(p);
    r = r * r; r = r * r;                         // ^4
    const float erf_v = copysignf(1.0f - r, x);
    return 0.5f * x * (1.0f + erf_v);
}

__device__ __forceinline__ float to_tf32(float x) {
    float r; asm("cvt.rna.tf32.f32 %0, %1;" : "=f"(r) : "f"(x)); return r;
}

// rotation between sample s and s+1: e^{+2pi i/65536}
#define C1R 0.9999999954025773f
#define S1R 9.587379909597734e-5f

// ------------------------------------------------------------------ max
__global__ void fno_kmax(const float* __restrict__ p) {
    __shared__ float sm[1024];
    float m = -1e30f;
    for (int i = threadIdx.x; i < Sn; i += 1024) m = fmaxf(m, p[i]);
    sm[threadIdx.x] = m;
    __syncthreads();
    for (int off = 512; off; off >>= 1) {
        if (threadIdx.x < off) sm[threadIdx.x] = fmaxf(sm[threadIdx.x], sm[threadIdx.x + off]);
        __syncthreads();
    }
    if (threadIdx.x == 0) { g_maxv = sm[0]; g_invmaxv = 1.0f / sm[0]; }
}

// ================= forward truncated DFT (16 modes) ========================
__device__ __forceinline__ void dft16_accum(const float hp[16], float zr, float zi,
                                            float* Fr, float* Fi) {
    const float C16[16] = { 1.f,  0.9238795325112867f,  0.7071067811865476f,  0.3826834323650898f,
                            0.f, -0.3826834323650898f, -0.7071067811865476f, -0.9238795325112867f,
                           -1.f, -0.9238795325112867f, -0.7071067811865476f, -0.3826834323650898f,
                            0.f,  0.3826834323650898f,  0.7071067811865476f,  0.9238795325112867f };
    const float S16[16] = { 0.f,  0.3826834323650898f,  0.7071067811865476f,  0.9238795325112867f,
                            1.f,  0.9238795325112867f,  0.7071067811865476f,  0.3826834323650898f,
                            0.f, -0.3826834323650898f, -0.7071067811865476f, -0.9238795325112867f,
                           -1.f, -0.9238795325112867f, -0.7071067811865476f, -0.3826834323650898f };
    float u[8], dd[8];
#pragma unroll
    for (int p = 0; p < 8; p++) { u[p] = hp[p] + hp[p + 8]; dd[p] = hp[p] - hp[p + 8]; }
    float BR[16], BI[16];
#pragma unroll
    for (int j = 0; j <= 4; j++) {
        float ar = 0.f, ai = 0.f;
#pragma unroll
        for (int p = 0; p < 8; p++) {
            const int m = (2 * j * p) & 15;
            ar += u[p] * C16[m];
            ai -= u[p] * S16[m];
        }
        BR[2 * j] = ar; BI[2 * j] = ai;
    }
#pragma unroll
    for (int k = 1; k < 8; k += 2) {
        float ar = 0.f, ai = 0.f;
#pragma unroll
        for (int p = 0; p < 8; p++) {
            const int m = (k * p) & 15;
            ar += dd[p] * C16[m];
            ai -= dd[p] * S16[m];
        }
        BR[k] = ar; BI[k] = ai;
    }
#pragma unroll
    for (int k = 9; k < 16; k++) { BR[k] = BR[16 - k]; BI[k] = -BI[16 - k]; }

    Fr[0] += BR[0];
    Fi[0] += BI[0];
    float wr = zr, wi = zi;
#pragma unroll
    for (int k = 1; k < 16; k++) {
        Fr[k] += BR[k] * wr - BI[k] * wi;
        Fi[k] += BR[k] * wi + BI[k] * wr;
        const float nwr = wr * zr - wi * zi;
        const float nwi = wr * zi + wi * zr;
        wr = nwr; wi = nwi;
    }
}

__device__ __forceinline__ void dft16_reduce_store(float* Fr, float* Fi,
                                                   int b, int c, int qc, int tid) {
#pragma unroll
    for (int off = 16; off; off >>= 1) {
#pragma unroll
        for (int k = 0; k < Mn; k++) {
            Fr[k] += __shfl_down_sync(0xffffffffu, Fr[k], off);
            Fi[k] += __shfl_down_sync(0xffffffffu, Fi[k], off);
        }
    }
    __shared__ float redR[8][Mn], redI[8][Mn];
    const int warp = tid >> 5, lane = tid & 31;
    if (lane == 0) {
#pragma unroll
        for (int k = 0; k < Mn; k++) { redR[warp][k] = Fr[k]; redI[warp][k] = Fi[k]; }
    }
    __syncthreads();
    if (tid < Mn) {
        float ar = 0.f, ai = 0.f;
#pragma unroll
        for (int w = 0; w < 8; w++) { ar += redR[w][tid]; ai += redI[w][tid]; }
        g_partR[b][c][qc][tid] = ar;
        g_partI[b][c][qc][tid] = ai;
    }
}

// generic forward DFT: reads g_h (2x unrolled for MLP)
__global__ void __launch_bounds__(256) fno_kfwd() {
    const int qc = blockIdx.x, c = blockIdx.y, b = blockIdx.z;
    const float* __restrict__ row = g_h + ((size_t)(b * Cn + c)) * Sn;
    const int tid = threadIdx.x;
    const int q0 = qc * 2048 + tid;

    float Fr[Mn], Fi[Mn];
#pragma unroll
    for (int k = 0; k < Mn; k++) { Fr[k] = 0.f; Fi[k] = 0.f; }
    float zr, zi;
    sincospif(-(float)q0 * (1.0f / 32768.0f), &zi, &zr);
    const float Rr =  0.9996988186962042f;
    const float Ri = -0.0245412285229123f;

    for (int it = 0; it < 8; it += 2) {
        const int qa = q0 + it * 256;
        const int qb = qa + 256;
        float hpa[16], hpb[16];
#pragma unroll
        for (int p = 0; p < 16; p++) hpa[p] = row[qa + p * Qn];
#pragma unroll
        for (int p = 0; p < 16; p++) hpb[p] = row[qb + p * Qn];
        dft16_accum(hpa, zr, zi, Fr, Fi);
        {
            const float nzr = zr * Rr - zi * Ri;
            const float nzi = zr * Ri + zi * Rr;
            zr = nzr; zi = nzi;
        }
        dft16_accum(hpb, zr, zi, Fr, Fi);
        {
            const float nzr = zr * Rr - zi * Ri;
            const float nzi = zr * Ri + zi * Rr;
            zr = nzr; zi = nzi;
        }
    }
    dft16_reduce_store(Fr, Fi, b, c, qc, tid);
}

// layer-0 forward DFT: computes h on the fly from x, point_data, fc0 (2x unrolled)
__global__ void __launch_bounds__(256) fno_kfwd0(const float* __restrict__ x,
                                                 const float* __restrict__ pd,
                                                 const float* __restrict__ fc0w,
                                                 const float* __restrict__ fc0b) {
    const int qc = blockIdx.x, c = blockIdx.y, b = blockIdx.z;
    const int tid = threadIdx.x;
    const int q0 = qc * 2048 + tid;
    const float w0 = fc0w[c], w1 = fc0w[Cn + c], bc = fc0b[c];
    const float invm = g_invmaxv;
    const float* __restrict__ xrow = x + (size_t)b * Sn;

    float Fr[Mn], Fi[Mn];
#pragma unroll
    for (int k = 0; k < Mn; k++) { Fr[k] = 0.f; Fi[k] = 0.f; }
    float zr, zi;
    sincospif(-(float)q0 * (1.0f / 32768.0f), &zi, &zr);
    const float Rr =  0.9996988186962042f;
    const float Ri = -0.0245412285229123f;

    for (int it = 0; it < 8; it += 2) {
        const int qa = q0 + it * 256;
        const int qb = qa + 256;
        float xa[16], pa[16], xb[16], pb[16];
#pragma unroll
        for (int p = 0; p < 16; p++) { xa[p] = xrow[qa + p * Qn]; pa[p] = pd[qa + p * Qn]; }
#pragma unroll
        for (int p = 0; p < 16; p++) { xb[p] = xrow[qb + p * Qn]; pb[p] = pd[qb + p * Qn]; }
        float hpa[16], hpb[16];
#pragma unroll
        for (int p = 0; p < 16; p++) hpa[p] = fmaf(xa[p], w0, fmaf(pa[p] * invm, w1, bc));
#pragma unroll
        for (int p = 0; p < 16; p++) hpb[p] = fmaf(xb[p], w0, fmaf(pb[p] * invm, w1, bc));
        dft16_accum(hpa, zr, zi, Fr, Fi);
        {
            const float nzr = zr * Rr - zi * Ri;
            const float nzi = zr * Ri + zi * Rr;
            zr = nzr; zi = nzi;
        }
        dft16_accum(hpb, zr, zi, Fr, Fi);
        {
            const float nzr = zr * Rr - zi * Ri;
            const float nzi = zr * Ri + zi * Rr;
            zr = nzr; zi = nzi;
        }
    }
    dft16_reduce_store(Fr, Fi, b, c, qc, tid);
}

// ------------------------------------------------------------------ mode mixing
__global__ void fno_kmix(const float* __restrict__ sre, const float* __restrict__ sim) {
    const int b = blockIdx.x, o = blockIdx.y;
    const int tid = threadIdx.x;
    const int k = tid & 15, ih = tid >> 4;
    float Gr = 0.f, Gi = 0.f;
#pragma unroll
    for (int j = 0; j < Cn / 2; j++) {
        const int i = ih * (Cn / 2) + j;
        const float fr = g_partR[b][i][0][k] + g_partR[b][i][1][k];
        const float fi = g_partI[b][i][0][k] + g_partI[b][i][1][k];
        const float wr = sre[i * (Cn * Mn) + o * Mn + k];
        const float wi = sim[i * (Cn * Mn) + o * Mn + k];
        Gr += fr * wr - fi * wi;
        Gi += fr * wi + fi * wr;
    }
    Gr += __shfl_down_sync(0xffffffffu, Gr, 16);
    Gi += __shfl_down_sync(0xffffffffu, Gi, 16);
    if (tid < 16) {
        const float invS = 1.0f / (float)Sn;
        float2 cf;
        if (k == 0) { cf.x = Gr * invS; cf.y = 0.f; }
        else        { cf.x = 2.f * Gr * invS; cf.y = 2.f * Gi * invS; }
        g_coef[b][o][k] = cf;
    }
}

// ===== shared staging: spectral coefs packed float4 (o-pairs), conv wT =====
__device__ __forceinline__ void coef_to_smem4(int b, const float* __restrict__ wb,
                                              float4 s_spec4[Mn][Cn / 2], float* s_base,
                                              int tid, int nthr) {
    float* specf = (float*)s_spec4;
    for (int i = tid; i < Cn * Mn; i += nthr) {
        const int o = i >> 4, k = i & 15;
        const float2 cf = g_coef[b][o][k];
        if (k == 0) s_base[o] = cf.x + wb[o];
        else {
            const int idx = k * (Cn * 2) + (o >> 1) * 4 + (o & 1) * 2;
            specf[idx]     = cf.x;
            specf[idx + 1] = -cf.y;
        }
    }
}

__device__ __forceinline__ void ww_to_smemT(const float* __restrict__ ww,
                                            float s_wwT[Cn][Cn], int tid, int nthr) {
    for (int i = tid; i < Cn * Cn; i += nthr) {
        const int o = i / Cn, c = i % Cn;
        s_wwT[c][o] = ww[i];
    }
}

// ========= spectral synthesis for a pair of samples (s0, s0+1) =============
__device__ __forceinline__ void synth2(const float4 s_spec4[Mn][Cn / 2], const float* s_base,
                                       int s0, float* to0, float* to1) {
    float e0r, e0i;
    sincospif((float)s0 * (1.0f / 32768.0f), &e0i, &e0r);
    const float e1r = e0r * C1R - e0i * S1R;
    const float e1i = e0r * S1R + e0i * C1R;

#pragma unroll
    for (int o = 0; o < Cn; o++) { to0[o] = s_base[o]; to1[o] = s_base[o]; }

    float w0r = e0r, w0i = e0i, w1r = e1r, w1i = e1i;
#pragma unroll
    for (int k = 1; k < Mn; k++) {
#pragma unroll
        for (int j = 0; j < Cn / 2; j++) {
            const float4 cc = s_spec4[k][j];
            to0[2 * j]     = fmaf(cc.x, w0r, fmaf(cc.y, w0i, to0[2 * j]));
            to1[2 * j]     = fmaf(cc.x, w1r, fmaf(cc.y, w1i, to1[2 * j]));
            to0[2 * j + 1] = fmaf(cc.z, w0r, fmaf(cc.w, w0i, to0[2 * j + 1]));
            to1[2 * j + 1] = fmaf(cc.z, w1r, fmaf(cc.w, w1i, to1[2 * j + 1]));
        }
        if (k < Mn - 1) {
            float nr = w0r * e0r - w0i * e0i, ni = w0r * e0i + w0i * e0r;
            w0r = nr; w0i = ni;
            nr = w1r * e1r - w1i * e1i; ni = w1r * e1i + w1i * e1r;
            w1r = nr; w1i = ni;
        }
    }
}

// conv accumulation using transposed float4 weights
__device__ __forceinline__ void conv_acc(const float s_wwT[Cn][Cn],
                                         float h0, float h1, int c,
                                         float* to0, float* to1) {
    const float4* wrow = (const float4*)s_wwT[c];
#pragma unroll
    for (int j = 0; j < Cn / 4; j++) {
        const float4 w4 = wrow[j];
        to0[4 * j + 0] = fmaf(h0, w4.x, to0[4 * j + 0]);
        to1[4 * j + 0] = fmaf(h1, w4.x, to1[4 * j + 0]);
        to0[4 * j + 1] = fmaf(h0, w4.y, to0[4 * j + 1]);
        to1[4 * j + 1] = fmaf(h1, w4.y, to1[4 * j + 1]);
        to0[4 * j + 2] = fmaf(h0, w4.z, to0[4 * j + 2]);
        to1[4 * j + 2] = fmaf(h1, w4.z, to1[4 * j + 2]);
        to0[4 * j + 3] = fmaf(h0, w4.w, to0[4 * j + 3]);
        to1[4 * j + 3] = fmaf(h1, w4.w, to1[4 * j + 3]);
    }
}

// ---- inverse + 1x1 conv + gelu (layers 1..2), 2 samples/thread -------------
// min 3 blocks/SM: regs capped at 84 (was 86 at 2 blocks) -> occ 24% -> 36%
__global__ void __launch_bounds__(256, 3) fno_kinv2(const float* __restrict__ ww,
                                                    const float* __restrict__ wb) {
    __shared__ float4 s_spec4[Mn][Cn / 2];
    __shared__ float  s_base[Cn];
    __shared__ float  s_wwT[Cn][Cn];
    const int b = blockIdx.y;
    const int tid = threadIdx.x;
    coef_to_smem4(b, wb, s_spec4, s_base, tid, 256);
    ww_to_smemT(ww, s_wwT, tid, 256);
    __syncthreads();

    const int s0 = blockIdx.x * 512 + 2 * tid;   // pair (s0, s0+1)
    float to0[Cn], to1[Cn];
    synth2(s_spec4, s_base, s0, to0, to1);

#pragma unroll
    for (int c = 0; c < Cn; c++) {
        const float2 hp = *(const float2*)(g_h + ((size_t)(b * Cn + c)) * Sn + s0);
        conv_acc(s_wwT, hp.x, hp.y, c, to0, to1);
    }
#pragma unroll
    for (int o = 0; o < Cn; o++) {
        float2 r = make_float2(gelu_fast(to0[o]), gelu_fast(to1[o]));
        *(float2*)(g_h + ((size_t)(b * Cn + o)) * Sn + s0) = r;
    }
}

// ---- layer-0 inverse: h computed on the fly from x/pd/fc0 -----------------
__global__ void __launch_bounds__(256, 3) fno_kinv2_l0(const float* __restrict__ ww,
                                                       const float* __restrict__ wb,
                                                       const float* __restrict__ x,
                                                       const float* __restrict__ pd,
                                                       const float* __restrict__ fc0w,
                                                       const float* __restrict__ fc0b) {
    __shared__ float4 s_spec4[Mn][Cn / 2];
    __shared__ float  s_base[Cn];
    __shared__ float  s_wwT[Cn][Cn];
    __shared__ float  s_f0w[2 * Cn];
    __shared__ float  s_f0b[Cn];
    const int b = blockIdx.y;
    const int tid = threadIdx.x;
    coef_to_smem4(b, wb, s_spec4, s_base, tid, 256);
    ww_to_smemT(ww, s_wwT, tid, 256);
    if (tid < 2 * Cn) s_f0w[tid] = fc0w[tid];
    if (tid < Cn) s_f0b[tid] = fc0b[tid];
    __syncthreads();

    const int s0 = blockIdx.x * 512 + 2 * tid;
    float to0[Cn], to1[Cn];
    synth2(s_spec4, s_base, s0, to0, to1);

    const float invm = g_invmaxv;
    const float2 xp = *(const float2*)(x + (size_t)b * Sn + s0);
    const float2 pp = *(const float2*)(pd + s0);
    const float gr0 = pp.x * invm, gr1 = pp.y * invm;
#pragma unroll
    for (int c = 0; c < Cn; c++) {
        const float w0 = s_f0w[c], w1 = s_f0w[Cn + c], bc = s_f0b[c];
        const float h0 = fmaf(xp.x, w0, fmaf(gr0, w1, bc));
        const float h1 = fmaf(xp.y, w0, fmaf(gr1, w1, bc));
        conv_acc(s_wwT, h0, h1, c, to0, to1);
    }
#pragma unroll
    for (int o = 0; o < Cn; o++) {
        float2 r = make_float2(gelu_fast(to0[o]), gelu_fast(to1[o]));
        *(float2*)(g_h + ((size_t)(b * Cn + o)) * Sn + s0) = r;
    }
}

// ---- final: layer-3 inverse+conv (no gelu) -> fc1 (tf32 MMA) -> gelu -> fc2
__global__ void __launch_bounds__(256, 2) fno_kfinal2(const float* __restrict__ ww,
                                                      const float* __restrict__ wb,
                                                      const float* __restrict__ fc1w,
                                                      const float* __restrict__ fc1b,
                                                      const float* __restrict__ fc2w,
                                                      const float* __restrict__ fc2b,
                                                      float* __restrict__ out) {
    __shared__ float4 s_spec4[Mn][Cn / 2];
    __shared__ float  s_base[Cn];
    __shared__ float  s_wwT[Cn][Cn];
    __shared__ float  s_toT[Cn][520];      // transposed to-values (tf32), pad 520
    __shared__ float  s_fc1w[Cn][136];     // fc1 weights k-major (tf32), pad 136
    __shared__ float  s_fc1b[Hn];
    __shared__ float  s_fc2[Hn];
    const int b = blockIdx.y;
    const int tid = threadIdx.x;
    coef_to_smem4(b, wb, s_spec4, s_base, tid, 256);
    ww_to_smemT(ww, s_wwT, tid, 256);
    for (int i = tid; i < Cn * Hn; i += 256) {
        const int c = i / Hn, n = i % Hn;
        s_fc1w[c][n] = to_tf32(fc1w[i]);
    }
    if (tid < Hn) { s_fc1b[tid] = fc1b[tid]; s_fc2[tid] = fc2w[tid]; }
    __syncthreads();

    const int s0 = blockIdx.x * 512 + 2 * tid;
    float to0[Cn], to1[Cn];
    synth2(s_spec4, s_base, s0, to0, to1);

#pragma unroll
    for (int c = 0; c < Cn; c++) {
        const float2 hp = *(const float2*)(g_h + ((size_t)(b * Cn + c)) * Sn + s0);
        conv_acc(s_wwT, hp.x, hp.y, c, to0, to1);
    }
    // layer 3 output (NO gelu) -> stage to smem transposed, tf32-rounded.
    const int ls = 2 * tid;   // block-local sample
#pragma unroll
    for (int c = 0; c < Cn; c++) {
        *(float2*)(&s_toT[c][ls]) = make_float2(to_tf32(to0[c]), to_tf32(to1[c]));
    }
    __syncwarp();   // warp w's threads wrote exactly warp w's 64 samples

    // fc1 via mma.sync m16n8k4 tf32: warp owns 64 samples = 4 M-tiles of 16.
    const int w = tid >> 5, lane = tid & 31;
    const int gq = lane >> 2;   // groupID 0..7
    const int qi = lane & 3;    // quad index 0..3
    const int sbase = w * 64;

    // preload all A fragments: [mtile][kstep][2]
    float afr[4][5][2];
#pragma unroll
    for (int mt = 0; mt < 4; mt++)
#pragma unroll
        for (int ks = 0; ks < 5; ks++) {
            afr[mt][ks][0] = s_toT[ks * 4 + qi][sbase + mt * 16 + gq];
            afr[mt][ks][1] = s_toT[ks * 4 + qi][sbase + mt * 16 + gq + 8];
        }

    float res[4][2];
#pragma unroll
    for (int mt = 0; mt < 4; mt++) { res[mt][0] = 0.f; res[mt][1] = 0.f; }

#pragma unroll 2
    for (int nt = 0; nt < 16; nt++) {
        float bfr[5];
#pragma unroll
        for (int ks = 0; ks < 5; ks++) bfr[ks] = s_fc1w[ks * 4 + qi][nt * 8 + gq];
        const int c0 = nt * 8 + 2 * qi;
        const float b0v = s_fc1b[c0], b1v = s_fc1b[c0 + 1];
        const float f20 = s_fc2[c0],  f21 = s_fc2[c0 + 1];
#pragma unroll
        for (int mt = 0; mt < 4; mt++) {
            float d0 = b0v, d1 = b1v, d2 = b0v, d3 = b1v;
#pragma unroll
            for (int ks = 0; ks < 5; ks++) {
                asm volatile(
                    "mma.sync.aligned.m16n8k4.row.col.f32.tf32.tf32.f32 "
                    "{%0,%1,%2,%3}, {%4,%5}, {%6}, {%0,%1,%2,%3};"
                    : "+f"(d0), "+f"(d1), "+f"(d2), "+f"(d3)
                    : "r"(__float_as_uint(afr[mt][ks][0])),
                      "r"(__float_as_uint(afr[mt][ks][1])),
                      "r"(__float_as_uint(bfr[ks])));
            }
            res[mt][0] += gelu_cheap(d0) * f20 + gelu_cheap(d1) * f21;
            res[mt][1] += gelu_cheap(d2) * f20 + gelu_cheap(d3) * f21;
        }
    }

    // quad reduction (lanes qi=0..3 hold disjoint column partials of same rows)
    const float f2b = fc2b[0];
    float* orow = out + (size_t)b * Sn + blockIdx.x * 512;
#pragma unroll
    for (int mt = 0; mt < 4; mt++) {
#pragma unroll
        for (int hh = 0; hh < 2; hh++) {
            float v = res[mt][hh];
            v += __shfl_xor_sync(0xffffffffu, v, 1);
            v += __shfl_xor_sync(0xffffffffu, v, 2);
            if (qi == 0) {
                orow[sbase + mt * 16 + gq + hh * 8] = v + f2b;
            }
        }
    }
}

// ------------------------------------------------------------------ launch
extern "C" void kernel_launch(void* const* d_in, const int* in_sizes, int n_in,
                              void* d_out, int out_size) {
    const float* x  = (const float*)d_in[0];
    const float* pd = (const float*)d_in[1];
    const float* fc0w = (const float*)d_in[2];
    const float* fc0b = (const float*)d_in[3];
    const float *fc1w, *fc1b, *fc2w, *fc2b;
    const float *sre[4], *sim[4], *lww[4], *lwb[4];

    if (in_sizes[4] == Cn * Hn) {
        fc1w = (const float*)d_in[4]; fc1b = (const float*)d_in[5];
        fc2w = (const float*)d_in[6]; fc2b = (const float*)d_in[7];
        for (int l = 0; l < 4; l++) {
            sre[l] = (const float*)d_in[8 + 4 * l];
            sim[l] = (const float*)d_in[9 + 4 * l];
            lww[l] = (const float*)d_in[10 + 4 * l];
            lwb[l] = (const float*)d_in[11 + 4 * l];
        }
    } else {
        for (int l = 0; l < 4; l++) {
            sre[l] = (const float*)d_in[4 + 4 * l];
            sim[l] = (const float*)d_in[5 + 4 * l];
            lww[l] = (const float*)d_in[6 + 4 * l];
            lwb[l] = (const float*)d_in[7 + 4 * l];
        }
        fc1w = (const float*)d_in[20]; fc1b = (const float*)d_in[21];
        fc2w = (const float*)d_in[22]; fc2b = (const float*)d_in[23];
    }

    float* out = (float*)d_out;
    const dim3 gInv(Sn / 512, Bn);
    const dim3 gMix(Bn, Cn);

    fno_kmax<<<1, 1024>>>(pd);

    // layer 0: forward DFT + inverse both compute fc0's h on the fly
    fno_kfwd0<<<dim3(2, Cn, Bn), 256>>>(x, pd, fc0w, fc0b);
    fno_kmix<<<gMix, 32>>>(sre[0], sim[0]);
    fno_kinv2_l0<<<gInv, 256>>>(lww[0], lwb[0], x, pd, fc0w, fc0b);

    for (int l = 1; l < 3; l++) {
        fno_kfwd<<<dim3(2, Cn, Bn), 256>>>();
        fno_kmix<<<gMix, 32>>>(sre[l], sim[l]);
        fno_kinv2<<<gInv, 256>>>(lww[l], lwb[l]);
    }
    fno_kfwd<<<dim3(2, Cn, Bn), 256>>>();
    fno_kmix<<<gMix, 32>>>(sre[3], sim[3]);
    fno_kfinal2<<<gInv, 256>>>(lww[3], lwb[3], fc1w, fc1b, fc2w, fc2b, out);
}

// round 15
// speedup vs baseline: 1.5994x; 1.0912x over previous
#include <cuda_runtime.h>
#include <math.h>

#define Bn 32
#define Cn 20
#define Sn 65536
#define Mn 16
#define Qn 4096
#define Hn 128

// Scratch (device globals; allocation-free rule)
__device__ float  g_h[(size_t)Bn * Cn * Sn];          // (B, C, S) ~168MB
__device__ float  g_partR[Bn][Cn][2][Mn];
__device__ float  g_partI[Bn][Cn][2][Mn];
__device__ float2 g_coef[Bn][Cn][Mn];
__device__ float  g_maxv;
__device__ float  g_invmaxv;

// Fast gelu: A&S 7.1.28 erf approximation, |eps| <= 3e-7, branch-free.
__device__ __forceinline__ float fast_rcp(float x) {
    float r; asm("rcp.approx.f32 %0, %1;" : "=f"(r) : "f"(x)); return r;
}
__device__ __forceinline__ float gelu_fast(float x) {
    const float u = fabsf(x) * 0.7071067811865476f;
    float p = fmaf(0.0000430638f, u, 0.0002765672f);
    p = fmaf(p, u, 0.0001520143f);
    p = fmaf(p, u, 0.0092705272f);
    p = fmaf(p, u, 0.0422820123f);
    p = fmaf(p, u, 0.0705230784f);
    p = fmaf(p, u, 1.0f);
    float r = fast_rcp(p);
    r = r * r; r = r * r; r = r * r; r = r * r;   // ^16
    const float erf_v = copysignf(1.0f - r, x);
    return 0.5f * x * (1.0f + erf_v);
}

// FINAL-layer gelu: tanh-form with HW tanh.approx (sm_75+ MUFU).
// |gelu_tanh - gelu_exact| <= ~3e-4 abs; tanh.approx adds ~5e-4 rel.
// Used only for the last nonlinearity (no compounding through layers).
__device__ __forceinline__ float gelu_tanh_hw(float x) {
    const float x3 = x * x * x;
    const float t = fmaf(0.044715f, x3, x) * 0.7978845608028654f;
    float th; asm("tanh.approx.f32 %0, %1;" : "=f"(th) : "f"(t));
    return 0.5f * x * (1.0f + th);
}

__device__ __forceinline__ float to_tf32(float x) {
    float r; asm("cvt.rna.tf32.f32 %0, %1;" : "=f"(r) : "f"(x)); return r;
}

// rotation between sample s and s+1: e^{+2pi i/65536}
#define C1R 0.9999999954025773f
#define S1R 9.587379909597734e-5f

// ------------------------------------------------------------------ max
__global__ void fno_kmax(const float* __restrict__ p) {
    __shared__ float sm[1024];
    float m = -1e30f;
    for (int i = threadIdx.x; i < Sn; i += 1024) m = fmaxf(m, p[i]);
    sm[threadIdx.x] = m;
    __syncthreads();
    for (int off = 512; off; off >>= 1) {
        if (threadIdx.x < off) sm[threadIdx.x] = fmaxf(sm[threadIdx.x], sm[threadIdx.x + off]);
        __syncthreads();
    }
    if (threadIdx.x == 0) { g_maxv = sm[0]; g_invmaxv = 1.0f / sm[0]; }
}

// ================= forward truncated DFT (16 modes) ========================
__device__ __forceinline__ void dft16_accum(const float hp[16], float zr, float zi,
                                            float* Fr, float* Fi) {
    const float C16[16] = { 1.f,  0.9238795325112867f,  0.7071067811865476f,  0.3826834323650898f,
                            0.f, -0.3826834323650898f, -0.7071067811865476f, -0.9238795325112867f,
                           -1.f, -0.9238795325112867f, -0.7071067811865476f, -0.3826834323650898f,
                            0.f,  0.3826834323650898f,  0.7071067811865476f,  0.9238795325112867f };
    const float S16[16] = { 0.f,  0.3826834323650898f,  0.7071067811865476f,  0.9238795325112867f,
                            1.f,  0.9238795325112867f,  0.7071067811865476f,  0.3826834323650898f,
                            0.f, -0.3826834323650898f, -0.7071067811865476f, -0.9238795325112867f,
                           -1.f, -0.9238795325112867f, -0.7071067811865476f, -0.3826834323650898f };
    float u[8], dd[8];
#pragma unroll
    for (int p = 0; p < 8; p++) { u[p] = hp[p] + hp[p + 8]; dd[p] = hp[p] - hp[p + 8]; }
    float BR[16], BI[16];
#pragma unroll
    for (int j = 0; j <= 4; j++) {
        float ar = 0.f, ai = 0.f;
#pragma unroll
        for (int p = 0; p < 8; p++) {
            const int m = (2 * j * p) & 15;
            ar += u[p] * C16[m];
            ai -= u[p] * S16[m];
        }
        BR[2 * j] = ar; BI[2 * j] = ai;
    }
#pragma unroll
    for (int k = 1; k < 8; k += 2) {
        float ar = 0.f, ai = 0.f;
#pragma unroll
        for (int p = 0; p < 8; p++) {
            const int m = (k * p) & 15;
            ar += dd[p] * C16[m];
            ai -= dd[p] * S16[m];
        }
        BR[k] = ar; BI[k] = ai;
    }
#pragma unroll
    for (int k = 9; k < 16; k++) { BR[k] = BR[16 - k]; BI[k] = -BI[16 - k]; }

    Fr[0] += BR[0];
    Fi[0] += BI[0];
    float wr = zr, wi = zi;
#pragma unroll
    for (int k = 1; k < 16; k++) {
        Fr[k] += BR[k] * wr - BI[k] * wi;
        Fi[k] += BR[k] * wi + BI[k] * wr;
        const float nwr = wr * zr - wi * zi;
        const float nwi = wr * zi + wi * zr;
        wr = nwr; wi = nwi;
    }
}

__device__ __forceinline__ void dft16_reduce_store(float* Fr, float* Fi,
                                                   int b, int c, int qc, int tid) {
#pragma unroll
    for (int off = 16; off; off >>= 1) {
#pragma unroll
        for (int k = 0; k < Mn; k++) {
            Fr[k] += __shfl_down_sync(0xffffffffu, Fr[k], off);
            Fi[k] += __shfl_down_sync(0xffffffffu, Fi[k], off);
        }
    }
    __shared__ float redR[8][Mn], redI[8][Mn];
    const int warp = tid >> 5, lane = tid & 31;
    if (lane == 0) {
#pragma unroll
        for (int k = 0; k < Mn; k++) { redR[warp][k] = Fr[k]; redI[warp][k] = Fi[k]; }
    }
    __syncthreads();
    if (tid < Mn) {
        float ar = 0.f, ai = 0.f;
#pragma unroll
        for (int w = 0; w < 8; w++) { ar += redR[w][tid]; ai += redI[w][tid]; }
        g_partR[b][c][qc][tid] = ar;
        g_partI[b][c][qc][tid] = ai;
    }
}

// generic forward DFT: reads g_h (2x unrolled for MLP)
__global__ void __launch_bounds__(256) fno_kfwd() {
    const int qc = blockIdx.x, c = blockIdx.y, b = blockIdx.z;
    const float* __restrict__ row = g_h + ((size_t)(b * Cn + c)) * Sn;
    const int tid = threadIdx.x;
    const int q0 = qc * 2048 + tid;

    float Fr[Mn], Fi[Mn];
#pragma unroll
    for (int k = 0; k < Mn; k++) { Fr[k] = 0.f; Fi[k] = 0.f; }
    float zr, zi;
    sincospif(-(float)q0 * (1.0f / 32768.0f), &zi, &zr);
    const float Rr =  0.9996988186962042f;
    const float Ri = -0.0245412285229123f;

    for (int it = 0; it < 8; it += 2) {
        const int qa = q0 + it * 256;
        const int qb = qa + 256;
        float hpa[16], hpb[16];
#pragma unroll
        for (int p = 0; p < 16; p++) hpa[p] = row[qa + p * Qn];
#pragma unroll
        for (int p = 0; p < 16; p++) hpb[p] = row[qb + p * Qn];
        dft16_accum(hpa, zr, zi, Fr, Fi);
        {
            const float nzr = zr * Rr - zi * Ri;
            const float nzi = zr * Ri + zi * Rr;
            zr = nzr; zi = nzi;
        }
        dft16_accum(hpb, zr, zi, Fr, Fi);
        {
            const float nzr = zr * Rr - zi * Ri;
            const float nzi = zr * Ri + zi * Rr;
            zr = nzr; zi = nzi;
        }
    }
    dft16_reduce_store(Fr, Fi, b, c, qc, tid);
}

// layer-0 forward DFT: computes h on the fly from x, point_data, fc0 (2x unrolled)
__global__ void __launch_bounds__(256) fno_kfwd0(const float* __restrict__ x,
                                                 const float* __restrict__ pd,
                                                 const float* __restrict__ fc0w,
                                                 const float* __restrict__ fc0b) {
    const int qc = blockIdx.x, c = blockIdx.y, b = blockIdx.z;
    const int tid = threadIdx.x;
    const int q0 = qc * 2048 + tid;
    const float w0 = fc0w[c], w1 = fc0w[Cn + c], bc = fc0b[c];
    const float invm = g_invmaxv;
    const float* __restrict__ xrow = x + (size_t)b * Sn;

    float Fr[Mn], Fi[Mn];
#pragma unroll
    for (int k = 0; k < Mn; k++) { Fr[k] = 0.f; Fi[k] = 0.f; }
    float zr, zi;
    sincospif(-(float)q0 * (1.0f / 32768.0f), &zi, &zr);
    const float Rr =  0.9996988186962042f;
    const float Ri = -0.0245412285229123f;

    for (int it = 0; it < 8; it += 2) {
        const int qa = q0 + it * 256;
        const int qb = qa + 256;
        float xa[16], pa[16], xb[16], pb[16];
#pragma unroll
        for (int p = 0; p < 16; p++) { xa[p] = xrow[qa + p * Qn]; pa[p] = pd[qa + p * Qn]; }
#pragma unroll
        for (int p = 0; p < 16; p++) { xb[p] = xrow[qb + p * Qn]; pb[p] = pd[qb + p * Qn]; }
        float hpa[16], hpb[16];
#pragma unroll
        for (int p = 0; p < 16; p++) hpa[p] = fmaf(xa[p], w0, fmaf(pa[p] * invm, w1, bc));
#pragma unroll
        for (int p = 0; p < 16; p++) hpb[p] = fmaf(xb[p], w0, fmaf(pb[p] * invm, w1, bc));
        dft16_accum(hpa, zr, zi, Fr, Fi);
        {
            const float nzr = zr * Rr - zi * Ri;
            const float nzi = zr * Ri + zi * Rr;
            zr = nzr; zi = nzi;
        }
        dft16_accum(hpb, zr, zi, Fr, Fi);
        {
            const float nzr = zr * Rr - zi * Ri;
            const float nzi = zr * Ri + zi * Rr;
            zr = nzr; zi = nzi;
        }
    }
    dft16_reduce_store(Fr, Fi, b, c, qc, tid);
}

// ------------------------------------------------------------------ mode mixing
__global__ void fno_kmix(const float* __restrict__ sre, const float* __restrict__ sim) {
    const int b = blockIdx.x, o = blockIdx.y;
    const int tid = threadIdx.x;
    const int k = tid & 15, ih = tid >> 4;
    float Gr = 0.f, Gi = 0.f;
#pragma unroll
    for (int j = 0; j < Cn / 2; j++) {
        const int i = ih * (Cn / 2) + j;
        const float fr = g_partR[b][i][0][k] + g_partR[b][i][1][k];
        const float fi = g_partI[b][i][0][k] + g_partI[b][i][1][k];
        const float wr = sre[i * (Cn * Mn) + o * Mn + k];
        const float wi = sim[i * (Cn * Mn) + o * Mn + k];
        Gr += fr * wr - fi * wi;
        Gi += fr * wi + fi * wr;
    }
    Gr += __shfl_down_sync(0xffffffffu, Gr, 16);
    Gi += __shfl_down_sync(0xffffffffu, Gi, 16);
    if (tid < 16) {
        const float invS = 1.0f / (float)Sn;
        float2 cf;
        if (k == 0) { cf.x = Gr * invS; cf.y = 0.f; }
        else        { cf.x = 2.f * Gr * invS; cf.y = 2.f * Gi * invS; }
        g_coef[b][o][k] = cf;
    }
}

// ===== shared staging: spectral coefs packed float4 (o-pairs), conv wT =====
__device__ __forceinline__ void coef_to_smem4(int b, const float* __restrict__ wb,
                                              float4 s_spec4[Mn][Cn / 2], float* s_base,
                                              int tid, int nthr) {
    float* specf = (float*)s_spec4;
    for (int i = tid; i < Cn * Mn; i += nthr) {
        const int o = i >> 4, k = i & 15;
        const float2 cf = g_coef[b][o][k];
        if (k == 0) s_base[o] = cf.x + wb[o];
        else {
            const int idx = k * (Cn * 2) + (o >> 1) * 4 + (o & 1) * 2;
            specf[idx]     = cf.x;
            specf[idx + 1] = -cf.y;
        }
    }
}

__device__ __forceinline__ void ww_to_smemT(const float* __restrict__ ww,
                                            float s_wwT[Cn][Cn], int tid, int nthr) {
    for (int i = tid; i < Cn * Cn; i += nthr) {
        const int o = i / Cn, c = i % Cn;
        s_wwT[c][o] = ww[i];
    }
}

// ========= spectral synthesis for a pair of samples (s0, s0+1) =============
__device__ __forceinline__ void synth2(const float4 s_spec4[Mn][Cn / 2], const float* s_base,
                                       int s0, float* to0, float* to1) {
    float e0r, e0i;
    sincospif((float)s0 * (1.0f / 32768.0f), &e0i, &e0r);
    const float e1r = e0r * C1R - e0i * S1R;
    const float e1i = e0r * S1R + e0i * C1R;

#pragma unroll
    for (int o = 0; o < Cn; o++) { to0[o] = s_base[o]; to1[o] = s_base[o]; }

    float w0r = e0r, w0i = e0i, w1r = e1r, w1i = e1i;
#pragma unroll
    for (int k = 1; k < Mn; k++) {
#pragma unroll
        for (int j = 0; j < Cn / 2; j++) {
            const float4 cc = s_spec4[k][j];
            to0[2 * j]     = fmaf(cc.x, w0r, fmaf(cc.y, w0i, to0[2 * j]));
            to1[2 * j]     = fmaf(cc.x, w1r, fmaf(cc.y, w1i, to1[2 * j]));
            to0[2 * j + 1] = fmaf(cc.z, w0r, fmaf(cc.w, w0i, to0[2 * j + 1]));
            to1[2 * j + 1] = fmaf(cc.z, w1r, fmaf(cc.w, w1i, to1[2 * j + 1]));
        }
        if (k < Mn - 1) {
            float nr = w0r * e0r - w0i * e0i, ni = w0r * e0i + w0i * e0r;
            w0r = nr; w0i = ni;
            nr = w1r * e1r - w1i * e1i; ni = w1r * e1i + w1i * e1r;
            w1r = nr; w1i = ni;
        }
    }
}

// conv accumulation using transposed float4 weights
__device__ __forceinline__ void conv_acc(const float s_wwT[Cn][Cn],
                                         float h0, float h1, int c,
                                         float* to0, float* to1) {
    const float4* wrow = (const float4*)s_wwT[c];
#pragma unroll
    for (int j = 0; j < Cn / 4; j++) {
        const float4 w4 = wrow[j];
        to0[4 * j + 0] = fmaf(h0, w4.x, to0[4 * j + 0]);
        to1[4 * j + 0] = fmaf(h1, w4.x, to1[4 * j + 0]);
        to0[4 * j + 1] = fmaf(h0, w4.y, to0[4 * j + 1]);
        to1[4 * j + 1] = fmaf(h1, w4.y, to1[4 * j + 1]);
        to0[4 * j + 2] = fmaf(h0, w4.z, to0[4 * j + 2]);
        to1[4 * j + 2] = fmaf(h1, w4.z, to1[4 * j + 2]);
        to0[4 * j + 3] = fmaf(h0, w4.w, to0[4 * j + 3]);
        to1[4 * j + 3] = fmaf(h1, w4.w, to1[4 * j + 3]);
    }
}

// ---- inverse + 1x1 conv + gelu (layers 1..2), 2 samples/thread -------------
__global__ void __launch_bounds__(256, 3) fno_kinv2(const float* __restrict__ ww,
                                                    const float* __restrict__ wb) {
    __shared__ float4 s_spec4[Mn][Cn / 2];
    __shared__ float  s_base[Cn];
    __shared__ float  s_wwT[Cn][Cn];
    const int b = blockIdx.y;
    const int tid = threadIdx.x;
    coef_to_smem4(b, wb, s_spec4, s_base, tid, 256);
    ww_to_smemT(ww, s_wwT, tid, 256);
    __syncthreads();

    const int s0 = blockIdx.x * 512 + 2 * tid;   // pair (s0, s0+1)
    float to0[Cn], to1[Cn];
    synth2(s_spec4, s_base, s0, to0, to1);

#pragma unroll
    for (int c = 0; c < Cn; c++) {
        const float2 hp = *(const float2*)(g_h + ((size_t)(b * Cn + c)) * Sn + s0);
        conv_acc(s_wwT, hp.x, hp.y, c, to0, to1);
    }
#pragma unroll
    for (int o = 0; o < Cn; o++) {
        float2 r = make_float2(gelu_fast(to0[o]), gelu_fast(to1[o]));
        *(float2*)(g_h + ((size_t)(b * Cn + o)) * Sn + s0) = r;
    }
}

// ---- layer-0 inverse: h computed on the fly from x/pd/fc0 -----------------
__global__ void __launch_bounds__(256, 3) fno_kinv2_l0(const float* __restrict__ ww,
                                                       const float* __restrict__ wb,
                                                       const float* __restrict__ x,
                                                       const float* __restrict__ pd,
                                                       const float* __restrict__ fc0w,
                                                       const float* __restrict__ fc0b) {
    __shared__ float4 s_spec4[Mn][Cn / 2];
    __shared__ float  s_base[Cn];
    __shared__ float  s_wwT[Cn][Cn];
    __shared__ float  s_f0w[2 * Cn];
    __shared__ float  s_f0b[Cn];
    const int b = blockIdx.y;
    const int tid = threadIdx.x;
    coef_to_smem4(b, wb, s_spec4, s_base, tid, 256);
    ww_to_smemT(ww, s_wwT, tid, 256);
    if (tid < 2 * Cn) s_f0w[tid] = fc0w[tid];
    if (tid < Cn) s_f0b[tid] = fc0b[tid];
    __syncthreads();

    const int s0 = blockIdx.x * 512 + 2 * tid;
    float to0[Cn], to1[Cn];
    synth2(s_spec4, s_base, s0, to0, to1);

    const float invm = g_invmaxv;
    const float2 xp = *(const float2*)(x + (size_t)b * Sn + s0);
    const float2 pp = *(const float2*)(pd + s0);
    const float gr0 = pp.x * invm, gr1 = pp.y * invm;
#pragma unroll
    for (int c = 0; c < Cn; c++) {
        const float w0 = s_f0w[c], w1 = s_f0w[Cn + c], bc = s_f0b[c];
        const float h0 = fmaf(xp.x, w0, fmaf(gr0, w1, bc));
        const float h1 = fmaf(xp.y, w0, fmaf(gr1, w1, bc));
        conv_acc(s_wwT, h0, h1, c, to0, to1);
    }
#pragma unroll
    for (int o = 0; o < Cn; o++) {
        float2 r = make_float2(gelu_fast(to0[o]), gelu_fast(to1[o]));
        *(float2*)(g_h + ((size_t)(b * Cn + o)) * Sn + s0) = r;
    }
}

// ---- final: layer-3 inverse+conv (no gelu) -> fc1 (tf32 MMA) -> gelu -> fc2
__global__ void __launch_bounds__(256, 2) fno_kfinal2(const float* __restrict__ ww,
                                                      const float* __restrict__ wb,
                                                      const float* __restrict__ fc1w,
                                                      const float* __restrict__ fc1b,
                                                      const float* __restrict__ fc2w,
                                                      const float* __restrict__ fc2b,
                                                      float* __restrict__ out) {
    __shared__ float4 s_spec4[Mn][Cn / 2];
    __shared__ float  s_base[Cn];
    __shared__ float  s_wwT[Cn][Cn];
    __shared__ float  s_toT[Cn][520];      // transposed to-values (tf32), pad 520
    __shared__ float  s_fc1w[Cn][136];     // fc1 weights k-major (tf32), pad 136
    __shared__ float  s_fc1b[Hn];
    __shared__ float  s_fc2[Hn];
    const int b = blockIdx.y;
    const int tid = threadIdx.x;
    coef_to_smem4(b, wb, s_spec4, s_base, tid, 256);
    ww_to_smemT(ww, s_wwT, tid, 256);
    for (int i = tid; i < Cn * Hn; i += 256) {
        const int c = i / Hn, n = i % Hn;
        s_fc1w[c][n] = to_tf32(fc1w[i]);
    }
    if (tid < Hn) { s_fc1b[tid] = fc1b[tid]; s_fc2[tid] = fc2w[tid]; }
    __syncthreads();

    const int s0 = blockIdx.x * 512 + 2 * tid;
    float to0[Cn], to1[Cn];
    synth2(s_spec4, s_base, s0, to0, to1);

#pragma unroll
    for (int c = 0; c < Cn; c++) {
        const float2 hp = *(const float2*)(g_h + ((size_t)(b * Cn + c)) * Sn + s0);
        conv_acc(s_wwT, hp.x, hp.y, c, to0, to1);
    }
    // layer 3 output (NO gelu) -> stage to smem transposed, tf32-rounded.
    const int ls = 2 * tid;   // block-local sample
#pragma unroll
    for (int c = 0; c < Cn; c++) {
        *(float2*)(&s_toT[c][ls]) = make_float2(to_tf32(to0[c]), to_tf32(to1[c]));
    }
    __syncwarp();   // warp w's threads wrote exactly warp w's 64 samples

    // fc1 via mma.sync m16n8k4 tf32: warp owns 64 samples = 4 M-tiles of 16.
    const int w = tid >> 5, lane = tid & 31;
    const int gq = lane >> 2;   // groupID 0..7
    const int qi = lane & 3;    // quad index 0..3
    const int sbase = w * 64;

    // preload all A fragments: [mtile][kstep][2]
    float afr[4][5][2];
#pragma unroll
    for (int mt = 0; mt < 4; mt++)
#pragma unroll
        for (int ks = 0; ks < 5; ks++) {
            afr[mt][ks][0] = s_toT[ks * 4 + qi][sbase + mt * 16 + gq];
            afr[mt][ks][1] = s_toT[ks * 4 + qi][sbase + mt * 16 + gq + 8];
        }

    float res[4][2];
#pragma unroll
    for (int mt = 0; mt < 4; mt++) { res[mt][0] = 0.f; res[mt][1] = 0.f; }

#pragma unroll 2
    for (int nt = 0; nt < 16; nt++) {
        float bfr[5];
#pragma unroll
        for (int ks = 0; ks < 5; ks++) bfr[ks] = s_fc1w[ks * 4 + qi][nt * 8 + gq];
        const int c0 = nt * 8 + 2 * qi;
        const float b0v = s_fc1b[c0], b1v = s_fc1b[c0 + 1];
        const float f20 = s_fc2[c0],  f21 = s_fc2[c0 + 1];
#pragma unroll
        for (int mt = 0; mt < 4; mt++) {
            float d0 = b0v, d1 = b1v, d2 = b0v, d3 = b1v;
#pragma unroll
            for (int ks = 0; ks < 5; ks++) {
                asm volatile(
                    "mma.sync.aligned.m16n8k4.row.col.f32.tf32.tf32.f32 "
                    "{%0,%1,%2,%3}, {%4,%5}, {%6}, {%0,%1,%2,%3};"
                    : "+f"(d0), "+f"(d1), "+f"(d2), "+f"(d3)
                    : "r"(__float_as_uint(afr[mt][ks][0])),
                      "r"(__float_as_uint(afr[mt][ks][1])),
                      "r"(__float_as_uint(bfr[ks])));
            }
            res[mt][0] += gelu_tanh_hw(d0) * f20 + gelu_tanh_hw(d1) * f21;
            res[mt][1] += gelu_tanh_hw(d2) * f20 + gelu_tanh_hw(d3) * f21;
        }
    }

    // quad reduction (lanes qi=0..3 hold disjoint column partials of same rows)
    const float f2b = fc2b[0];
    float* orow = out + (size_t)b * Sn + blockIdx.x * 512;
#pragma unroll
    for (int mt = 0; mt < 4; mt++) {
#pragma unroll
        for (int hh = 0; hh < 2; hh++) {
            float v = res[mt][hh];
            v += __shfl_xor_sync(0xffffffffu, v, 1);
            v += __shfl_xor_sync(0xffffffffu, v, 2);
            if (qi == 0) {
                orow[sbase + mt * 16 + gq + hh * 8] = v + f2b;
            }
        }
    }
}

// ------------------------------------------------------------------ launch
extern "C" void kernel_launch(void* const* d_in, const int* in_sizes, int n_in,
                              void* d_out, int out_size) {
    const float* x  = (const float*)d_in[0];
    const float* pd = (const float*)d_in[1];
    const float* fc0w = (const float*)d_in[2];
    const float* fc0b = (const float*)d_in[3];
    const float *fc1w, *fc1b, *fc2w, *fc2b;
    const float *sre[4], *sim[4], *lww[4], *lwb[4];

    if (in_sizes[4] == Cn * Hn) {
        fc1w = (const float*)d_in[4]; fc1b = (const float*)d_in[5];
        fc2w = (const float*)d_in[6]; fc2b = (const float*)d_in[7];
        for (int l = 0; l < 4; l++) {
            sre[l] = (const float*)d_in[8 + 4 * l];
            sim[l] = (const float*)d_in[9 + 4 * l];
            lww[l] = (const float*)d_in[10 + 4 * l];
            lwb[l] = (const float*)d_in[11 + 4 * l];
        }
    } else {
        for (int l = 0; l < 4; l++) {
            sre[l] = (const float*)d_in[4 + 4 * l];
            sim[l] = (const float*)d_in[5 + 4 * l];
            lww[l] = (const float*)d_in[6 + 4 * l];
            lwb[l] = (const float*)d_in[7 + 4 * l];
        }
        fc1w = (const float*)d_in[20]; fc1b = (const float*)d_in[21];
        fc2w = (const float*)d_in[22]; fc2b = (const float*)d_in[23];
    }

    float* out = (float*)d_out;
    const dim3 gInv(Sn / 512, Bn);
    const dim3 gMix(Bn, Cn);

    fno_kmax<<<1, 1024>>>(pd);

    // layer 0: forward DFT + inverse both compute fc0's h on the fly
    fno_kfwd0<<<dim3(2, Cn, Bn), 256>>>(x, pd, fc0w, fc0b);
    fno_kmix<<<gMix, 32>>>(sre[0], sim[0]);
    fno_kinv2_l0<<<gInv, 256>>>(lww[0], lwb[0], x, pd, fc0w, fc0b);

    for (int l = 1; l < 3; l++) {
        fno_kfwd<<<dim3(2, Cn, Bn), 256>>>();
        fno_kmix<<<gMix, 32>>>(sre[l], sim[l]);
        fno_kinv2<<<gInv, 256>>>(lww[l], lwb[l]);
    }
    fno_kfwd<<<dim3(2, Cn, Bn), 256>>>();
    fno_kmix<<<gMix, 32>>>(sre[3], sim[3]);
    fno_kfinal2<<<gInv, 256>>>(lww[3], lwb[3], fc1w, fc1b, fc2w, fc2b, out);
}

// round 17
// speedup vs baseline: 1.7039x; 1.0653x over previous
#include <cuda_runtime.h>
#include <math.h>

#define Bn 32
#define Cn 20
#define Sn 65536
#define Mn 16
#define Qn 4096
#define Hn 128

// Scratch (device globals; allocation-free rule)
__device__ float  g_h[(size_t)Bn * Cn * Sn];          // (B, C, S) ~168MB
__device__ float  g_partR[Bn][Cn][2][Mn];
__device__ float  g_partI[Bn][Cn][2][Mn];
__device__ float2 g_coef[Bn][Cn][Mn];
__device__ float  g_maxv;
__device__ float  g_invmaxv;

// gelu via tanh-form with HW tanh.approx (MUFU). |model err| ~3e-4 abs.
// Used for ALL gelus now; total error stays tf32-dominated (see R15/R16 notes).
__device__ __forceinline__ float gelu_tanh_hw(float x) {
    const float x3 = x * x * x;
    const float t = fmaf(0.044715f, x3, x) * 0.7978845608028654f;
    float th; asm("tanh.approx.f32 %0, %1;" : "=f"(th) : "f"(t));
    return 0.5f * x * (1.0f + th);
}

__device__ __forceinline__ float to_tf32(float x) {
    float r; asm("cvt.rna.tf32.f32 %0, %1;" : "=f"(r) : "f"(x)); return r;
}

// rotation between sample s and s+1: e^{+2pi i/65536}
#define C1R 0.9999999954025773f
#define S1R 9.587379909597734e-5f

// ------------------------------------------------------------------ max
__global__ void fno_kmax(const float* __restrict__ p) {
    __shared__ float sm[1024];
    float m = -1e30f;
    for (int i = threadIdx.x; i < Sn; i += 1024) m = fmaxf(m, p[i]);
    sm[threadIdx.x] = m;
    __syncthreads();
    for (int off = 512; off; off >>= 1) {
        if (threadIdx.x < off) sm[threadIdx.x] = fmaxf(sm[threadIdx.x], sm[threadIdx.x + off]);
        __syncthreads();
    }
    if (threadIdx.x == 0) { g_maxv = sm[0]; g_invmaxv = 1.0f / sm[0]; }
}

// ================= forward truncated DFT (16 modes) ========================
__device__ __forceinline__ void dft16_accum(const float hp[16], float zr, float zi,
                                            float* Fr, float* Fi) {
    const float C16[16] = { 1.f,  0.9238795325112867f,  0.7071067811865476f,  0.3826834323650898f,
                            0.f, -0.3826834323650898f, -0.7071067811865476f, -0.9238795325112867f,
                           -1.f, -0.9238795325112867f, -0.7071067811865476f, -0.3826834323650898f,
                            0.f,  0.3826834323650898f,  0.7071067811865476f,  0.9238795325112867f };
    const float S16[16] = { 0.f,  0.3826834323650898f,  0.7071067811865476f,  0.9238795325112867f,
                            1.f,  0.9238795325112867f,  0.7071067811865476f,  0.3826834323650898f,
                            0.f, -0.3826834323650898f, -0.7071067811865476f, -0.9238795325112867f,
                           -1.f, -0.9238795325112867f, -0.7071067811865476f, -0.3826834323650898f };
    float u[8], dd[8];
#pragma unroll
    for (int p = 0; p < 8; p++) { u[p] = hp[p] + hp[p + 8]; dd[p] = hp[p] - hp[p + 8]; }
    float BR[16], BI[16];
#pragma unroll
    for (int j = 0; j <= 4; j++) {
        float ar = 0.f, ai = 0.f;
#pragma unroll
        for (int p = 0; p < 8; p++) {
            const int m = (2 * j * p) & 15;
            ar += u[p] * C16[m];
            ai -= u[p] * S16[m];
        }
        BR[2 * j] = ar; BI[2 * j] = ai;
    }
#pragma unroll
    for (int k = 1; k < 8; k += 2) {
        float ar = 0.f, ai = 0.f;
#pragma unroll
        for (int p = 0; p < 8; p++) {
            const int m = (k * p) & 15;
            ar += dd[p] * C16[m];
            ai -= dd[p] * S16[m];
        }
        BR[k] = ar; BI[k] = ai;
    }
#pragma unroll
    for (int k = 9; k < 16; k++) { BR[k] = BR[16 - k]; BI[k] = -BI[16 - k]; }

    Fr[0] += BR[0];
    Fi[0] += BI[0];
    float wr = zr, wi = zi;
#pragma unroll
    for (int k = 1; k < 16; k++) {
        Fr[k] += BR[k] * wr - BI[k] * wi;
        Fi[k] += BR[k] * wi + BI[k] * wr;
        const float nwr = wr * zr - wi * zi;
        const float nwi = wr * zi + wi * zr;
        wr = nwr; wi = nwi;
    }
}

__device__ __forceinline__ void dft16_reduce_store(float* Fr, float* Fi,
                                                   int b, int c, int qc, int tid) {
#pragma unroll
    for (int off = 16; off; off >>= 1) {
#pragma unroll
        for (int k = 0; k < Mn; k++) {
            Fr[k] += __shfl_down_sync(0xffffffffu, Fr[k], off);
            Fi[k] += __shfl_down_sync(0xffffffffu, Fi[k], off);
        }
    }
    __shared__ float redR[8][Mn], redI[8][Mn];
    const int warp = tid >> 5, lane = tid & 31;
    if (lane == 0) {
#pragma unroll
        for (int k = 0; k < Mn; k++) { redR[warp][k] = Fr[k]; redI[warp][k] = Fi[k]; }
    }
    __syncthreads();
    if (tid < Mn) {
        float ar = 0.f, ai = 0.f;
#pragma unroll
        for (int w = 0; w < 8; w++) { ar += redR[w][tid]; ai += redI[w][tid]; }
        g_partR[b][c][qc][tid] = ar;
        g_partI[b][c][qc][tid] = ai;
    }
}

// generic forward DFT: reads g_h (2x unrolled for MLP)
__global__ void __launch_bounds__(256) fno_kfwd() {
    const int qc = blockIdx.x, c = blockIdx.y, b = blockIdx.z;
    const float* __restrict__ row = g_h + ((size_t)(b * Cn + c)) * Sn;
    const int tid = threadIdx.x;
    const int q0 = qc * 2048 + tid;

    float Fr[Mn], Fi[Mn];
#pragma unroll
    for (int k = 0; k < Mn; k++) { Fr[k] = 0.f; Fi[k] = 0.f; }
    float zr, zi;
    sincospif(-(float)q0 * (1.0f / 32768.0f), &zi, &zr);
    const float Rr =  0.9996988186962042f;
    const float Ri = -0.0245412285229123f;

    for (int it = 0; it < 8; it += 2) {
        const int qa = q0 + it * 256;
        const int qb = qa + 256;
        float hpa[16], hpb[16];
#pragma unroll
        for (int p = 0; p < 16; p++) hpa[p] = row[qa + p * Qn];
#pragma unroll
        for (int p = 0; p < 16; p++) hpb[p] = row[qb + p * Qn];
        dft16_accum(hpa, zr, zi, Fr, Fi);
        {
            const float nzr = zr * Rr - zi * Ri;
            const float nzi = zr * Ri + zi * Rr;
            zr = nzr; zi = nzi;
        }
        dft16_accum(hpb, zr, zi, Fr, Fi);
        {
            const float nzr = zr * Rr - zi * Ri;
            const float nzi = zr * Ri + zi * Rr;
            zr = nzr; zi = nzi;
        }
    }
    dft16_reduce_store(Fr, Fi, b, c, qc, tid);
}

// layer-0 forward DFT: computes h on the fly from x, point_data, fc0 (2x unrolled)
__global__ void __launch_bounds__(256) fno_kfwd0(const float* __restrict__ x,
                                                 const float* __restrict__ pd,
                                                 const float* __restrict__ fc0w,
                                                 const float* __restrict__ fc0b) {
    const int qc = blockIdx.x, c = blockIdx.y, b = blockIdx.z;
    const int tid = threadIdx.x;
    const int q0 = qc * 2048 + tid;
    const float w0 = fc0w[c], w1 = fc0w[Cn + c], bc = fc0b[c];
    const float invm = g_invmaxv;
    const float* __restrict__ xrow = x + (size_t)b * Sn;

    float Fr[Mn], Fi[Mn];
#pragma unroll
    for (int k = 0; k < Mn; k++) { Fr[k] = 0.f; Fi[k] = 0.f; }
    float zr, zi;
    sincospif(-(float)q0 * (1.0f / 32768.0f), &zi, &zr);
    const float Rr =  0.9996988186962042f;
    const float Ri = -0.0245412285229123f;

    for (int it = 0; it < 8; it += 2) {
        const int qa = q0 + it * 256;
        const int qb = qa + 256;
        float xa[16], pa[16], xb[16], pb[16];
#pragma unroll
        for (int p = 0; p < 16; p++) { xa[p] = xrow[qa + p * Qn]; pa[p] = pd[qa + p * Qn]; }
#pragma unroll
        for (int p = 0; p < 16; p++) { xb[p] = xrow[qb + p * Qn]; pb[p] = pd[qb + p * Qn]; }
        float hpa[16], hpb[16];
#pragma unroll
        for (int p = 0; p < 16; p++) hpa[p] = fmaf(xa[p], w0, fmaf(pa[p] * invm, w1, bc));
#pragma unroll
        for (int p = 0; p < 16; p++) hpb[p] = fmaf(xb[p], w0, fmaf(pb[p] * invm, w1, bc));
        dft16_accum(hpa, zr, zi, Fr, Fi);
        {
            const float nzr = zr * Rr - zi * Ri;
            const float nzi = zr * Ri + zi * Rr;
            zr = nzr; zi = nzi;
        }
        dft16_accum(hpb, zr, zi, Fr, Fi);
        {
            const float nzr = zr * Rr - zi * Ri;
            const float nzi = zr * Ri + zi * Rr;
            zr = nzr; zi = nzi;
        }
    }
    dft16_reduce_store(Fr, Fi, b, c, qc, tid);
}

// ------------------------------------------------------------------ mode mixing
__global__ void fno_kmix(const float* __restrict__ sre, const float* __restrict__ sim) {
    const int b = blockIdx.x, o = blockIdx.y;
    const int tid = threadIdx.x;
    const int k = tid & 15, ih = tid >> 4;
    float Gr = 0.f, Gi = 0.f;
#pragma unroll
    for (int j = 0; j < Cn / 2; j++) {
        const int i = ih * (Cn / 2) + j;
        const float fr = g_partR[b][i][0][k] + g_partR[b][i][1][k];
        const float fi = g_partI[b][i][0][k] + g_partI[b][i][1][k];
        const float wr = sre[i * (Cn * Mn) + o * Mn + k];
        const float wi = sim[i * (Cn * Mn) + o * Mn + k];
        Gr += fr * wr - fi * wi;
        Gi += fr * wi + fi * wr;
    }
    Gr += __shfl_down_sync(0xffffffffu, Gr, 16);
    Gi += __shfl_down_sync(0xffffffffu, Gi, 16);
    if (tid < 16) {
        const float invS = 1.0f / (float)Sn;
        float2 cf;
        if (k == 0) { cf.x = Gr * invS; cf.y = 0.f; }
        else        { cf.x = 2.f * Gr * invS; cf.y = 2.f * Gi * invS; }
        g_coef[b][o][k] = cf;
    }
}

// ===== shared staging: spectral coefs packed float4 (o-pairs), conv wT =====
__device__ __forceinline__ void coef_to_smem4(int b, const float* __restrict__ wb,
                                              float4 s_spec4[Mn][Cn / 2], float* s_base,
                                              int tid, int nthr) {
    float* specf = (float*)s_spec4;
    for (int i = tid; i < Cn * Mn; i += nthr) {
        const int o = i >> 4, k = i & 15;
        const float2 cf = g_coef[b][o][k];
        if (k == 0) s_base[o] = cf.x + wb[o];
        else {
            const int idx = k * (Cn * 2) + (o >> 1) * 4 + (o & 1) * 2;
            specf[idx]     = cf.x;
            specf[idx + 1] = -cf.y;
        }
    }
}

__device__ __forceinline__ void ww_to_smemT(const float* __restrict__ ww,
                                            float s_wwT[Cn][Cn], int tid, int nthr) {
    for (int i = tid; i < Cn * Cn; i += nthr) {
        const int o = i / Cn, c = i % Cn;
        s_wwT[c][o] = ww[i];
    }
}

// ========= spectral synthesis for a pair of samples (s0, s0+1) =============
__device__ __forceinline__ void synth2(const float4 s_spec4[Mn][Cn / 2], const float* s_base,
                                       int s0, float* to0, float* to1) {
    float e0r, e0i;
    sincospif((float)s0 * (1.0f / 32768.0f), &e0i, &e0r);
    const float e1r = e0r * C1R - e0i * S1R;
    const float e1i = e0r * S1R + e0i * C1R;

#pragma unroll
    for (int o = 0; o < Cn; o++) { to0[o] = s_base[o]; to1[o] = s_base[o]; }

    float w0r = e0r, w0i = e0i, w1r = e1r, w1i = e1i;
#pragma unroll
    for (int k = 1; k < Mn; k++) {
#pragma unroll
        for (int j = 0; j < Cn / 2; j++) {
            const float4 cc = s_spec4[k][j];
            to0[2 * j]     = fmaf(cc.x, w0r, fmaf(cc.y, w0i, to0[2 * j]));
            to1[2 * j]     = fmaf(cc.x, w1r, fmaf(cc.y, w1i, to1[2 * j]));
            to0[2 * j + 1] = fmaf(cc.z, w0r, fmaf(cc.w, w0i, to0[2 * j + 1]));
            to1[2 * j + 1] = fmaf(cc.z, w1r, fmaf(cc.w, w1i, to1[2 * j + 1]));
        }
        if (k < Mn - 1) {
            float nr = w0r * e0r - w0i * e0i, ni = w0r * e0i + w0i * e0r;
            w0r = nr; w0i = ni;
            nr = w1r * e1r - w1i * e1i; ni = w1r * e1i + w1i * e1r;
            w1r = nr; w1i = ni;
        }
    }
}

// conv accumulation using transposed float4 weights
__device__ __forceinline__ void conv_acc(const float s_wwT[Cn][Cn],
                                         float h0, float h1, int c,
                                         float* to0, float* to1) {
    const float4* wrow = (const float4*)s_wwT[c];
#pragma unroll
    for (int j = 0; j < Cn / 4; j++) {
        const float4 w4 = wrow[j];
        to0[4 * j + 0] = fmaf(h0, w4.x, to0[4 * j + 0]);
        to1[4 * j + 0] = fmaf(h1, w4.x, to1[4 * j + 0]);
        to0[4 * j + 1] = fmaf(h0, w4.y, to0[4 * j + 1]);
        to1[4 * j + 1] = fmaf(h1, w4.y, to1[4 * j + 1]);
        to0[4 * j + 2] = fmaf(h0, w4.z, to0[4 * j + 2]);
        to1[4 * j + 2] = fmaf(h1, w4.z, to1[4 * j + 2]);
        to0[4 * j + 3] = fmaf(h0, w4.w, to0[4 * j + 3]);
        to1[4 * j + 3] = fmaf(h1, w4.w, to1[4 * j + 3]);
    }
}

// ---- inverse + 1x1 conv + gelu (layers 1..2), 2 samples/thread -------------
__global__ void __launch_bounds__(256, 3) fno_kinv2(const float* __restrict__ ww,
                                                    const float* __restrict__ wb) {
    __shared__ float4 s_spec4[Mn][Cn / 2];
    __shared__ float  s_base[Cn];
    __shared__ float  s_wwT[Cn][Cn];
    const int b = blockIdx.y;
    const int tid = threadIdx.x;
    coef_to_smem4(b, wb, s_spec4, s_base, tid, 256);
    ww_to_smemT(ww, s_wwT, tid, 256);
    __syncthreads();

    const int s0 = blockIdx.x * 512 + 2 * tid;   // pair (s0, s0+1)
    float to0[Cn], to1[Cn];
    synth2(s_spec4, s_base, s0, to0, to1);

#pragma unroll
    for (int c = 0; c < Cn; c++) {
        const float2 hp = *(const float2*)(g_h + ((size_t)(b * Cn + c)) * Sn + s0);
        conv_acc(s_wwT, hp.x, hp.y, c, to0, to1);
    }
#pragma unroll
    for (int o = 0; o < Cn; o++) {
        float2 r = make_float2(gelu_tanh_hw(to0[o]), gelu_tanh_hw(to1[o]));
        *(float2*)(g_h + ((size_t)(b * Cn + o)) * Sn + s0) = r;
    }
}

// ---- layer-0 inverse: h computed on the fly from x/pd/fc0 -----------------
__global__ void __launch_bounds__(256, 3) fno_kinv2_l0(const float* __restrict__ ww,
                                                       const float* __restrict__ wb,
                                                       const float* __restrict__ x,
                                                       const float* __restrict__ pd,
                                                       const float* __restrict__ fc0w,
                                                       const float* __restrict__ fc0b) {
    __shared__ float4 s_spec4[Mn][Cn / 2];
    __shared__ float  s_base[Cn];
    __shared__ float  s_wwT[Cn][Cn];
    __shared__ float  s_f0w[2 * Cn];
    __shared__ float  s_f0b[Cn];
    const int b = blockIdx.y;
    const int tid = threadIdx.x;
    coef_to_smem4(b, wb, s_spec4, s_base, tid, 256);
    ww_to_smemT(ww, s_wwT, tid, 256);
    if (tid < 2 * Cn) s_f0w[tid] = fc0w[tid];
    if (tid < Cn) s_f0b[tid] = fc0b[tid];
    __syncthreads();

    const int s0 = blockIdx.x * 512 + 2 * tid;
    float to0[Cn], to1[Cn];
    synth2(s_spec4, s_base, s0, to0, to1);

    const float invm = g_invmaxv;
    const float2 xp = *(const float2*)(x + (size_t)b * Sn + s0);
    const float2 pp = *(const float2*)(pd + s0);
    const float gr0 = pp.x * invm, gr1 = pp.y * invm;
#pragma unroll
    for (int c = 0; c < Cn; c++) {
        const float w0 = s_f0w[c], w1 = s_f0w[Cn + c], bc = s_f0b[c];
        const float h0 = fmaf(xp.x, w0, fmaf(gr0, w1, bc));
        const float h1 = fmaf(xp.y, w0, fmaf(gr1, w1, bc));
        conv_acc(s_wwT, h0, h1, c, to0, to1);
    }
#pragma unroll
    for (int o = 0; o < Cn; o++) {
        float2 r = make_float2(gelu_tanh_hw(to0[o]), gelu_tanh_hw(to1[o]));
        *(float2*)(g_h + ((size_t)(b * Cn + o)) * Sn + s0) = r;
    }
}

// ---- final: layer-3 inverse+conv (no gelu) -> fc1 (tf32 MMA) -> gelu -> fc2
__global__ void __launch_bounds__(256, 2) fno_kfinal2(const float* __restrict__ ww,
                                                      const float* __restrict__ wb,
                                                      const float* __restrict__ fc1w,
                                                      const float* __restrict__ fc1b,
                                                      const float* __restrict__ fc2w,
                                                      const float* __restrict__ fc2b,
                                                      float* __restrict__ out) {
    __shared__ float4 s_spec4[Mn][Cn / 2];
    __shared__ float  s_base[Cn];
    __shared__ float  s_wwT[Cn][Cn];
    __shared__ float  s_toT[Cn][520];      // transposed to-values (tf32), pad 520
    __shared__ float  s_fc1w[Cn][136];     // fc1 weights k-major (tf32), pad 136
    __shared__ float  s_fc1b[Hn];
    __shared__ float  s_fc2[Hn];
    const int b = blockIdx.y;
    const int tid = threadIdx.x;
    coef_to_smem4(b, wb, s_spec4, s_base, tid, 256);
    ww_to_smemT(ww, s_wwT, tid, 256);
    for (int i = tid; i < Cn * Hn; i += 256) {
        const int c = i / Hn, n = i % Hn;
        s_fc1w[c][n] = to_tf32(fc1w[i]);
    }
    if (tid < Hn) { s_fc1b[tid] = fc1b[tid]; s_fc2[tid] = fc2w[tid]; }
    __syncthreads();

    const int s0 = blockIdx.x * 512 + 2 * tid;
    float to0[Cn], to1[Cn];
    synth2(s_spec4, s_base, s0, to0, to1);

#pragma unroll
    for (int c = 0; c < Cn; c++) {
        const float2 hp = *(const float2*)(g_h + ((size_t)(b * Cn + c)) * Sn + s0);
        conv_acc(s_wwT, hp.x, hp.y, c, to0, to1);
    }
    // layer 3 output (NO gelu) -> stage to smem transposed, tf32-rounded.
    const int ls = 2 * tid;   // block-local sample
#pragma unroll
    for (int c = 0; c < Cn; c++) {
        *(float2*)(&s_toT[c][ls]) = make_float2(to_tf32(to0[c]), to_tf32(to1[c]));
    }
    __syncwarp();   // warp w's threads wrote exactly warp w's 64 samples

    // fc1 via mma.sync m16n8k4 tf32: warp owns 64 samples = 4 M-tiles of 16.
    const int w = tid >> 5, lane = tid & 31;
    const int gq = lane >> 2;   // groupID 0..7
    const int qi = lane & 3;    // quad index 0..3
    const int sbase = w * 64;

    // preload all A fragments: [mtile][kstep][2]
    float afr[4][5][2];
#pragma unroll
    for (int mt = 0; mt < 4; mt++)
#pragma unroll
        for (int ks = 0; ks < 5; ks++) {
            afr[mt][ks][0] = s_toT[ks * 4 + qi][sbase + mt * 16 + gq];
            afr[mt][ks][1] = s_toT[ks * 4 + qi][sbase + mt * 16 + gq + 8];
        }

    float res[4][2];
#pragma unroll
    for (int mt = 0; mt < 4; mt++) { res[mt][0] = 0.f; res[mt][1] = 0.f; }

#pragma unroll 2
    for (int nt = 0; nt < 16; nt++) {
        float bfr[5];
#pragma unroll
        for (int ks = 0; ks < 5; ks++) bfr[ks] = s_fc1w[ks * 4 + qi][nt * 8 + gq];
        const int c0 = nt * 8 + 2 * qi;
        const float b0v = s_fc1b[c0], b1v = s_fc1b[c0 + 1];
        const float f20 = s_fc2[c0],  f21 = s_fc2[c0 + 1];
#pragma unroll
        for (int mt = 0; mt < 4; mt++) {
            float d0 = b0v, d1 = b1v, d2 = b0v, d3 = b1v;
#pragma unroll
            for (int ks = 0; ks < 5; ks++) {
                asm volatile(
                    "mma.sync.aligned.m16n8k4.row.col.f32.tf32.tf32.f32 "
                    "{%0,%1,%2,%3}, {%4,%5}, {%6}, {%0,%1,%2,%3};"
                    : "+f"(d0), "+f"(d1), "+f"(d2), "+f"(d3)
                    : "r"(__float_as_uint(afr[mt][ks][0])),
                      "r"(__float_as_uint(afr[mt][ks][1])),
                      "r"(__float_as_uint(bfr[ks])));
            }
            res[mt][0] += gelu_tanh_hw(d0) * f20 + gelu_tanh_hw(d1) * f21;
            res[mt][1] += gelu_tanh_hw(d2) * f20 + gelu_tanh_hw(d3) * f21;
        }
    }

    // quad reduction (lanes qi=0..3 hold disjoint column partials of same rows)
    const float f2b = fc2b[0];
    float* orow = out + (size_t)b * Sn + blockIdx.x * 512;
#pragma unroll
    for (int mt = 0; mt < 4; mt++) {
#pragma unroll
        for (int hh = 0; hh < 2; hh++) {
            float v = res[mt][hh];
            v += __shfl_xor_sync(0xffffffffu, v, 1);
            v += __shfl_xor_sync(0xffffffffu, v, 2);
            if (qi == 0) {
                orow[sbase + mt * 16 + gq + hh * 8] = v + f2b;
            }
        }
    }
}

// ------------------------------------------------------------------ launch
extern "C" void kernel_launch(void* const* d_in, const int* in_sizes, int n_in,
                              void* d_out, int out_size) {
    const float* x  = (const float*)d_in[0];
    const float* pd = (const float*)d_in[1];
    const float* fc0w = (const float*)d_in[2];
    const float* fc0b = (const float*)d_in[3];
    const float *fc1w, *fc1b, *fc2w, *fc2b;
    const float *sre[4], *sim[4], *lww[4], *lwb[4];

    if (in_sizes[4] == Cn * Hn) {
        fc1w = (const float*)d_in[4]; fc1b = (const float*)d_in[5];
        fc2w = (const float*)d_in[6]; fc2b = (const float*)d_in[7];
        for (int l = 0; l < 4; l++) {
            sre[l] = (const float*)d_in[8 + 4 * l];
            sim[l] = (const float*)d_in[9 + 4 * l];
            lww[l] = (const float*)d_in[10 + 4 * l];
            lwb[l] = (const float*)d_in[11 + 4 * l];
        }
    } else {
        for (int l = 0; l < 4; l++) {
            sre[l] = (const float*)d_in[4 + 4 * l];
            sim[l] = (const float*)d_in[5 + 4 * l];
            lww[l] = (const float*)d_in[6 + 4 * l];
            lwb[l] = (const float*)d_in[7 + 4 * l];
        }
        fc1w = (const float*)d_in[20]; fc1b = (const float*)d_in[21];
        fc2w = (const float*)d_in[22]; fc2b = (const float*)d_in[23];
    }

    float* out = (float*)d_out;
    const dim3 gInv(Sn / 512, Bn);
    const dim3 gMix(Bn, Cn);

    fno_kmax<<<1, 1024>>>(pd);

    // layer 0: forward DFT + inverse both compute fc0's h on the fly
    fno_kfwd0<<<dim3(2, Cn, Bn), 256>>>(x, pd, fc0w, fc0b);
    fno_kmix<<<gMix, 32>>>(sre[0], sim[0]);
    fno_kinv2_l0<<<gInv, 256>>>(lww[0], lwb[0], x, pd, fc0w, fc0b);

    for (int l = 1; l < 3; l++) {
        fno_kfwd<<<dim3(2, Cn, Bn), 256>>>();
        fno_kmix<<<gMix, 32>>>(sre[l], sim[l]);
        fno_kinv2<<<gInv, 256>>>(lww[l], lwb[l]);
    }
    fno_kfwd<<<dim3(2, Cn, Bn), 256>>>();
    fno_kmix<<<gMix, 32>>>(sre[3], sim[3]);
    fno_kfinal2<<<gInv, 256>>>(lww[3], lwb[3], fc1w, fc1b, fc2w, fc2b, out);
}